// round 2
// baseline (speedup 1.0000x reference)
#include <cuda_runtime.h>
#include <math.h>

#define Bz 8
#define Mz 512
#define DMz 1024
#define Hz 16
#define DHz 64
#define DFFz 4096
#define RAz 32
#define RFz 384
#define ROz 384
#define BMr (Bz*Mz)          // 4096 rows
#define C3 (3*Hz*RAz)        // 1536
#define LN_EPS 1e-12f

// ---------------- scratch (device globals; no allocations allowed) ----------------
__device__ float g_Wcat[DMz * C3];            // packed Pq|Pk|Pv  [1024][1536]
__device__ float g_T[BMr * C3];               // low-rank qkv      [4096][1536]
__device__ float g_Q[Bz*Hz*Mz*DHz];
__device__ float g_K[Bz*Hz*Mz*DHz];
__device__ float g_V[Bz*Hz*Mz*DHz];
__device__ float g_S[(size_t)Bz*Hz*Mz*Mz];    // scores/probs      134 MB
__device__ float g_attn[BMr*DMz];             // attn in [b,m,h*64+d]
__device__ float g_t1[BMr*ROz];
__device__ float g_y1[BMr*DMz];
__device__ float g_x1[BMr*DMz];
__device__ float g_mid[BMr*RFz];
__device__ float g_hdn[(size_t)BMr*DFFz];
__device__ float g_t2[BMr*RFz];
__device__ float g_y2[BMr*DMz];

__device__ __forceinline__ float gelu_f(float x) {
    return 0.5f * x * (1.0f + erff(x * 0.70710678118654752440f));
}

// ---------------- pack Pq/Pk/Pv -> Wcat[d][j*512 + h*32 + r] ----------------
__global__ void pack_w(const float* __restrict__ Pq, const float* __restrict__ Pk,
                       const float* __restrict__ Pv) {
    int idx = blockIdx.x * blockDim.x + threadIdx.x;
    if (idx >= DMz * C3) return;
    int d = idx / C3;
    int c = idx % C3;
    int j = c / (Hz * RAz);
    int hr = c % (Hz * RAz);
    int h = hr / RAz, r = hr % RAz;
    const float* P = (j == 0) ? Pq : ((j == 1) ? Pk : Pv);
    g_Wcat[idx] = P[((size_t)h * DMz + d) * RAz + r];
}

// ---------------- generic SGEMM 128x128x8, 256 threads, 8x8 per thread ----------------
// EPI: 0 = none, 1 = +bias, 2 = gelu(+bias)
template <int EPI>
__launch_bounds__(256)
__global__ void sgemm_k(const float* __restrict__ A, const float* __restrict__ Bm,
                        float* __restrict__ C, int N, int K,
                        const float* __restrict__ bias) {
    __shared__ float As[8][128];
    __shared__ float Bs[8][128];
    int tid = threadIdx.x;
    int brow = blockIdx.y, bcol = blockIdx.x;
    const float* Ab = A + (size_t)brow * 128 * K;
    const float* Bb = Bm + (size_t)bcol * 128;

    float acc[8][8];
#pragma unroll
    for (int i = 0; i < 8; i++)
#pragma unroll
        for (int j = 0; j < 8; j++) acc[i][j] = 0.f;

    int arow = tid >> 1, acol = (tid & 1) * 4;
    int browi = tid >> 5, bcoli = (tid & 31) * 4;
    int tr = tid >> 4, tc = tid & 15;

    for (int k0 = 0; k0 < K; k0 += 8) {
        float4 av = *(const float4*)(Ab + (size_t)arow * K + k0 + acol);
        As[acol + 0][arow] = av.x;
        As[acol + 1][arow] = av.y;
        As[acol + 2][arow] = av.z;
        As[acol + 3][arow] = av.w;
        float4 bv = *(const float4*)(Bb + (size_t)(k0 + browi) * N + bcoli);
        *(float4*)(&Bs[browi][bcoli]) = bv;
        __syncthreads();
#pragma unroll
        for (int k = 0; k < 8; k++) {
            float rm[8], rn[8];
#pragma unroll
            for (int i = 0; i < 8; i++) rm[i] = As[k][tr * 8 + i];
#pragma unroll
            for (int j = 0; j < 8; j++) rn[j] = Bs[k][tc * 8 + j];
#pragma unroll
            for (int i = 0; i < 8; i++)
#pragma unroll
                for (int j = 0; j < 8; j++) acc[i][j] += rm[i] * rn[j];
        }
        __syncthreads();
    }

#pragma unroll
    for (int i = 0; i < 8; i++) {
        int row = brow * 128 + tr * 8 + i;
#pragma unroll
        for (int j4 = 0; j4 < 8; j4 += 4) {
            int col = bcol * 128 + tc * 8 + j4;
            float4 o;
            o.x = acc[i][j4 + 0];
            o.y = acc[i][j4 + 1];
            o.z = acc[i][j4 + 2];
            o.w = acc[i][j4 + 3];
            if (EPI >= 1) {
                o.x += bias[col + 0];
                o.y += bias[col + 1];
                o.z += bias[col + 2];
                o.w += bias[col + 3];
            }
            if (EPI == 2) {
                o.x = gelu_f(o.x);
                o.y = gelu_f(o.y);
                o.z = gelu_f(o.z);
                o.w = gelu_f(o.w);
            }
            *(float4*)(C + (size_t)row * N + col) = o;
        }
    }
}

// ---------------- rank-32 expansion: Q/K/V = T(:, j,h,:) @ Vj[h] + bj[h] ----------------
__launch_bounds__(256)
__global__ void qkv2_k(const float* __restrict__ Vq, const float* __restrict__ Vk,
                       const float* __restrict__ Vv, const float* __restrict__ bq,
                       const float* __restrict__ bk, const float* __restrict__ bv) {
    __shared__ float Vs[RAz][DHz];
    int z = blockIdx.y;            // b*H + h
    int j = blockIdx.z;            // 0=q,1=k,2=v
    int b = z / Hz, h = z % Hz;
    const float* Vm = (j == 0) ? Vq : ((j == 1) ? Vk : Vv);
    const float* bm = (j == 0) ? bq : ((j == 1) ? bk : bv);
    float* out = (j == 0) ? g_Q : ((j == 1) ? g_K : g_V);

    int tid = threadIdx.y * 64 + threadIdx.x;
#pragma unroll
    for (int i = 0; i < 8; i++) {
        int idx = tid + i * 256;   // 2048 elems
        Vs[idx >> 6][idx & 63] = Vm[(size_t)h * RAz * DHz + idx];
    }
    __syncthreads();

    int m = blockIdx.x * 4 + threadIdx.y;
    int d = threadIdx.x;
    const float* trow = g_T + ((size_t)(b * Mz + m)) * C3 + j * (Hz * RAz) + h * RAz;
    float acc = bm[h * DHz + d];
#pragma unroll
    for (int r = 0; r < RAz; r++) acc += trow[r] * Vs[r][d];
    out[((size_t)z * Mz + m) * DHz + d] = acc;
}

// ---------------- batched scores = (Q K^T) * 1/sqrt(64) ----------------
__launch_bounds__(256)
__global__ void scores_k() {
    __shared__ float Qs[DHz][65];
    __shared__ float Ks[DHz][65];
    int z = blockIdx.z;
    int m0 = blockIdx.y * 64, n0 = blockIdx.x * 64;
    const float* Qb = g_Q + (size_t)z * Mz * DHz;
    const float* Kb = g_K + (size_t)z * Mz * DHz;
    int tid = threadIdx.x;
#pragma unroll
    for (int i = 0; i < 16; i++) {
        int idx = tid + i * 256;           // 4096 elems each
        int mm = idx >> 6, dd = idx & 63;
        Qs[dd][mm] = Qb[(size_t)(m0 + mm) * DHz + dd];
        Ks[dd][mm] = Kb[(size_t)(n0 + mm) * DHz + dd];
    }
    __syncthreads();
    int tr = tid >> 4, tc = tid & 15;
    float acc[4][4];
#pragma unroll
    for (int i = 0; i < 4; i++)
#pragma unroll
        for (int j = 0; j < 4; j++) acc[i][j] = 0.f;
#pragma unroll 16
    for (int d = 0; d < DHz; d++) {
        float qv[4], kv[4];
#pragma unroll
        for (int i = 0; i < 4; i++) qv[i] = Qs[d][tr * 4 + i];
#pragma unroll
        for (int j = 0; j < 4; j++) kv[j] = Ks[d][tc * 4 + j];
#pragma unroll
        for (int i = 0; i < 4; i++)
#pragma unroll
            for (int j = 0; j < 4; j++) acc[i][j] += qv[i] * kv[j];
    }
    float* Sb = g_S + (size_t)z * Mz * Mz;
#pragma unroll
    for (int i = 0; i < 4; i++) {
        int m = m0 + tr * 4 + i;
        float4 o;
        o.x = acc[i][0] * 0.125f;
        o.y = acc[i][1] * 0.125f;
        o.z = acc[i][2] * 0.125f;
        o.w = acc[i][3] * 0.125f;
        *(float4*)(Sb + (size_t)m * Mz + n0 + tc * 4) = o;
    }
}

// ---------------- row softmax over n (with additive mask) ----------------
__launch_bounds__(128)
__global__ void softmax_k(const float* __restrict__ mask) {
    __shared__ float sh[4];
    int row = blockIdx.x;              // b*H*M
    int b = row / (Hz * Mz);
    float* s = g_S + (size_t)row * Mz;
    const float* mk = mask + (size_t)b * Mz;
    int tid = threadIdx.x;
    int lane = tid & 31, warp = tid >> 5;

    float v[4];
    float mx = -INFINITY;
#pragma unroll
    for (int i = 0; i < 4; i++) {
        int c = tid + i * 128;
        v[i] = s[c] + mk[c];
        mx = fmaxf(mx, v[i]);
    }
#pragma unroll
    for (int o = 16; o > 0; o >>= 1) mx = fmaxf(mx, __shfl_xor_sync(0xffffffffu, mx, o));
    if (lane == 0) sh[warp] = mx;
    __syncthreads();
    if (warp == 0) {
        float t = (lane < 4) ? sh[lane] : -INFINITY;
#pragma unroll
        for (int o = 2; o > 0; o >>= 1) t = fmaxf(t, __shfl_xor_sync(0xffffffffu, t, o));
        if (lane == 0) sh[0] = t;
    }
    __syncthreads();
    mx = sh[0];
    __syncthreads();

    float sum = 0.f;
#pragma unroll
    for (int i = 0; i < 4; i++) {
        v[i] = __expf(v[i] - mx);
        sum += v[i];
    }
#pragma unroll
    for (int o = 16; o > 0; o >>= 1) sum += __shfl_xor_sync(0xffffffffu, sum, o);
    if (lane == 0) sh[warp] = sum;
    __syncthreads();
    if (warp == 0) {
        float t = (lane < 4) ? sh[lane] : 0.f;
#pragma unroll
        for (int o = 2; o > 0; o >>= 1) t += __shfl_xor_sync(0xffffffffu, t, o);
        if (lane == 0) sh[0] = t;
    }
    __syncthreads();
    float inv = 1.0f / sh[0];
#pragma unroll
    for (int i = 0; i < 4; i++) s[tid + i * 128] = v[i] * inv;
}

// ---------------- attn = probs @ V, written as [b, m, h*64 + d] ----------------
__launch_bounds__(256)
__global__ void attnv_k() {
    __shared__ float Ps[32][65];
    __shared__ float Vs[32][64];
    int z = blockIdx.y;
    int m0 = blockIdx.x * 64;
    int b = z >> 4, h = z & 15;
    const float* Pb = g_S + (size_t)z * Mz * Mz;
    const float* Vb = g_V + (size_t)z * Mz * DHz;
    int tid = threadIdx.x;
    int tr = tid >> 4, tc = tid & 15;
    float acc[4][4];
#pragma unroll
    for (int i = 0; i < 4; i++)
#pragma unroll
        for (int j = 0; j < 4; j++) acc[i][j] = 0.f;

    for (int kb = 0; kb < Mz; kb += 32) {
#pragma unroll
        for (int i = 0; i < 8; i++) {
            int idx = tid + i * 256;       // 2048 elems each tile
            int mm = idx >> 5, nn = idx & 31;
            Ps[nn][mm] = Pb[(size_t)(m0 + mm) * Mz + kb + nn];
            int vn = idx >> 6, vd = idx & 63;
            Vs[vn][vd] = Vb[(size_t)(kb + vn) * DHz + vd];
        }
        __syncthreads();
#pragma unroll
        for (int n = 0; n < 32; n++) {
            float pv[4], vv[4];
#pragma unroll
            for (int i = 0; i < 4; i++) pv[i] = Ps[n][tr * 4 + i];
#pragma unroll
            for (int j = 0; j < 4; j++) vv[j] = Vs[n][tc * 4 + j];
#pragma unroll
            for (int i = 0; i < 4; i++)
#pragma unroll
                for (int j = 0; j < 4; j++) acc[i][j] += pv[i] * vv[j];
        }
        __syncthreads();
    }
#pragma unroll
    for (int i = 0; i < 4; i++) {
        int m = m0 + tr * 4 + i;
        float4 o;
        o.x = acc[i][0];
        o.y = acc[i][1];
        o.z = acc[i][2];
        o.w = acc[i][3];
        *(float4*)(g_attn + ((size_t)(b * Mz + m)) * DMz + h * DHz + tc * 4) = o;
    }
}

// ---------------- residual + LayerNorm ----------------
__launch_bounds__(256)
__global__ void ln_k(const float* __restrict__ a, const float* __restrict__ r,
                     const float* __restrict__ g, const float* __restrict__ bb,
                     float* __restrict__ out) {
    __shared__ float sh[8];
    int row = blockIdx.x;
    int tid = threadIdx.x;
    int lane = tid & 31, warp = tid >> 5;
    const float* ap = a + (size_t)row * DMz;
    const float* rp = r + (size_t)row * DMz;
    float v[4];
    float s = 0.f;
#pragma unroll
    for (int i = 0; i < 4; i++) {
        int c = tid + i * 256;
        v[i] = ap[c] + rp[c];
        s += v[i];
    }
#pragma unroll
    for (int o = 16; o > 0; o >>= 1) s += __shfl_xor_sync(0xffffffffu, s, o);
    if (lane == 0) sh[warp] = s;
    __syncthreads();
    if (warp == 0) {
        float t = (lane < 8) ? sh[lane] : 0.f;
#pragma unroll
        for (int o = 4; o > 0; o >>= 1) t += __shfl_xor_sync(0xffffffffu, t, o);
        if (lane == 0) sh[0] = t;
    }
    __syncthreads();
    float mu = sh[0] * (1.0f / DMz);
    __syncthreads();

    float q = 0.f;
#pragma unroll
    for (int i = 0; i < 4; i++) {
        float d = v[i] - mu;
        q += d * d;
    }
#pragma unroll
    for (int o = 16; o > 0; o >>= 1) q += __shfl_xor_sync(0xffffffffu, q, o);
    if (lane == 0) sh[warp] = q;
    __syncthreads();
    if (warp == 0) {
        float t = (lane < 8) ? sh[lane] : 0.f;
#pragma unroll
        for (int o = 4; o > 0; o >>= 1) t += __shfl_xor_sync(0xffffffffu, t, o);
        if (lane == 0) sh[0] = t;
    }
    __syncthreads();
    float var = sh[0] * (1.0f / DMz);
    float rs = rsqrtf(var + LN_EPS);
#pragma unroll
    for (int i = 0; i < 4; i++) {
        int c = tid + i * 256;
        out[(size_t)row * DMz + c] = (v[i] - mu) * rs * g[c] + bb[c];
    }
}

// ---------------- launch ----------------
extern "C" void kernel_launch(void* const* d_in, const int* in_sizes, int n_in,
                              void* d_out, int out_size) {
    const float* x    = (const float*)d_in[0];
    const float* mask = (const float*)d_in[1];
    const float* Pq   = (const float*)d_in[2];
    const float* Vq   = (const float*)d_in[3];
    const float* Pk   = (const float*)d_in[4];
    const float* Vk   = (const float*)d_in[5];
    const float* Pv   = (const float*)d_in[6];
    const float* Vv   = (const float*)d_in[7];
    const float* bq   = (const float*)d_in[8];
    const float* bk   = (const float*)d_in[9];
    const float* bv   = (const float*)d_in[10];
    const float* Uo   = (const float*)d_in[11];
    const float* Vo   = (const float*)d_in[12];
    const float* bo   = (const float*)d_in[13];
    const float* U1   = (const float*)d_in[14];
    const float* V1   = (const float*)d_in[15];
    const float* b1   = (const float*)d_in[16];
    const float* U2   = (const float*)d_in[17];
    const float* V2   = (const float*)d_in[18];
    const float* b2   = (const float*)d_in[19];
    const float* ln1g = (const float*)d_in[20];
    const float* ln1b = (const float*)d_in[21];
    const float* ln2g = (const float*)d_in[22];
    const float* ln2b = (const float*)d_in[23];
    float* out = (float*)d_out;

    float *Wcat, *T, *attn, *t1, *y1, *x1, *mid, *hdn, *t2, *y2;
    cudaGetSymbolAddress((void**)&Wcat, g_Wcat);
    cudaGetSymbolAddress((void**)&T, g_T);
    cudaGetSymbolAddress((void**)&attn, g_attn);
    cudaGetSymbolAddress((void**)&t1, g_t1);
    cudaGetSymbolAddress((void**)&y1, g_y1);
    cudaGetSymbolAddress((void**)&x1, g_x1);
    cudaGetSymbolAddress((void**)&mid, g_mid);
    cudaGetSymbolAddress((void**)&hdn, g_hdn);
    cudaGetSymbolAddress((void**)&t2, g_t2);
    cudaGetSymbolAddress((void**)&y2, g_y2);

    // qkv low-rank projection
    pack_w<<<(DMz * C3 + 255) / 256, 256>>>(Pq, Pk, Pv);
    sgemm_k<0><<<dim3(C3 / 128, BMr / 128), 256>>>(x, Wcat, T, C3, DMz, nullptr);
    qkv2_k<<<dim3(Mz / 4, Bz * Hz, 3), dim3(64, 4)>>>(Vq, Vk, Vv, bq, bk, bv);

    // attention
    scores_k<<<dim3(Mz / 64, Mz / 64, Bz * Hz), 256>>>();
    softmax_k<<<Bz * Hz * Mz, 128>>>(mask);
    attnv_k<<<dim3(Mz / 64, Bz * Hz), 256>>>();

    // output projection + residual + LN1
    sgemm_k<0><<<dim3(ROz / 128, BMr / 128), 256>>>(attn, Uo, t1, ROz, DMz, nullptr);
    sgemm_k<1><<<dim3(DMz / 128, BMr / 128), 256>>>(t1, Vo, y1, DMz, ROz, bo);
    ln_k<<<BMr, 256>>>(x, y1, ln1g, ln1b, x1);

    // FFN
    sgemm_k<0><<<dim3(RFz / 128, BMr / 128), 256>>>(x1, U1, mid, RFz, DMz, nullptr);
    sgemm_k<2><<<dim3(DFFz / 128, BMr / 128), 256>>>(mid, V1, hdn, DFFz, RFz, b1);
    sgemm_k<0><<<dim3(RFz / 128, BMr / 128), 256>>>(hdn, U2, t2, RFz, DFFz, nullptr);
    sgemm_k<1><<<dim3(DMz / 128, BMr / 128), 256>>>(t2, V2, y2, DMz, RFz, b2);

    // residual + LN2 -> out
    ln_k<<<BMr, 256>>>(x1, y2, ln2g, ln2b, out);
}

// round 3
// speedup vs baseline: 1.1470x; 1.1470x over previous
#include <cuda_runtime.h>
#include <math.h>
#include <stdint.h>

#define Bz 8
#define Mz 512
#define DMz 1024
#define Hz 16
#define DHz 64
#define DFFz 4096
#define RAz 32
#define RFz 384
#define ROz 384
#define BMr (Bz*Mz)          // 4096 rows
#define C3 (3*Hz*RAz)        // 1536
#define LN_EPS 1e-12f

// ---------------- scratch (device globals; no allocations allowed) ----------------
__device__ float g_Wcat[DMz * C3];            // packed Pq|Pk|Pv  [1024][1536]
__device__ float g_T[BMr * C3];               // low-rank qkv      [4096][1536]
__device__ float g_Q[Bz*Hz*Mz*DHz];
__device__ float g_K[Bz*Hz*Mz*DHz];
__device__ float g_V[Bz*Hz*Mz*DHz];
__device__ float g_S[(size_t)Bz*Hz*Mz*Mz];    // scores/probs      134 MB
__device__ float g_attn[BMr*DMz];             // attn in [b,m,h*64+d]
__device__ float g_t1[BMr*ROz];
__device__ float g_y1[BMr*DMz];
__device__ float g_x1[BMr*DMz];
__device__ float g_mid[BMr*RFz];
__device__ float g_hdn[(size_t)BMr*DFFz];
__device__ float g_t2[BMr*RFz];
__device__ float g_y2[BMr*DMz];

__device__ __forceinline__ float gelu_f(float x) {
    return 0.5f * x * (1.0f + erff(x * 0.70710678118654752440f));
}

// tf32 split: x ~= hi + lo, both representable in tf32 (rna rounding)
__device__ __forceinline__ void tf32_split(float x, uint32_t& h, uint32_t& l) {
    uint32_t hi;
    asm("cvt.rna.tf32.f32 %0, %1;" : "=r"(hi) : "f"(x));
    float r = x - __uint_as_float(hi);
    uint32_t lo;
    asm("cvt.rna.tf32.f32 %0, %1;" : "=r"(lo) : "f"(r));
    h = hi; l = lo;
}

__device__ __forceinline__ void mma8(float* c, const uint32_t* a, const uint32_t* b) {
    asm volatile(
        "mma.sync.aligned.m16n8k8.row.col.f32.tf32.tf32.f32 "
        "{%0,%1,%2,%3}, {%4,%5,%6,%7}, {%8,%9}, {%0,%1,%2,%3};"
        : "+f"(c[0]), "+f"(c[1]), "+f"(c[2]), "+f"(c[3])
        : "r"(a[0]), "r"(a[1]), "r"(a[2]), "r"(a[3]), "r"(b[0]), "r"(b[1]));
}

// ---------------- pack Pq/Pk/Pv -> Wcat[d][j*512 + h*32 + r] ----------------
__global__ void pack_w(const float* __restrict__ Pq, const float* __restrict__ Pk,
                       const float* __restrict__ Pv) {
    int idx = blockIdx.x * blockDim.x + threadIdx.x;
    if (idx >= DMz * C3) return;
    int d = idx / C3;
    int c = idx % C3;
    int j = c / (Hz * RAz);
    int hr = c % (Hz * RAz);
    int h = hr / RAz, r = hr % RAz;
    const float* P = (j == 0) ? Pq : ((j == 1) ? Pk : Pv);
    g_Wcat[idx] = P[((size_t)h * DMz + d) * RAz + r];
}

// =====================================================================
// Generic tf32x2 tensor-core GEMM: C[M,N] = A[M,K](row) @ B[K,N](row)
// CTA tile 128x128, BK=16, 8 warps (warp tile 64x32).
// EPI: 0 none, 1 +bias, 2 gelu(+bias)
// =====================================================================
#define APAD 8
template <int EPI>
__launch_bounds__(256)
__global__ void mma_gemm(const float* __restrict__ A, const float* __restrict__ B,
                         float* __restrict__ C, int N, int K,
                         const float* __restrict__ bias) {
    __shared__ uint32_t Ah[16][128 + APAD];
    __shared__ uint32_t Al[16][128 + APAD];
    __shared__ uint32_t Bh[16][128 + APAD];
    __shared__ uint32_t Bl[16][128 + APAD];

    int tid = threadIdx.x;
    int lane = tid & 31, wid = tid >> 5;
    int warp_m = (wid >> 2) * 64;
    int warp_n = (wid & 3) * 32;
    int by = blockIdx.y, bx = blockIdx.x;

    // global load mapping
    int arow = tid >> 1, aco = (tid & 1) * 8;
    int brow = tid >> 4, bco = (tid & 15) * 8;
    const float* Ap = A + (size_t)(by * 128 + arow) * K + aco;
    const float* Bp = B + (size_t)brow * N + bx * 128 + bco;

    float acc[4][4][4];
#pragma unroll
    for (int i = 0; i < 4; i++)
#pragma unroll
        for (int j = 0; j < 4; j++)
#pragma unroll
            for (int t = 0; t < 4; t++) acc[i][j][t] = 0.f;

    float4 pa0 = *(const float4*)(Ap);
    float4 pa1 = *(const float4*)(Ap + 4);
    float4 pb0 = *(const float4*)(Bp);
    float4 pb1 = *(const float4*)(Bp + 4);

    for (int k0 = 0; k0 < K; k0 += 16) {
        // store prefetched tile (with tf32 split)
        {
            float av[8] = {pa0.x, pa0.y, pa0.z, pa0.w, pa1.x, pa1.y, pa1.z, pa1.w};
#pragma unroll
            for (int j = 0; j < 8; j++) {
                uint32_t h, l;
                tf32_split(av[j], h, l);
                Ah[aco + j][arow] = h;
                Al[aco + j][arow] = l;
            }
            float bv[8] = {pb0.x, pb0.y, pb0.z, pb0.w, pb1.x, pb1.y, pb1.z, pb1.w};
#pragma unroll
            for (int j = 0; j < 8; j++) {
                uint32_t h, l;
                tf32_split(bv[j], h, l);
                Bh[brow][bco + j] = h;
                Bl[brow][bco + j] = l;
            }
        }
        __syncthreads();
        if (k0 + 16 < K) {
            Ap += 16;
            Bp += (size_t)16 * N;
            pa0 = *(const float4*)(Ap);
            pa1 = *(const float4*)(Ap + 4);
            pb0 = *(const float4*)(Bp);
            pb1 = *(const float4*)(Bp + 4);
        }
#pragma unroll
        for (int ks = 0; ks < 16; ks += 8) {
            uint32_t ah[4][4], al[4][4], bh[4][2], bl[4][2];
            int kr = ks + (lane & 3);
            int mq = lane >> 2;
#pragma unroll
            for (int mt = 0; mt < 4; mt++) {
                int mb = warp_m + mt * 16;
                ah[mt][0] = Ah[kr][mb + mq];
                ah[mt][1] = Ah[kr][mb + 8 + mq];
                ah[mt][2] = Ah[kr + 4][mb + mq];
                ah[mt][3] = Ah[kr + 4][mb + 8 + mq];
                al[mt][0] = Al[kr][mb + mq];
                al[mt][1] = Al[kr][mb + 8 + mq];
                al[mt][2] = Al[kr + 4][mb + mq];
                al[mt][3] = Al[kr + 4][mb + 8 + mq];
            }
#pragma unroll
            for (int nt = 0; nt < 4; nt++) {
                int nb = warp_n + nt * 8;
                bh[nt][0] = Bh[kr][nb + mq];
                bh[nt][1] = Bh[kr + 4][nb + mq];
                bl[nt][0] = Bl[kr][nb + mq];
                bl[nt][1] = Bl[kr + 4][nb + mq];
            }
#pragma unroll
            for (int mt = 0; mt < 4; mt++)
#pragma unroll
                for (int nt = 0; nt < 4; nt++) {
                    mma8(acc[mt][nt], ah[mt], bh[nt]);
                    mma8(acc[mt][nt], ah[mt], bl[nt]);
                    mma8(acc[mt][nt], al[mt], bh[nt]);
                }
        }
        __syncthreads();
    }

    // epilogue
#pragma unroll
    for (int mt = 0; mt < 4; mt++) {
#pragma unroll
        for (int nt = 0; nt < 4; nt++) {
            int row = by * 128 + warp_m + mt * 16 + (lane >> 2);
            int col = bx * 128 + warp_n + nt * 8 + (lane & 3) * 2;
            float2 v0 = make_float2(acc[mt][nt][0], acc[mt][nt][1]);
            float2 v1 = make_float2(acc[mt][nt][2], acc[mt][nt][3]);
            if (EPI >= 1) {
                float2 bb = *(const float2*)(bias + col);
                v0.x += bb.x; v0.y += bb.y;
                v1.x += bb.x; v1.y += bb.y;
            }
            if (EPI == 2) {
                v0.x = gelu_f(v0.x); v0.y = gelu_f(v0.y);
                v1.x = gelu_f(v1.x); v1.y = gelu_f(v1.y);
            }
            *(float2*)(C + (size_t)row * N + col) = v0;
            *(float2*)(C + (size_t)(row + 8) * N + col) = v1;
        }
    }
}

// =====================================================================
// Batched scores = (Q K^T) / 8  : per z, M=N=512, K=64. CTA 128x128.
// =====================================================================
__launch_bounds__(256)
__global__ void mma_scores() {
    __shared__ uint32_t Ah[16][128 + APAD];
    __shared__ uint32_t Al[16][128 + APAD];
    __shared__ uint32_t Bh[16][128 + APAD];
    __shared__ uint32_t Bl[16][128 + APAD];

    int tid = threadIdx.x;
    int lane = tid & 31, wid = tid >> 5;
    int warp_m = (wid >> 2) * 64;
    int warp_n = (wid & 3) * 32;
    int by = blockIdx.y, bx = blockIdx.x, z = blockIdx.z;

    const float* Qb = g_Q + (size_t)z * Mz * DHz;
    const float* Kb = g_K + (size_t)z * Mz * DHz;

    int arow = tid >> 1, aco = (tid & 1) * 8;   // Q rows (m), k offset
    const float* Ap = Qb + (size_t)(by * 128 + arow) * DHz + aco;
    const float* Bp = Kb + (size_t)(bx * 128 + arow) * DHz + aco;  // K rows (n)

    float acc[4][4][4];
#pragma unroll
    for (int i = 0; i < 4; i++)
#pragma unroll
        for (int j = 0; j < 4; j++)
#pragma unroll
            for (int t = 0; t < 4; t++) acc[i][j][t] = 0.f;

    float4 pa0 = *(const float4*)(Ap);
    float4 pa1 = *(const float4*)(Ap + 4);
    float4 pb0 = *(const float4*)(Bp);
    float4 pb1 = *(const float4*)(Bp + 4);

    for (int k0 = 0; k0 < DHz; k0 += 16) {
        {
            float av[8] = {pa0.x, pa0.y, pa0.z, pa0.w, pa1.x, pa1.y, pa1.z, pa1.w};
            float bv[8] = {pb0.x, pb0.y, pb0.z, pb0.w, pb1.x, pb1.y, pb1.z, pb1.w};
#pragma unroll
            for (int j = 0; j < 8; j++) {
                uint32_t h, l;
                tf32_split(av[j], h, l);
                Ah[aco + j][arow] = h;
                Al[aco + j][arow] = l;
                tf32_split(bv[j], h, l);
                Bh[aco + j][arow] = h;   // Bs[k][n] from K[n][k] (transposed)
                Bl[aco + j][arow] = l;
            }
        }
        __syncthreads();
        if (k0 + 16 < DHz) {
            Ap += 16; Bp += 16;
            pa0 = *(const float4*)(Ap);
            pa1 = *(const float4*)(Ap + 4);
            pb0 = *(const float4*)(Bp);
            pb1 = *(const float4*)(Bp + 4);
        }
#pragma unroll
        for (int ks = 0; ks < 16; ks += 8) {
            uint32_t ah[4][4], al[4][4], bh[4][2], bl[4][2];
            int kr = ks + (lane & 3);
            int mq = lane >> 2;
#pragma unroll
            for (int mt = 0; mt < 4; mt++) {
                int mb = warp_m + mt * 16;
                ah[mt][0] = Ah[kr][mb + mq];
                ah[mt][1] = Ah[kr][mb + 8 + mq];
                ah[mt][2] = Ah[kr + 4][mb + mq];
                ah[mt][3] = Ah[kr + 4][mb + 8 + mq];
                al[mt][0] = Al[kr][mb + mq];
                al[mt][1] = Al[kr][mb + 8 + mq];
                al[mt][2] = Al[kr + 4][mb + mq];
                al[mt][3] = Al[kr + 4][mb + 8 + mq];
            }
#pragma unroll
            for (int nt = 0; nt < 4; nt++) {
                int nb = warp_n + nt * 8;
                bh[nt][0] = Bh[kr][nb + mq];
                bh[nt][1] = Bh[kr + 4][nb + mq];
                bl[nt][0] = Bl[kr][nb + mq];
                bl[nt][1] = Bl[kr + 4][nb + mq];
            }
#pragma unroll
            for (int mt = 0; mt < 4; mt++)
#pragma unroll
                for (int nt = 0; nt < 4; nt++) {
                    mma8(acc[mt][nt], ah[mt], bh[nt]);
                    mma8(acc[mt][nt], ah[mt], bl[nt]);
                    mma8(acc[mt][nt], al[mt], bh[nt]);
                }
        }
        __syncthreads();
    }

    float* Sb = g_S + (size_t)z * Mz * Mz;
#pragma unroll
    for (int mt = 0; mt < 4; mt++)
#pragma unroll
        for (int nt = 0; nt < 4; nt++) {
            int row = by * 128 + warp_m + mt * 16 + (lane >> 2);
            int col = bx * 128 + warp_n + nt * 8 + (lane & 3) * 2;
            float2 v0 = make_float2(acc[mt][nt][0] * 0.125f, acc[mt][nt][1] * 0.125f);
            float2 v1 = make_float2(acc[mt][nt][2] * 0.125f, acc[mt][nt][3] * 0.125f);
            *(float2*)(Sb + (size_t)row * Mz + col) = v0;
            *(float2*)(Sb + (size_t)(row + 8) * Mz + col) = v1;
        }
}

// =====================================================================
// Batched attn = probs @ V  -> g_attn[b, m, h*64+d]. CTA 128x64, K=512.
// =====================================================================
__launch_bounds__(256)
__global__ void mma_attnv() {
    __shared__ uint32_t Ah[16][128 + APAD];
    __shared__ uint32_t Al[16][128 + APAD];
    __shared__ uint32_t Bh[16][64 + APAD];
    __shared__ uint32_t Bl[16][64 + APAD];

    int tid = threadIdx.x;
    int lane = tid & 31, wid = tid >> 5;
    int warp_m = (wid >> 1) * 32;
    int warp_n = (wid & 1) * 32;
    int by = blockIdx.x, z = blockIdx.y;
    int b = z >> 4, h = z & 15;

    const float* Pb = g_S + (size_t)z * Mz * Mz;
    const float* Vb = g_V + (size_t)z * Mz * DHz;

    int arow = tid >> 1, aco = (tid & 1) * 8;
    int brow = tid >> 4, bco = (tid & 15) * 4;
    const float* Ap = Pb + (size_t)(by * 128 + arow) * Mz + aco;
    const float* Bp = Vb + (size_t)brow * DHz + bco;

    float acc[2][4][4];
#pragma unroll
    for (int i = 0; i < 2; i++)
#pragma unroll
        for (int j = 0; j < 4; j++)
#pragma unroll
            for (int t = 0; t < 4; t++) acc[i][j][t] = 0.f;

    float4 pa0 = *(const float4*)(Ap);
    float4 pa1 = *(const float4*)(Ap + 4);
    float4 pb0 = *(const float4*)(Bp);

    for (int k0 = 0; k0 < Mz; k0 += 16) {
        {
            float av[8] = {pa0.x, pa0.y, pa0.z, pa0.w, pa1.x, pa1.y, pa1.z, pa1.w};
#pragma unroll
            for (int j = 0; j < 8; j++) {
                uint32_t hh, ll;
                tf32_split(av[j], hh, ll);
                Ah[aco + j][arow] = hh;
                Al[aco + j][arow] = ll;
            }
            float bv[4] = {pb0.x, pb0.y, pb0.z, pb0.w};
#pragma unroll
            for (int j = 0; j < 4; j++) {
                uint32_t hh, ll;
                tf32_split(bv[j], hh, ll);
                Bh[brow][bco + j] = hh;
                Bl[brow][bco + j] = ll;
            }
        }
        __syncthreads();
        if (k0 + 16 < Mz) {
            Ap += 16;
            Bp += (size_t)16 * DHz;
            pa0 = *(const float4*)(Ap);
            pa1 = *(const float4*)(Ap + 4);
            pb0 = *(const float4*)(Bp);
        }
#pragma unroll
        for (int ks = 0; ks < 16; ks += 8) {
            uint32_t ah[2][4], al[2][4], bh[4][2], bl[4][2];
            int kr = ks + (lane & 3);
            int mq = lane >> 2;
#pragma unroll
            for (int mt = 0; mt < 2; mt++) {
                int mb = warp_m + mt * 16;
                ah[mt][0] = Ah[kr][mb + mq];
                ah[mt][1] = Ah[kr][mb + 8 + mq];
                ah[mt][2] = Ah[kr + 4][mb + mq];
                ah[mt][3] = Ah[kr + 4][mb + 8 + mq];
                al[mt][0] = Al[kr][mb + mq];
                al[mt][1] = Al[kr][mb + 8 + mq];
                al[mt][2] = Al[kr + 4][mb + mq];
                al[mt][3] = Al[kr + 4][mb + 8 + mq];
            }
#pragma unroll
            for (int nt = 0; nt < 4; nt++) {
                int nb = warp_n + nt * 8;
                bh[nt][0] = Bh[kr][nb + mq];
                bh[nt][1] = Bh[kr + 4][nb + mq];
                bl[nt][0] = Bl[kr][nb + mq];
                bl[nt][1] = Bl[kr + 4][nb + mq];
            }
#pragma unroll
            for (int mt = 0; mt < 2; mt++)
#pragma unroll
                for (int nt = 0; nt < 4; nt++) {
                    mma8(acc[mt][nt], ah[mt], bh[nt]);
                    mma8(acc[mt][nt], ah[mt], bl[nt]);
                    mma8(acc[mt][nt], al[mt], bh[nt]);
                }
        }
        __syncthreads();
    }

#pragma unroll
    for (int mt = 0; mt < 2; mt++)
#pragma unroll
        for (int nt = 0; nt < 4; nt++) {
            int m = by * 128 + warp_m + mt * 16 + (lane >> 2);
            int d = warp_n + nt * 8 + (lane & 3) * 2;
            float2 v0 = make_float2(acc[mt][nt][0], acc[mt][nt][1]);
            float2 v1 = make_float2(acc[mt][nt][2], acc[mt][nt][3]);
            float* o0 = g_attn + ((size_t)(b * Mz + m)) * DMz + h * DHz + d;
            float* o1 = g_attn + ((size_t)(b * Mz + m + 8)) * DMz + h * DHz + d;
            *(float2*)o0 = v0;
            *(float2*)o1 = v1;
        }
}

// ---------------- rank-32 expansion: Q/K/V = T(:, j,h,:) @ Vj[h] + bj[h] ----------------
__launch_bounds__(256)
__global__ void qkv2_k(const float* __restrict__ Vq, const float* __restrict__ Vk,
                       const float* __restrict__ Vv, const float* __restrict__ bq,
                       const float* __restrict__ bk, const float* __restrict__ bv) {
    __shared__ float Vs[RAz][DHz];
    int z = blockIdx.y;            // b*H + h
    int j = blockIdx.z;            // 0=q,1=k,2=v
    int b = z / Hz, h = z % Hz;
    const float* Vm = (j == 0) ? Vq : ((j == 1) ? Vk : Vv);
    const float* bm = (j == 0) ? bq : ((j == 1) ? bk : bv);
    float* out = (j == 0) ? g_Q : ((j == 1) ? g_K : g_V);

    int tid = threadIdx.y * 64 + threadIdx.x;
#pragma unroll
    for (int i = 0; i < 8; i++) {
        int idx = tid + i * 256;   // 2048 elems
        Vs[idx >> 6][idx & 63] = Vm[(size_t)h * RAz * DHz + idx];
    }
    __syncthreads();

    int m = blockIdx.x * 4 + threadIdx.y;
    int d = threadIdx.x;
    const float* trow = g_T + ((size_t)(b * Mz + m)) * C3 + j * (Hz * RAz) + h * RAz;
    float acc = bm[h * DHz + d];
#pragma unroll
    for (int r = 0; r < RAz; r++) acc += trow[r] * Vs[r][d];
    out[((size_t)z * Mz + m) * DHz + d] = acc;
}

// ---------------- row softmax over n (with additive mask) ----------------
__launch_bounds__(128)
__global__ void softmax_k(const float* __restrict__ mask) {
    __shared__ float sh[4];
    int row = blockIdx.x;              // b*H*M
    int b = row / (Hz * Mz);
    float* s = g_S + (size_t)row * Mz;
    const float* mk = mask + (size_t)b * Mz;
    int tid = threadIdx.x;
    int lane = tid & 31, warp = tid >> 5;

    float v[4];
    float mx = -INFINITY;
#pragma unroll
    for (int i = 0; i < 4; i++) {
        int c = tid + i * 128;
        v[i] = s[c] + mk[c];
        mx = fmaxf(mx, v[i]);
    }
#pragma unroll
    for (int o = 16; o > 0; o >>= 1) mx = fmaxf(mx, __shfl_xor_sync(0xffffffffu, mx, o));
    if (lane == 0) sh[warp] = mx;
    __syncthreads();
    if (warp == 0) {
        float t = (lane < 4) ? sh[lane] : -INFINITY;
#pragma unroll
        for (int o = 2; o > 0; o >>= 1) t = fmaxf(t, __shfl_xor_sync(0xffffffffu, t, o));
        if (lane == 0) sh[0] = t;
    }
    __syncthreads();
    mx = sh[0];
    __syncthreads();

    float sum = 0.f;
#pragma unroll
    for (int i = 0; i < 4; i++) {
        v[i] = __expf(v[i] - mx);
        sum += v[i];
    }
#pragma unroll
    for (int o = 16; o > 0; o >>= 1) sum += __shfl_xor_sync(0xffffffffu, sum, o);
    if (lane == 0) sh[warp] = sum;
    __syncthreads();
    if (warp == 0) {
        float t = (lane < 4) ? sh[lane] : 0.f;
#pragma unroll
        for (int o = 2; o > 0; o >>= 1) t += __shfl_xor_sync(0xffffffffu, t, o);
        if (lane == 0) sh[0] = t;
    }
    __syncthreads();
    float inv = 1.0f / sh[0];
#pragma unroll
    for (int i = 0; i < 4; i++) s[tid + i * 128] = v[i] * inv;
}

// ---------------- residual + LayerNorm ----------------
__launch_bounds__(256)
__global__ void ln_k(const float* __restrict__ a, const float* __restrict__ r,
                     const float* __restrict__ g, const float* __restrict__ bb,
                     float* __restrict__ out) {
    __shared__ float sh[8];
    int row = blockIdx.x;
    int tid = threadIdx.x;
    int lane = tid & 31, warp = tid >> 5;
    const float* ap = a + (size_t)row * DMz;
    const float* rp = r + (size_t)row * DMz;
    float v[4];
    float s = 0.f;
#pragma unroll
    for (int i = 0; i < 4; i++) {
        int c = tid + i * 256;
        v[i] = ap[c] + rp[c];
        s += v[i];
    }
#pragma unroll
    for (int o = 16; o > 0; o >>= 1) s += __shfl_xor_sync(0xffffffffu, s, o);
    if (lane == 0) sh[warp] = s;
    __syncthreads();
    if (warp == 0) {
        float t = (lane < 8) ? sh[lane] : 0.f;
#pragma unroll
        for (int o = 4; o > 0; o >>= 1) t += __shfl_xor_sync(0xffffffffu, t, o);
        if (lane == 0) sh[0] = t;
    }
    __syncthreads();
    float mu = sh[0] * (1.0f / DMz);
    __syncthreads();

    float q = 0.f;
#pragma unroll
    for (int i = 0; i < 4; i++) {
        float d = v[i] - mu;
        q += d * d;
    }
#pragma unroll
    for (int o = 16; o > 0; o >>= 1) q += __shfl_xor_sync(0xffffffffu, q, o);
    if (lane == 0) sh[warp] = q;
    __syncthreads();
    if (warp == 0) {
        float t = (lane < 8) ? sh[lane] : 0.f;
#pragma unroll
        for (int o = 4; o > 0; o >>= 1) t += __shfl_xor_sync(0xffffffffu, t, o);
        if (lane == 0) sh[0] = t;
    }
    __syncthreads();
    float var = sh[0] * (1.0f / DMz);
    float rs = rsqrtf(var + LN_EPS);
#pragma unroll
    for (int i = 0; i < 4; i++) {
        int c = tid + i * 256;
        out[(size_t)row * DMz + c] = (v[i] - mu) * rs * g[c] + bb[c];
    }
}

// ---------------- launch ----------------
extern "C" void kernel_launch(void* const* d_in, const int* in_sizes, int n_in,
                              void* d_out, int out_size) {
    const float* x    = (const float*)d_in[0];
    const float* mask = (const float*)d_in[1];
    const float* Pq   = (const float*)d_in[2];
    const float* Vq   = (const float*)d_in[3];
    const float* Pk   = (const float*)d_in[4];
    const float* Vk   = (const float*)d_in[5];
    const float* Pv   = (const float*)d_in[6];
    const float* Vv   = (const float*)d_in[7];
    const float* bq   = (const float*)d_in[8];
    const float* bk   = (const float*)d_in[9];
    const float* bv   = (const float*)d_in[10];
    const float* Uo   = (const float*)d_in[11];
    const float* Vo   = (const float*)d_in[12];
    const float* bo   = (const float*)d_in[13];
    const float* U1   = (const float*)d_in[14];
    const float* V1   = (const float*)d_in[15];
    const float* b1   = (const float*)d_in[16];
    const float* U2   = (const float*)d_in[17];
    const float* V2   = (const float*)d_in[18];
    const float* b2   = (const float*)d_in[19];
    const float* ln1g = (const float*)d_in[20];
    const float* ln1b = (const float*)d_in[21];
    const float* ln2g = (const float*)d_in[22];
    const float* ln2b = (const float*)d_in[23];
    float* out = (float*)d_out;

    float *Wcat, *T, *attn, *t1, *y1, *x1, *mid, *hdn, *t2, *y2;
    cudaGetSymbolAddress((void**)&Wcat, g_Wcat);
    cudaGetSymbolAddress((void**)&T, g_T);
    cudaGetSymbolAddress((void**)&attn, g_attn);
    cudaGetSymbolAddress((void**)&t1, g_t1);
    cudaGetSymbolAddress((void**)&y1, g_y1);
    cudaGetSymbolAddress((void**)&x1, g_x1);
    cudaGetSymbolAddress((void**)&mid, g_mid);
    cudaGetSymbolAddress((void**)&hdn, g_hdn);
    cudaGetSymbolAddress((void**)&t2, g_t2);
    cudaGetSymbolAddress((void**)&y2, g_y2);

    // qkv low-rank projection
    pack_w<<<(DMz * C3 + 255) / 256, 256>>>(Pq, Pk, Pv);
    mma_gemm<0><<<dim3(C3 / 128, BMr / 128), 256>>>(x, Wcat, T, C3, DMz, nullptr);
    qkv2_k<<<dim3(Mz / 4, Bz * Hz, 3), dim3(64, 4)>>>(Vq, Vk, Vv, bq, bk, bv);

    // attention
    mma_scores<<<dim3(Mz / 128, Mz / 128, Bz * Hz), 256>>>();
    softmax_k<<<Bz * Hz * Mz, 128>>>(mask);
    mma_attnv<<<dim3(Mz / 128, Bz * Hz), 256>>>();

    // output projection + residual + LN1
    mma_gemm<0><<<dim3(ROz / 128, BMr / 128), 256>>>(attn, Uo, t1, ROz, DMz, nullptr);
    mma_gemm<1><<<dim3(DMz / 128, BMr / 128), 256>>>(t1, Vo, y1, DMz, ROz, bo);
    ln_k<<<BMr, 256>>>(x, y1, ln1g, ln1b, x1);

    // FFN
    mma_gemm<0><<<dim3(RFz / 128, BMr / 128), 256>>>(x1, U1, mid, RFz, DMz, nullptr);
    mma_gemm<2><<<dim3(DFFz / 128, BMr / 128), 256>>>(mid, V1, hdn, DFFz, RFz, b1);
    mma_gemm<0><<<dim3(RFz / 128, BMr / 128), 256>>>(hdn, U2, t2, RFz, DFFz, nullptr);
    mma_gemm<1><<<dim3(DMz / 128, BMr / 128), 256>>>(t2, V2, y2, DMz, RFz, b2);

    // residual + LN2 -> out
    ln_k<<<BMr, 256>>>(x1, y2, ln2g, ln2b, out);
}

// round 4
// speedup vs baseline: 1.4963x; 1.3045x over previous
#include <cuda_runtime.h>
#include <math.h>
#include <stdint.h>

#define Bz 8
#define Mz 512
#define DMz 1024
#define Hz 16
#define DHz 64
#define DFFz 4096
#define RAz 32
#define RFz 384
#define ROz 384
#define BMr (Bz*Mz)          // 4096 rows
#define C3 (3*Hz*RAz)        // 1536
#define LN_EPS 1e-12f

// ---------------- scratch (device globals; no allocations allowed) ----------------
__device__ float g_Wcat[DMz * C3];
__device__ float g_T[BMr * C3];
__device__ float g_Q[Bz*Hz*Mz*DHz];
__device__ float g_K[Bz*Hz*Mz*DHz];
__device__ float g_V[Bz*Hz*Mz*DHz];
__device__ float g_S[(size_t)Bz*Hz*Mz*Mz];
__device__ float g_attn[BMr*DMz];
__device__ float g_t1[BMr*ROz];
__device__ float g_y1[BMr*DMz];
__device__ float g_x1[BMr*DMz];
__device__ float g_mid[BMr*RFz];
__device__ float g_hdn[(size_t)BMr*DFFz];
__device__ float g_t2[BMr*RFz];
__device__ float g_y2[BMr*DMz];

__device__ __forceinline__ float gelu_f(float x) {
    return 0.5f * x * (1.0f + erff(x * 0.70710678118654752440f));
}

__device__ __forceinline__ void tf32_split(float x, uint32_t& h, uint32_t& l) {
    uint32_t hi;
    asm("cvt.rna.tf32.f32 %0, %1;" : "=r"(hi) : "f"(x));
    float r = x - __uint_as_float(hi);
    uint32_t lo;
    asm("cvt.rna.tf32.f32 %0, %1;" : "=r"(lo) : "f"(r));
    h = hi; l = lo;
}

__device__ __forceinline__ void mma8(float* c, const uint32_t* a, const uint32_t* b) {
    asm volatile(
        "mma.sync.aligned.m16n8k8.row.col.f32.tf32.tf32.f32 "
        "{%0,%1,%2,%3}, {%4,%5,%6,%7}, {%8,%9}, {%0,%1,%2,%3};"
        : "+f"(c[0]), "+f"(c[1]), "+f"(c[2]), "+f"(c[3])
        : "r"(a[0]), "r"(a[1]), "r"(a[2]), "r"(a[3]), "r"(b[0]), "r"(b[1]));
}

__device__ __forceinline__ uint32_t smem_u32(const void* p) {
    return (uint32_t)__cvta_generic_to_shared(p);
}
__device__ __forceinline__ void cp16(uint32_t dst, const void* src) {
    asm volatile("cp.async.cg.shared.global [%0], [%1], 16;" :: "r"(dst), "l"(src));
}
#define CP_COMMIT() asm volatile("cp.async.commit_group;")
#define CP_WAIT1()  asm volatile("cp.async.wait_group 1;")

// split a raw fp32 fragment of 4 (A) or 2 (B)
__device__ __forceinline__ void split4(const float* r, uint32_t* h, uint32_t* l) {
#pragma unroll
    for (int j = 0; j < 4; j++) tf32_split(r[j], h[j], l[j]);
}
__device__ __forceinline__ void split2(const float* r, uint32_t* h, uint32_t* l) {
    tf32_split(r[0], h[0], l[0]);
    tf32_split(r[1], h[1], l[1]);
}

// ---------------- pack Pq/Pk/Pv -> Wcat ----------------
__global__ void pack_w(const float* __restrict__ Pq, const float* __restrict__ Pk,
                       const float* __restrict__ Pv) {
    int idx = blockIdx.x * blockDim.x + threadIdx.x;
    if (idx >= DMz * C3) return;
    int d = idx / C3;
    int c = idx % C3;
    int j = c / (Hz * RAz);
    int hr = c % (Hz * RAz);
    int h = hr / RAz, r = hr % RAz;
    const float* P = (j == 0) ? Pq : ((j == 1) ? Pk : Pv);
    g_Wcat[idx] = P[((size_t)h * DMz + d) * RAz + r];
}

// =====================================================================
// Generic tf32x3 GEMM, cp.async 2-stage pipeline.
// C[M,N] = A[M,K](row) @ B[K,N](row). CTA 128x128, BK=16, 8 warps.
// =====================================================================
template <int EPI>
__launch_bounds__(256)
__global__ void mma_gemm(const float* __restrict__ A, const float* __restrict__ B,
                         float* __restrict__ C, int N, int K,
                         const float* __restrict__ bias) {
    __shared__ float As[2][128][20];   // m-major, 16 k + 4 pad
    __shared__ float Bs[2][16][136];   // k-major, 128 n + 8 pad

    int tid = threadIdx.x;
    int lane = tid & 31, wid = tid >> 5;
    int warp_m = (wid >> 2) * 64;
    int warp_n = (wid & 3) * 32;
    int by = blockIdx.y, bx = blockIdx.x;

    int arow = tid >> 1, akq = (tid & 1) * 8;
    int brow = tid >> 4, bnq = (tid & 15) * 8;
    const float* Ag = A + (size_t)(by * 128 + arow) * K + akq;
    const float* Bg = B + (size_t)brow * N + bx * 128 + bnq;

    uint32_t a_dst[2], b_dst[2];
    a_dst[0] = smem_u32(&As[0][arow][akq]);
    a_dst[1] = smem_u32(&As[1][arow][akq]);
    b_dst[0] = smem_u32(&Bs[0][brow][bnq]);
    b_dst[1] = smem_u32(&Bs[1][brow][bnq]);

    float acc[4][4][4];
#pragma unroll
    for (int i = 0; i < 4; i++)
#pragma unroll
        for (int j = 0; j < 4; j++)
#pragma unroll
            for (int t = 0; t < 4; t++) acc[i][j][t] = 0.f;

    int nk = K >> 4;
    // prologue: stage 0
    {
        const float* ap = Ag;
        cp16(a_dst[0], ap); cp16(a_dst[0] + 16, ap + 4);
        const float* bp = Bg;
        cp16(b_dst[0], bp); cp16(b_dst[0] + 16, bp + 4);
        CP_COMMIT();
    }

    int mq = lane >> 2, kr = lane & 3;

    for (int kt = 0; kt < nk; kt++) {
        if (kt + 1 < nk) {
            int s = (kt + 1) & 1;
            const float* ap = Ag + (kt + 1) * 16;
            cp16(a_dst[s], ap); cp16(a_dst[s] + 16, ap + 4);
            const float* bp = Bg + (size_t)(kt + 1) * 16 * N;
            cp16(b_dst[s], bp); cp16(b_dst[s] + 16, bp + 4);
        }
        CP_COMMIT();
        CP_WAIT1();
        __syncthreads();
        int s = kt & 1;
#pragma unroll
        for (int ks = 0; ks < 16; ks += 8) {
            uint32_t ah[4][4], al[4][4], bh[4][2], bl[4][2];
#pragma unroll
            for (int mt = 0; mt < 4; mt++) {
                int mb = warp_m + mt * 16;
                float r[4];
                r[0] = As[s][mb + mq][ks + kr];
                r[1] = As[s][mb + 8 + mq][ks + kr];
                r[2] = As[s][mb + mq][ks + kr + 4];
                r[3] = As[s][mb + 8 + mq][ks + kr + 4];
                split4(r, ah[mt], al[mt]);
            }
#pragma unroll
            for (int nt = 0; nt < 4; nt++) {
                int nb = warp_n + nt * 8;
                float r[2];
                r[0] = Bs[s][ks + kr][nb + mq];
                r[1] = Bs[s][ks + kr + 4][nb + mq];
                split2(r, bh[nt], bl[nt]);
            }
#pragma unroll
            for (int mt = 0; mt < 4; mt++)
#pragma unroll
                for (int nt = 0; nt < 4; nt++) {
                    mma8(acc[mt][nt], ah[mt], bh[nt]);
                    mma8(acc[mt][nt], ah[mt], bl[nt]);
                    mma8(acc[mt][nt], al[mt], bh[nt]);
                }
        }
        __syncthreads();
    }

#pragma unroll
    for (int mt = 0; mt < 4; mt++)
#pragma unroll
        for (int nt = 0; nt < 4; nt++) {
            int row = by * 128 + warp_m + mt * 16 + mq;
            int col = bx * 128 + warp_n + nt * 8 + kr * 2;
            float2 v0 = make_float2(acc[mt][nt][0], acc[mt][nt][1]);
            float2 v1 = make_float2(acc[mt][nt][2], acc[mt][nt][3]);
            if (EPI >= 1) {
                float2 bb = *(const float2*)(bias + col);
                v0.x += bb.x; v0.y += bb.y;
                v1.x += bb.x; v1.y += bb.y;
            }
            if (EPI == 2) {
                v0.x = gelu_f(v0.x); v0.y = gelu_f(v0.y);
                v1.x = gelu_f(v1.x); v1.y = gelu_f(v1.y);
            }
            *(float2*)(C + (size_t)row * N + col) = v0;
            *(float2*)(C + (size_t)(row + 8) * N + col) = v1;
        }
}

// =====================================================================
// Batched scores = (Q K^T)/8. per z: M=N=512, K=64. CTA 128x128.
// =====================================================================
__launch_bounds__(256)
__global__ void mma_scores() {
    __shared__ float As[2][128][20];
    __shared__ float Ns[2][128][20];   // K-matrix rows (n-major)

    int tid = threadIdx.x;
    int lane = tid & 31, wid = tid >> 5;
    int warp_m = (wid >> 2) * 64;
    int warp_n = (wid & 3) * 32;
    int by = blockIdx.y, bx = blockIdx.x, z = blockIdx.z;

    const float* Qb = g_Q + (size_t)z * Mz * DHz;
    const float* Kb = g_K + (size_t)z * Mz * DHz;

    int arow = tid >> 1, akq = (tid & 1) * 8;
    const float* Ag = Qb + (size_t)(by * 128 + arow) * DHz + akq;
    const float* Bg = Kb + (size_t)(bx * 128 + arow) * DHz + akq;

    uint32_t a_dst[2], b_dst[2];
    a_dst[0] = smem_u32(&As[0][arow][akq]);
    a_dst[1] = smem_u32(&As[1][arow][akq]);
    b_dst[0] = smem_u32(&Ns[0][arow][akq]);
    b_dst[1] = smem_u32(&Ns[1][arow][akq]);

    float acc[4][4][4];
#pragma unroll
    for (int i = 0; i < 4; i++)
#pragma unroll
        for (int j = 0; j < 4; j++)
#pragma unroll
            for (int t = 0; t < 4; t++) acc[i][j][t] = 0.f;

    {
        cp16(a_dst[0], Ag); cp16(a_dst[0] + 16, Ag + 4);
        cp16(b_dst[0], Bg); cp16(b_dst[0] + 16, Bg + 4);
        CP_COMMIT();
    }
    int mq = lane >> 2, kr = lane & 3;
    const int nk = DHz >> 4;   // 4

    for (int kt = 0; kt < nk; kt++) {
        if (kt + 1 < nk) {
            int s = (kt + 1) & 1;
            const float* ap = Ag + (kt + 1) * 16;
            const float* bp = Bg + (kt + 1) * 16;
            cp16(a_dst[s], ap); cp16(a_dst[s] + 16, ap + 4);
            cp16(b_dst[s], bp); cp16(b_dst[s] + 16, bp + 4);
        }
        CP_COMMIT();
        CP_WAIT1();
        __syncthreads();
        int s = kt & 1;
#pragma unroll
        for (int ks = 0; ks < 16; ks += 8) {
            uint32_t ah[4][4], al[4][4], bh[4][2], bl[4][2];
#pragma unroll
            for (int mt = 0; mt < 4; mt++) {
                int mb = warp_m + mt * 16;
                float r[4];
                r[0] = As[s][mb + mq][ks + kr];
                r[1] = As[s][mb + 8 + mq][ks + kr];
                r[2] = As[s][mb + mq][ks + kr + 4];
                r[3] = As[s][mb + 8 + mq][ks + kr + 4];
                split4(r, ah[mt], al[mt]);
            }
#pragma unroll
            for (int nt = 0; nt < 4; nt++) {
                int nb = warp_n + nt * 8;
                float r[2];
                r[0] = Ns[s][nb + mq][ks + kr];
                r[1] = Ns[s][nb + mq][ks + kr + 4];
                split2(r, bh[nt], bl[nt]);
            }
#pragma unroll
            for (int mt = 0; mt < 4; mt++)
#pragma unroll
                for (int nt = 0; nt < 4; nt++) {
                    mma8(acc[mt][nt], ah[mt], bh[nt]);
                    mma8(acc[mt][nt], ah[mt], bl[nt]);
                    mma8(acc[mt][nt], al[mt], bh[nt]);
                }
        }
        __syncthreads();
    }

    float* Sb = g_S + (size_t)z * Mz * Mz;
#pragma unroll
    for (int mt = 0; mt < 4; mt++)
#pragma unroll
        for (int nt = 0; nt < 4; nt++) {
            int row = by * 128 + warp_m + mt * 16 + mq;
            int col = bx * 128 + warp_n + nt * 8 + kr * 2;
            float2 v0 = make_float2(acc[mt][nt][0] * 0.125f, acc[mt][nt][1] * 0.125f);
            float2 v1 = make_float2(acc[mt][nt][2] * 0.125f, acc[mt][nt][3] * 0.125f);
            *(float2*)(Sb + (size_t)row * Mz + col) = v0;
            *(float2*)(Sb + (size_t)(row + 8) * Mz + col) = v1;
        }
}

// =====================================================================
// Batched attn = probs @ V -> g_attn[b,m,h*64+d]. CTA 128x64, K=512.
// =====================================================================
__launch_bounds__(256)
__global__ void mma_attnv() {
    __shared__ float As[2][128][20];
    __shared__ float Bs[2][16][72];

    int tid = threadIdx.x;
    int lane = tid & 31, wid = tid >> 5;
    int warp_m = (wid >> 1) * 32;
    int warp_n = (wid & 1) * 32;
    int by = blockIdx.x, z = blockIdx.y;
    int b = z >> 4, h = z & 15;

    const float* Pb = g_S + (size_t)z * Mz * Mz;
    const float* Vb = g_V + (size_t)z * Mz * DHz;

    int arow = tid >> 1, akq = (tid & 1) * 8;
    int brow = tid >> 4, bnq = (tid & 15) * 4;
    const float* Ag = Pb + (size_t)(by * 128 + arow) * Mz + akq;
    const float* Bg = Vb + (size_t)brow * DHz + bnq;

    uint32_t a_dst[2], b_dst[2];
    a_dst[0] = smem_u32(&As[0][arow][akq]);
    a_dst[1] = smem_u32(&As[1][arow][akq]);
    b_dst[0] = smem_u32(&Bs[0][brow][bnq]);
    b_dst[1] = smem_u32(&Bs[1][brow][bnq]);

    float acc[2][4][4];
#pragma unroll
    for (int i = 0; i < 2; i++)
#pragma unroll
        for (int j = 0; j < 4; j++)
#pragma unroll
            for (int t = 0; t < 4; t++) acc[i][j][t] = 0.f;

    {
        cp16(a_dst[0], Ag); cp16(a_dst[0] + 16, Ag + 4);
        cp16(b_dst[0], Bg);
        CP_COMMIT();
    }
    int mq = lane >> 2, kr = lane & 3;
    const int nk = Mz >> 4;   // 32

    for (int kt = 0; kt < nk; kt++) {
        if (kt + 1 < nk) {
            int s = (kt + 1) & 1;
            const float* ap = Ag + (kt + 1) * 16;
            cp16(a_dst[s], ap); cp16(a_dst[s] + 16, ap + 4);
            const float* bp = Bg + (size_t)(kt + 1) * 16 * DHz;
            cp16(b_dst[s], bp);
        }
        CP_COMMIT();
        CP_WAIT1();
        __syncthreads();
        int s = kt & 1;
#pragma unroll
        for (int ks = 0; ks < 16; ks += 8) {
            uint32_t ah[2][4], al[2][4], bh[4][2], bl[4][2];
#pragma unroll
            for (int mt = 0; mt < 2; mt++) {
                int mb = warp_m + mt * 16;
                float r[4];
                r[0] = As[s][mb + mq][ks + kr];
                r[1] = As[s][mb + 8 + mq][ks + kr];
                r[2] = As[s][mb + mq][ks + kr + 4];
                r[3] = As[s][mb + 8 + mq][ks + kr + 4];
                split4(r, ah[mt], al[mt]);
            }
#pragma unroll
            for (int nt = 0; nt < 4; nt++) {
                int nb = warp_n + nt * 8;
                float r[2];
                r[0] = Bs[s][ks + kr][nb + mq];
                r[1] = Bs[s][ks + kr + 4][nb + mq];
                split2(r, bh[nt], bl[nt]);
            }
#pragma unroll
            for (int mt = 0; mt < 2; mt++)
#pragma unroll
                for (int nt = 0; nt < 4; nt++) {
                    mma8(acc[mt][nt], ah[mt], bh[nt]);
                    mma8(acc[mt][nt], ah[mt], bl[nt]);
                    mma8(acc[mt][nt], al[mt], bh[nt]);
                }
        }
        __syncthreads();
    }

#pragma unroll
    for (int mt = 0; mt < 2; mt++)
#pragma unroll
        for (int nt = 0; nt < 4; nt++) {
            int m = by * 128 + warp_m + mt * 16 + mq;
            int d = warp_n + nt * 8 + kr * 2;
            float2 v0 = make_float2(acc[mt][nt][0], acc[mt][nt][1]);
            float2 v1 = make_float2(acc[mt][nt][2], acc[mt][nt][3]);
            *(float2*)(g_attn + ((size_t)(b * Mz + m)) * DMz + h * DHz + d) = v0;
            *(float2*)(g_attn + ((size_t)(b * Mz + m + 8)) * DMz + h * DHz + d) = v1;
        }
}

// ---------------- rank-32 expansion ----------------
__launch_bounds__(256)
__global__ void qkv2_k(const float* __restrict__ Vq, const float* __restrict__ Vk,
                       const float* __restrict__ Vv, const float* __restrict__ bq,
                       const float* __restrict__ bk, const float* __restrict__ bv) {
    __shared__ float Vs[RAz][DHz];
    int z = blockIdx.y;
    int j = blockIdx.z;
    int b = z / Hz, h = z % Hz;
    const float* Vm = (j == 0) ? Vq : ((j == 1) ? Vk : Vv);
    const float* bm = (j == 0) ? bq : ((j == 1) ? bk : bv);
    float* out = (j == 0) ? g_Q : ((j == 1) ? g_K : g_V);

    int tid = threadIdx.y * 64 + threadIdx.x;
#pragma unroll
    for (int i = 0; i < 8; i++) {
        int idx = tid + i * 256;
        Vs[idx >> 6][idx & 63] = Vm[(size_t)h * RAz * DHz + idx];
    }
    __syncthreads();

    int m = blockIdx.x * 4 + threadIdx.y;
    int d = threadIdx.x;
    const float* trow = g_T + ((size_t)(b * Mz + m)) * C3 + j * (Hz * RAz) + h * RAz;
    float acc = bm[h * DHz + d];
#pragma unroll
    for (int r = 0; r < RAz; r++) acc += trow[r] * Vs[r][d];
    out[((size_t)z * Mz + m) * DHz + d] = acc;
}

// ---------------- row softmax (with additive mask) ----------------
__launch_bounds__(128)
__global__ void softmax_k(const float* __restrict__ mask) {
    __shared__ float sh[4];
    int row = blockIdx.x;
    int b = row / (Hz * Mz);
    float* s = g_S + (size_t)row * Mz;
    const float* mk = mask + (size_t)b * Mz;
    int tid = threadIdx.x;
    int lane = tid & 31, warp = tid >> 5;

    float v[4];
    float mx = -INFINITY;
#pragma unroll
    for (int i = 0; i < 4; i++) {
        int c = tid + i * 128;
        v[i] = s[c] + mk[c];
        mx = fmaxf(mx, v[i]);
    }
#pragma unroll
    for (int o = 16; o > 0; o >>= 1) mx = fmaxf(mx, __shfl_xor_sync(0xffffffffu, mx, o));
    if (lane == 0) sh[warp] = mx;
    __syncthreads();
    if (warp == 0) {
        float t = (lane < 4) ? sh[lane] : -INFINITY;
#pragma unroll
        for (int o = 2; o > 0; o >>= 1) t = fmaxf(t, __shfl_xor_sync(0xffffffffu, t, o));
        if (lane == 0) sh[0] = t;
    }
    __syncthreads();
    mx = sh[0];
    __syncthreads();

    float sum = 0.f;
#pragma unroll
    for (int i = 0; i < 4; i++) {
        v[i] = __expf(v[i] - mx);
        sum += v[i];
    }
#pragma unroll
    for (int o = 16; o > 0; o >>= 1) sum += __shfl_xor_sync(0xffffffffu, sum, o);
    if (lane == 0) sh[warp] = sum;
    __syncthreads();
    if (warp == 0) {
        float t = (lane < 4) ? sh[lane] : 0.f;
#pragma unroll
        for (int o = 2; o > 0; o >>= 1) t += __shfl_xor_sync(0xffffffffu, t, o);
        if (lane == 0) sh[0] = t;
    }
    __syncthreads();
    float inv = 1.0f / sh[0];
#pragma unroll
    for (int i = 0; i < 4; i++) s[tid + i * 128] = v[i] * inv;
}

// ---------------- residual + LayerNorm ----------------
__launch_bounds__(256)
__global__ void ln_k(const float* __restrict__ a, const float* __restrict__ r,
                     const float* __restrict__ g, const float* __restrict__ bb,
                     float* __restrict__ out) {
    __shared__ float sh[8];
    int row = blockIdx.x;
    int tid = threadIdx.x;
    int lane = tid & 31, warp = tid >> 5;
    const float* ap = a + (size_t)row * DMz;
    const float* rp = r + (size_t)row * DMz;
    float v[4];
    float s = 0.f;
#pragma unroll
    for (int i = 0; i < 4; i++) {
        int c = tid + i * 256;
        v[i] = ap[c] + rp[c];
        s += v[i];
    }
#pragma unroll
    for (int o = 16; o > 0; o >>= 1) s += __shfl_xor_sync(0xffffffffu, s, o);
    if (lane == 0) sh[warp] = s;
    __syncthreads();
    if (warp == 0) {
        float t = (lane < 8) ? sh[lane] : 0.f;
#pragma unroll
        for (int o = 4; o > 0; o >>= 1) t += __shfl_xor_sync(0xffffffffu, t, o);
        if (lane == 0) sh[0] = t;
    }
    __syncthreads();
    float mu = sh[0] * (1.0f / DMz);
    __syncthreads();

    float q = 0.f;
#pragma unroll
    for (int i = 0; i < 4; i++) {
        float d = v[i] - mu;
        q += d * d;
    }
#pragma unroll
    for (int o = 16; o > 0; o >>= 1) q += __shfl_xor_sync(0xffffffffu, q, o);
    if (lane == 0) sh[warp] = q;
    __syncthreads();
    if (warp == 0) {
        float t = (lane < 8) ? sh[lane] : 0.f;
#pragma unroll
        for (int o = 4; o > 0; o >>= 1) t += __shfl_xor_sync(0xffffffffu, t, o);
        if (lane == 0) sh[0] = t;
    }
    __syncthreads();
    float var = sh[0] * (1.0f / DMz);
    float rs = rsqrtf(var + LN_EPS);
#pragma unroll
    for (int i = 0; i < 4; i++) {
        int c = tid + i * 256;
        out[(size_t)row * DMz + c] = (v[i] - mu) * rs * g[c] + bb[c];
    }
}

// ---------------- launch ----------------
extern "C" void kernel_launch(void* const* d_in, const int* in_sizes, int n_in,
                              void* d_out, int out_size) {
    const float* x    = (const float*)d_in[0];
    const float* mask = (const float*)d_in[1];
    const float* Pq   = (const float*)d_in[2];
    const float* Vq   = (const float*)d_in[3];
    const float* Pk   = (const float*)d_in[4];
    const float* Vk   = (const float*)d_in[5];
    const float* Pv   = (const float*)d_in[6];
    const float* Vv   = (const float*)d_in[7];
    const float* bq   = (const float*)d_in[8];
    const float* bk   = (const float*)d_in[9];
    const float* bv   = (const float*)d_in[10];
    const float* Uo   = (const float*)d_in[11];
    const float* Vo   = (const float*)d_in[12];
    const float* bo   = (const float*)d_in[13];
    const float* U1   = (const float*)d_in[14];
    const float* V1   = (const float*)d_in[15];
    const float* b1   = (const float*)d_in[16];
    const float* U2   = (const float*)d_in[17];
    const float* V2   = (const float*)d_in[18];
    const float* b2   = (const float*)d_in[19];
    const float* ln1g = (const float*)d_in[20];
    const float* ln1b = (const float*)d_in[21];
    const float* ln2g = (const float*)d_in[22];
    const float* ln2b = (const float*)d_in[23];
    float* out = (float*)d_out;

    float *Wcat, *T, *attn, *t1, *y1, *x1, *mid, *hdn, *t2, *y2;
    cudaGetSymbolAddress((void**)&Wcat, g_Wcat);
    cudaGetSymbolAddress((void**)&T, g_T);
    cudaGetSymbolAddress((void**)&attn, g_attn);
    cudaGetSymbolAddress((void**)&t1, g_t1);
    cudaGetSymbolAddress((void**)&y1, g_y1);
    cudaGetSymbolAddress((void**)&x1, g_x1);
    cudaGetSymbolAddress((void**)&mid, g_mid);
    cudaGetSymbolAddress((void**)&hdn, g_hdn);
    cudaGetSymbolAddress((void**)&t2, g_t2);
    cudaGetSymbolAddress((void**)&y2, g_y2);

    // qkv low-rank projection
    pack_w<<<(DMz * C3 + 255) / 256, 256>>>(Pq, Pk, Pv);
    mma_gemm<0><<<dim3(C3 / 128, BMr / 128), 256>>>(x, Wcat, T, C3, DMz, nullptr);
    qkv2_k<<<dim3(Mz / 4, Bz * Hz, 3), dim3(64, 4)>>>(Vq, Vk, Vv, bq, bk, bv);

    // attention
    mma_scores<<<dim3(Mz / 128, Mz / 128, Bz * Hz), 256>>>();
    softmax_k<<<Bz * Hz * Mz, 128>>>(mask);
    mma_attnv<<<dim3(Mz / 128, Bz * Hz), 256>>>();

    // output projection + residual + LN1
    mma_gemm<0><<<dim3(ROz / 128, BMr / 128), 256>>>(attn, Uo, t1, ROz, DMz, nullptr);
    mma_gemm<1><<<dim3(DMz / 128, BMr / 128), 256>>>(t1, Vo, y1, DMz, ROz, bo);
    ln_k<<<BMr, 256>>>(x, y1, ln1g, ln1b, x1);

    // FFN
    mma_gemm<0><<<dim3(RFz / 128, BMr / 128), 256>>>(x1, U1, mid, RFz, DMz, nullptr);
    mma_gemm<2><<<dim3(DFFz / 128, BMr / 128), 256>>>(mid, V1, hdn, DFFz, RFz, b1);
    mma_gemm<0><<<dim3(RFz / 128, BMr / 128), 256>>>(hdn, U2, t2, RFz, DFFz, nullptr);
    mma_gemm<1><<<dim3(DMz / 128, BMr / 128), 256>>>(t2, V2, y2, DMz, RFz, b2);

    // residual + LN2 -> out
    ln_k<<<BMr, 256>>>(x1, y2, ln2g, ln2b, out);
}

// round 8
// speedup vs baseline: 1.8128x; 1.2115x over previous
#include <cuda_runtime.h>
#include <cuda_fp16.h>
#include <math.h>
#include <stdint.h>

#define Bz 8
#define Mz 512
#define DMz 1024
#define Hz 16
#define DHz 64
#define DFFz 4096
#define RAz 32
#define RFz 384
#define ROz 384
#define BMr (Bz*Mz)          // 4096
#define C3 (3*Hz*RAz)        // 1536
#define ZT (Bz*Hz)           // 128
#define LN_EPS 1e-12f

// ---------------- scratch (device globals) ----------------
// split pair arrays: u32 = half2(hi0,hi1) along the K dimension
__device__ uint32_t g_xh[BMr*512],  g_xl[BMr*512];          // x   A-fmt [4096][512]
__device__ uint32_t g_wch[512*C3],  g_wcl[512*C3];          // Wcat B-fmt [512][1536]
__device__ float    g_T[BMr*C3];
__device__ uint32_t g_Qh[ZT*Mz*32], g_Ql[ZT*Mz*32];         // [z][512][32]
__device__ uint32_t g_Kh[ZT*Mz*32], g_Kl[ZT*Mz*32];
__device__ uint32_t g_Vh[ZT*256*64], g_Vl[ZT*256*64];       // B-fmt [z][256][64]
__device__ float    g_S[(size_t)ZT*Mz*Mz];
__device__ uint32_t g_Ph[(size_t)ZT*Mz*256], g_Pl[(size_t)ZT*Mz*256]; // probs A-fmt
__device__ uint32_t g_ath[BMr*512], g_atl[BMr*512];         // attn A-fmt [4096][512]
__device__ uint32_t g_Uoh[512*ROz],  g_Uol[512*ROz];
__device__ uint32_t g_Voh[192*DMz],  g_Vol[192*DMz];
__device__ uint32_t g_U1h[512*RFz],  g_U1l[512*RFz];
__device__ uint32_t g_V1h[192*DFFz], g_V1l[192*DFFz];
__device__ uint32_t g_U2h[2048*RFz], g_U2l[2048*RFz];
__device__ uint32_t g_V2h[192*DMz],  g_V2l[192*DMz];
__device__ uint32_t g_t1h[BMr*192],  g_t1l[BMr*192];
__device__ float    g_y1[BMr*DMz];
__device__ float    g_x1[BMr*DMz];
__device__ uint32_t g_x1h[BMr*512],  g_x1l[BMr*512];
__device__ uint32_t g_mdh[BMr*192],  g_mdl[BMr*192];
__device__ uint32_t g_hdh[(size_t)BMr*2048], g_hdl[(size_t)BMr*2048];
__device__ uint32_t g_t2h[BMr*192],  g_t2l[BMr*192];
__device__ float    g_y2[BMr*DMz];

// ---------------- helpers ----------------
__device__ __forceinline__ float gelu_f(float x) {
    return 0.5f * x * (1.0f + erff(x * 0.70710678118654752440f));
}
__device__ __forceinline__ void split_pair(float x0, float x1, uint32_t& uh, uint32_t& ul) {
    __half h0 = __float2half_rn(x0);
    __half h1 = __float2half_rn(x1);
    __half l0 = __float2half_rn(x0 - __half2float(h0));
    __half l1 = __float2half_rn(x1 - __half2float(h1));
    __half2 hh = __halves2half2(h0, h1);
    __half2 ll = __halves2half2(l0, l1);
    uh = *(uint32_t*)&hh;
    ul = *(uint32_t*)&ll;
}
__device__ __forceinline__ void mma16(float* c, const uint32_t* a, const uint32_t* b) {
    asm volatile(
        "mma.sync.aligned.m16n8k16.row.col.f32.f16.f16.f32 "
        "{%0,%1,%2,%3}, {%4,%5,%6,%7}, {%8,%9}, {%0,%1,%2,%3};"
        : "+f"(c[0]), "+f"(c[1]), "+f"(c[2]), "+f"(c[3])
        : "r"(a[0]), "r"(a[1]), "r"(a[2]), "r"(a[3]), "r"(b[0]), "r"(b[1]));
}
__device__ __forceinline__ uint32_t smem_u32(const void* p) {
    return (uint32_t)__cvta_generic_to_shared(p);
}
__device__ __forceinline__ void cp16(uint32_t dst, const void* src) {
    asm volatile("cp.async.cg.shared.global [%0], [%1], 16;" :: "r"(dst), "l"(src));
}
#define CP_COMMIT() asm volatile("cp.async.commit_group;")
#define CP_WAIT1()  asm volatile("cp.async.wait_group 1;")

// ---------------- conversion kernels ----------------
__global__ void conv_x(const float* __restrict__ x) {
    int idx = blockIdx.x * blockDim.x + threadIdx.x;   // 4096*512
    int row = idx >> 9, p = idx & 511;
    float2 v = *(const float2*)(x + (size_t)row * DMz + 2 * p);
    split_pair(v.x, v.y, g_xh[idx], g_xl[idx]);
}
__global__ void pack_w_split(const float* __restrict__ Pq, const float* __restrict__ Pk,
                             const float* __restrict__ Pv) {
    int idx = blockIdx.x * blockDim.x + threadIdx.x;   // 512*1536
    int kp = idx / C3, c = idx % C3;
    int j = c / 512, hr = c % 512, h = hr >> 5, r = hr & 31;
    const float* P = (j == 0) ? Pq : ((j == 1) ? Pk : Pv);
    float v0 = P[((size_t)h * DMz + 2 * kp) * RAz + r];
    float v1 = P[((size_t)h * DMz + 2 * kp + 1) * RAz + r];
    split_pair(v0, v1, g_wch[idx], g_wcl[idx]);
}
__global__ void convB(const float* __restrict__ W, uint32_t* __restrict__ oh,
                      uint32_t* __restrict__ ol, int K2, int N) {
    int idx = blockIdx.x * blockDim.x + threadIdx.x;
    if (idx >= K2 * N) return;
    int kp = idx / N, n = idx % N;
    float v0 = W[(size_t)(2 * kp) * N + n];
    float v1 = W[(size_t)(2 * kp + 1) * N + n];
    split_pair(v0, v1, oh[idx], ol[idx]);
}

// =====================================================================
// Generic fp16x3 GEMM. CTAM in {128, 64}. A: [M][K/2] pairs. B: [K/2][N] pairs.
// EPI: 0 none, 1 bias, 2 bias+gelu. Outputs: fp32 and/or split pairs.
// =====================================================================
template <int CTAM, bool OF32, bool OSPL, int EPI>
__launch_bounds__(256, 2)
__global__ void hgemm(const uint32_t* __restrict__ Ah, const uint32_t* __restrict__ Al,
                      const uint32_t* __restrict__ Bh, const uint32_t* __restrict__ Bl,
                      float* __restrict__ Cf, uint32_t* __restrict__ Ch,
                      uint32_t* __restrict__ Cl, int N, int K,
                      const float* __restrict__ bias) {
    constexpr int MT = CTAM / 32;           // 4 or 2
    __shared__ uint32_t Ash[3][CTAM][8], Asl[3][CTAM][8];
    __shared__ uint32_t Bsh[3][8][128], Bsl[3][8][128];

    int tid = threadIdx.x, lane = tid & 31, wid = tid >> 5;
    int warp_m = (wid >> 2) * (CTAM / 2);
    int warp_n = (wid & 3) * 32;
    int by = blockIdx.y, bx = blockIdx.x;
    int kp2 = K >> 1;
    int mq = lane >> 2, kq = lane & 3, sw = mq & 4;
    int nk = K >> 4;

    auto load_stage = [&](int kt, int s) {
        if (tid < CTAM * 2) {
            int row = tid >> 1, hf = (tid & 1) * 4;
            int cc = hf ^ (row & 4);
            size_t so = (size_t)(by * CTAM + row) * kp2 + kt * 8 + hf;
            cp16(smem_u32(&Ash[s][row][cc]), Ah + so);
            cp16(smem_u32(&Asl[s][row][cc]), Al + so);
        }
        {
            int kp = tid >> 5, c0 = (tid & 31) * 4;
            int cc = c0 ^ (kp * 8);
            size_t so = (size_t)(kt * 8 + kp) * N + bx * 128 + c0;
            cp16(smem_u32(&Bsh[s][kp][cc]), Bh + so);
            cp16(smem_u32(&Bsl[s][kp][cc]), Bl + so);
        }
    };

    float acc[MT][4][4];
#pragma unroll
    for (int i = 0; i < MT; i++)
#pragma unroll
        for (int j = 0; j < 4; j++)
#pragma unroll
            for (int t = 0; t < 4; t++) acc[i][j][t] = 0.f;

    load_stage(0, 0); CP_COMMIT();
    load_stage(1, 1); CP_COMMIT();

    for (int kt = 0; kt < nk; kt++) {
        CP_WAIT1();
        __syncthreads();
        int s = kt % 3;
        uint32_t fbh[4][2], fbl[4][2];
#pragma unroll
        for (int nt = 0; nt < 4; nt++) {
            int n = warp_n + nt * 8 + mq;
            int c1 = n ^ (kq * 8);
            fbh[nt][0] = Bsh[s][kq][c1];
            fbh[nt][1] = Bsh[s][kq + 4][c1 ^ 32];
            fbl[nt][0] = Bsl[s][kq][c1];
            fbl[nt][1] = Bsl[s][kq + 4][c1 ^ 32];
        }
#pragma unroll
        for (int mt = 0; mt < MT; mt++) {
            int r0 = warp_m + mt * 16 + mq;
            uint32_t fah[4], fal[4];
            fah[0] = Ash[s][r0][kq ^ sw];
            fah[1] = Ash[s][r0 + 8][kq ^ sw];
            fah[2] = Ash[s][r0][(kq + 4) ^ sw];
            fah[3] = Ash[s][r0 + 8][(kq + 4) ^ sw];
            fal[0] = Asl[s][r0][kq ^ sw];
            fal[1] = Asl[s][r0 + 8][kq ^ sw];
            fal[2] = Asl[s][r0][(kq + 4) ^ sw];
            fal[3] = Asl[s][r0 + 8][(kq + 4) ^ sw];
#pragma unroll
            for (int nt = 0; nt < 4; nt++) {
                mma16(acc[mt][nt], fah, fbh[nt]);
                mma16(acc[mt][nt], fah, fbl[nt]);
                mma16(acc[mt][nt], fal, fbh[nt]);
            }
        }
        if (kt + 2 < nk) load_stage(kt + 2, (kt + 2) % 3);
        CP_COMMIT();
    }

#pragma unroll
    for (int mt = 0; mt < MT; mt++)
#pragma unroll
        for (int nt = 0; nt < 4; nt++) {
            int row = by * CTAM + warp_m + mt * 16 + mq;
            int col = bx * 128 + warp_n + nt * 8 + kq * 2;
            float v0 = acc[mt][nt][0], v1 = acc[mt][nt][1];
            float v2 = acc[mt][nt][2], v3 = acc[mt][nt][3];
            if (EPI >= 1) {
                float b0 = bias[col], b1 = bias[col + 1];
                v0 += b0; v1 += b1; v2 += b0; v3 += b1;
            }
            if (EPI == 2) {
                v0 = gelu_f(v0); v1 = gelu_f(v1); v2 = gelu_f(v2); v3 = gelu_f(v3);
            }
            if (OF32) {
                *(float2*)(Cf + (size_t)row * N + col) = make_float2(v0, v1);
                *(float2*)(Cf + (size_t)(row + 8) * N + col) = make_float2(v2, v3);
            }
            if (OSPL) {
                uint32_t uh, ul;
                size_t o = (size_t)row * (N >> 1) + (col >> 1);
                split_pair(v0, v1, uh, ul);
                Ch[o] = uh; Cl[o] = ul;
                o = (size_t)(row + 8) * (N >> 1) + (col >> 1);
                split_pair(v2, v3, uh, ul);
                Ch[o] = uh; Cl[o] = ul;
            }
        }
}

// =====================================================================
// scores = (Q K^T)/8 per z. CTA 128x128, K=64 (nk=4).
// =====================================================================
__launch_bounds__(256, 2)
__global__ void hscores() {
    __shared__ uint32_t Qsh[3][128][8], Qsl[3][128][8];
    __shared__ uint32_t Ksh[3][128][8], Ksl[3][128][8];

    int tid = threadIdx.x, lane = tid & 31, wid = tid >> 5;
    int warp_m = (wid >> 2) * 64, warp_n = (wid & 3) * 32;
    int by = blockIdx.y, bx = blockIdx.x, z = blockIdx.z;
    int mq = lane >> 2, kq = lane & 3, sw = mq & 4;

    const uint32_t* Qhb = g_Qh + (size_t)z * Mz * 32;
    const uint32_t* Qlb = g_Ql + (size_t)z * Mz * 32;
    const uint32_t* Khb = g_Kh + (size_t)z * Mz * 32;
    const uint32_t* Klb = g_Kl + (size_t)z * Mz * 32;

    auto load_stage = [&](int kt, int s) {
        int row = tid >> 1, hf = (tid & 1) * 4;
        int cc = hf ^ (row & 4);
        size_t soq = (size_t)(by * 128 + row) * 32 + kt * 8 + hf;
        size_t sok = (size_t)(bx * 128 + row) * 32 + kt * 8 + hf;
        cp16(smem_u32(&Qsh[s][row][cc]), Qhb + soq);
        cp16(smem_u32(&Qsl[s][row][cc]), Qlb + soq);
        cp16(smem_u32(&Ksh[s][row][cc]), Khb + sok);
        cp16(smem_u32(&Ksl[s][row][cc]), Klb + sok);
    };

    float acc[4][4][4];
#pragma unroll
    for (int i = 0; i < 4; i++)
#pragma unroll
        for (int j = 0; j < 4; j++)
#pragma unroll
            for (int t = 0; t < 4; t++) acc[i][j][t] = 0.f;

    load_stage(0, 0); CP_COMMIT();
    load_stage(1, 1); CP_COMMIT();

    const int nk = 4;
    for (int kt = 0; kt < nk; kt++) {
        CP_WAIT1();
        __syncthreads();
        int s = kt % 3;
        uint32_t fbh[4][2], fbl[4][2];
#pragma unroll
        for (int nt = 0; nt < 4; nt++) {
            int n = warp_n + nt * 8 + mq;
            fbh[nt][0] = Ksh[s][n][kq ^ sw];
            fbh[nt][1] = Ksh[s][n][(kq + 4) ^ sw];
            fbl[nt][0] = Ksl[s][n][kq ^ sw];
            fbl[nt][1] = Ksl[s][n][(kq + 4) ^ sw];
        }
#pragma unroll
        for (int mt = 0; mt < 4; mt++) {
            int r0 = warp_m + mt * 16 + mq;
            uint32_t fah[4], fal[4];
            fah[0] = Qsh[s][r0][kq ^ sw];
            fah[1] = Qsh[s][r0 + 8][kq ^ sw];
            fah[2] = Qsh[s][r0][(kq + 4) ^ sw];
            fah[3] = Qsh[s][r0 + 8][(kq + 4) ^ sw];
            fal[0] = Qsl[s][r0][kq ^ sw];
            fal[1] = Qsl[s][r0 + 8][kq ^ sw];
            fal[2] = Qsl[s][r0][(kq + 4) ^ sw];
            fal[3] = Qsl[s][r0 + 8][(kq + 4) ^ sw];
#pragma unroll
            for (int nt = 0; nt < 4; nt++) {
                mma16(acc[mt][nt], fah, fbh[nt]);
                mma16(acc[mt][nt], fah, fbl[nt]);
                mma16(acc[mt][nt], fal, fbh[nt]);
            }
        }
        if (kt + 2 < nk) load_stage(kt + 2, (kt + 2) % 3);
        CP_COMMIT();
    }

    float* Sb = g_S + (size_t)z * Mz * Mz;
#pragma unroll
    for (int mt = 0; mt < 4; mt++)
#pragma unroll
        for (int nt = 0; nt < 4; nt++) {
            int row = by * 128 + warp_m + mt * 16 + mq;
            int col = bx * 128 + warp_n + nt * 8 + kq * 2;
            *(float2*)(Sb + (size_t)row * Mz + col) =
                make_float2(acc[mt][nt][0] * 0.125f, acc[mt][nt][1] * 0.125f);
            *(float2*)(Sb + (size_t)(row + 8) * Mz + col) =
                make_float2(acc[mt][nt][2] * 0.125f, acc[mt][nt][3] * 0.125f);
        }
}

// =====================================================================
// attn = probs @ V per z. CTA 128x64, K=512 (nk=32). Writes split pairs.
// =====================================================================
__launch_bounds__(256, 2)
__global__ void hattnv() {
    __shared__ uint32_t Psh[3][128][8], Psl[3][128][8];
    __shared__ uint32_t Vsh[3][8][64], Vsl[3][8][64];

    int tid = threadIdx.x, lane = tid & 31, wid = tid >> 5;
    int warp_m = (wid >> 1) * 32, warp_n = (wid & 1) * 32;
    int by = blockIdx.x, z = blockIdx.y;
    int b = z >> 4, h = z & 15;
    int mq = lane >> 2, kq = lane & 3, sw = mq & 4;

    const uint32_t* Phb = g_Ph + (size_t)z * Mz * 256;
    const uint32_t* Plb = g_Pl + (size_t)z * Mz * 256;
    const uint32_t* Vhb = g_Vh + (size_t)z * 256 * 64;
    const uint32_t* Vlb = g_Vl + (size_t)z * 256 * 64;

    auto load_stage = [&](int kt, int s) {
        {
            int row = tid >> 1, hf = (tid & 1) * 4;
            int cc = hf ^ (row & 4);
            size_t so = (size_t)(by * 128 + row) * 256 + kt * 8 + hf;
            cp16(smem_u32(&Psh[s][row][cc]), Phb + so);
            cp16(smem_u32(&Psl[s][row][cc]), Plb + so);
        }
        if (tid < 128) {
            int kp = tid >> 4, c0 = (tid & 15) * 4;
            int cc = c0 ^ (kp * 8);
            size_t so = (size_t)(kt * 8 + kp) * 64 + c0;
            cp16(smem_u32(&Vsh[s][kp][cc]), Vhb + so);
            cp16(smem_u32(&Vsl[s][kp][cc]), Vlb + so);
        }
    };

    float acc[2][4][4];
#pragma unroll
    for (int i = 0; i < 2; i++)
#pragma unroll
        for (int j = 0; j < 4; j++)
#pragma unroll
            for (int t = 0; t < 4; t++) acc[i][j][t] = 0.f;

    load_stage(0, 0); CP_COMMIT();
    load_stage(1, 1); CP_COMMIT();

    const int nk = 32;
    for (int kt = 0; kt < nk; kt++) {
        CP_WAIT1();
        __syncthreads();
        int s = kt % 3;
        uint32_t fbh[4][2], fbl[4][2];
#pragma unroll
        for (int nt = 0; nt < 4; nt++) {
            int n = warp_n + nt * 8 + mq;
            int c1 = n ^ (kq * 8);
            fbh[nt][0] = Vsh[s][kq][c1];
            fbh[nt][1] = Vsh[s][kq + 4][c1 ^ 32];
            fbl[nt][0] = Vsl[s][kq][c1];
            fbl[nt][1] = Vsl[s][kq + 4][c1 ^ 32];
        }
#pragma unroll
        for (int mt = 0; mt < 2; mt++) {
            int r0 = warp_m + mt * 16 + mq;
            uint32_t fah[4], fal[4];
            fah[0] = Psh[s][r0][kq ^ sw];
            fah[1] = Psh[s][r0 + 8][kq ^ sw];
            fah[2] = Psh[s][r0][(kq + 4) ^ sw];
            fah[3] = Psh[s][r0 + 8][(kq + 4) ^ sw];
            fal[0] = Psl[s][r0][kq ^ sw];
            fal[1] = Psl[s][r0 + 8][kq ^ sw];
            fal[2] = Psl[s][r0][(kq + 4) ^ sw];
            fal[3] = Psl[s][r0 + 8][(kq + 4) ^ sw];
#pragma unroll
            for (int nt = 0; nt < 4; nt++) {
                mma16(acc[mt][nt], fah, fbh[nt]);
                mma16(acc[mt][nt], fah, fbl[nt]);
                mma16(acc[mt][nt], fal, fbh[nt]);
            }
        }
        if (kt + 2 < nk) load_stage(kt + 2, (kt + 2) % 3);
        CP_COMMIT();
    }

#pragma unroll
    for (int mt = 0; mt < 2; mt++)
#pragma unroll
        for (int nt = 0; nt < 4; nt++) {
            int m = by * 128 + warp_m + mt * 16 + mq;
            int d = warp_n + nt * 8 + kq * 2;
            int colp = (h * DHz + d) >> 1;
            uint32_t uh, ul;
            split_pair(acc[mt][nt][0], acc[mt][nt][1], uh, ul);
            size_t o = (size_t)(b * Mz + m) * 512 + colp;
            g_ath[o] = uh; g_atl[o] = ul;
            split_pair(acc[mt][nt][2], acc[mt][nt][3], uh, ul);
            o = (size_t)(b * Mz + m + 8) * 512 + colp;
            g_ath[o] = uh; g_atl[o] = ul;
        }
}

// ---------------- rank-32 expansion + split-pack ----------------
__launch_bounds__(256)
__global__ void qkv2_k(const float* __restrict__ Vq, const float* __restrict__ Vk,
                       const float* __restrict__ Vv, const float* __restrict__ bq,
                       const float* __restrict__ bk, const float* __restrict__ bv) {
    __shared__ float Vs[RAz][DHz];
    __shared__ float tile[8][65];
    int z = blockIdx.y, j = blockIdx.z;
    int b = z / Hz, h = z % Hz;
    const float* Vm = (j == 0) ? Vq : ((j == 1) ? Vk : Vv);
    const float* bm = (j == 0) ? bq : ((j == 1) ? bk : bv);
    int tid = threadIdx.x;
#pragma unroll
    for (int i = 0; i < 8; i++) {
        int idx = tid + i * 256;
        Vs[idx >> 6][idx & 63] = Vm[(size_t)h * RAz * DHz + idx];
    }
    __syncthreads();

    int m0 = blockIdx.x * 8;
    int d = tid & 63, ml = tid >> 6;
#pragma unroll
    for (int rr = 0; rr < 2; rr++) {
        int r = ml + rr * 4;
        int m = m0 + r;
        const float* trow = g_T + ((size_t)(b * Mz + m)) * C3 + j * 512 + h * RAz;
        float acc = bm[h * DHz + d];
#pragma unroll
        for (int k = 0; k < RAz; k++) acc += trow[k] * Vs[k][d];
        tile[r][d] = acc;
    }
    __syncthreads();

    if (j < 2) {
        // pairs along d
        int m = tid >> 5, dp = tid & 31;
        uint32_t uh, ul;
        split_pair(tile[m][2 * dp], tile[m][2 * dp + 1], uh, ul);
        size_t o = ((size_t)z * Mz + m0 + m) * 32 + dp;
        if (j == 0) { g_Qh[o] = uh; g_Ql[o] = ul; }
        else        { g_Kh[o] = uh; g_Kl[o] = ul; }
    } else {
        // pairs along m
        int mp = tid >> 6, dd = tid & 63;
        uint32_t uh, ul;
        split_pair(tile[2 * mp][dd], tile[2 * mp + 1][dd], uh, ul);
        size_t o = ((size_t)z * 256 + (m0 >> 1) + mp) * 64 + dd;
        g_Vh[o] = uh; g_Vl[o] = ul;
    }
}

// ---------------- softmax (reads fp32 S, writes split probs) ----------------
__launch_bounds__(128)
__global__ void softmax_k(const float* __restrict__ mask) {
    __shared__ float sh[4];
    int row = blockIdx.x;
    int b = row / (Hz * Mz);
    const float* s = g_S + (size_t)row * Mz;
    const float* mk = mask + (size_t)b * Mz;
    int tid = threadIdx.x;
    int lane = tid & 31, warp = tid >> 5;
    int c = tid * 4;

    float4 v = *(const float4*)(s + c);
    float4 mv = *(const float4*)(mk + c);
    v.x += mv.x; v.y += mv.y; v.z += mv.z; v.w += mv.w;
    float mx = fmaxf(fmaxf(v.x, v.y), fmaxf(v.z, v.w));
#pragma unroll
    for (int o = 16; o > 0; o >>= 1) mx = fmaxf(mx, __shfl_xor_sync(0xffffffffu, mx, o));
    if (lane == 0) sh[warp] = mx;
    __syncthreads();
    if (warp == 0) {
        float t = (lane < 4) ? sh[lane] : -INFINITY;
#pragma unroll
        for (int o = 2; o > 0; o >>= 1) t = fmaxf(t, __shfl_xor_sync(0xffffffffu, t, o));
        if (lane == 0) sh[0] = t;
    }
    __syncthreads();
    mx = sh[0];
    __syncthreads();

    v.x = __expf(v.x - mx); v.y = __expf(v.y - mx);
    v.z = __expf(v.z - mx); v.w = __expf(v.w - mx);
    float sum = v.x + v.y + v.z + v.w;
#pragma unroll
    for (int o = 16; o > 0; o >>= 1) sum += __shfl_xor_sync(0xffffffffu, sum, o);
    if (lane == 0) sh[warp] = sum;
    __syncthreads();
    if (warp == 0) {
        float t = (lane < 4) ? sh[lane] : 0.f;
#pragma unroll
        for (int o = 2; o > 0; o >>= 1) t += __shfl_xor_sync(0xffffffffu, t, o);
        if (lane == 0) sh[0] = t;
    }
    __syncthreads();
    float inv = 1.0f / sh[0];
    v.x *= inv; v.y *= inv; v.z *= inv; v.w *= inv;

    uint32_t uh, ul;
    size_t o = (size_t)row * 256 + (c >> 1);
    split_pair(v.x, v.y, uh, ul);
    g_Ph[o] = uh; g_Pl[o] = ul;
    split_pair(v.z, v.w, uh, ul);
    g_Ph[o + 1] = uh; g_Pl[o + 1] = ul;
}

// ---------------- residual + LayerNorm (ln1: fp32 + split; ln2: fp32 out) ----------------
template <bool SPLIT>
__launch_bounds__(256)
__global__ void ln_k(const float* __restrict__ a, const float* __restrict__ r,
                     const float* __restrict__ g, const float* __restrict__ bb,
                     float* __restrict__ out) {
    __shared__ float sh[8];
    int row = blockIdx.x;
    int tid = threadIdx.x;
    int lane = tid & 31, warp = tid >> 5;
    int c = tid * 4;
    float4 xa = *(const float4*)(a + (size_t)row * DMz + c);
    float4 ya = *(const float4*)(r + (size_t)row * DMz + c);
    float v[4] = {xa.x + ya.x, xa.y + ya.y, xa.z + ya.z, xa.w + ya.w};
    float s = v[0] + v[1] + v[2] + v[3];
#pragma unroll
    for (int o = 16; o > 0; o >>= 1) s += __shfl_xor_sync(0xffffffffu, s, o);
    if (lane == 0) sh[warp] = s;
    __syncthreads();
    if (warp == 0) {
        float t = (lane < 8) ? sh[lane] : 0.f;
#pragma unroll
        for (int o = 4; o > 0; o >>= 1) t += __shfl_xor_sync(0xffffffffu, t, o);
        if (lane == 0) sh[0] = t;
    }
    __syncthreads();
    float mu = sh[0] * (1.0f / DMz);
    __syncthreads();

    float q = 0.f;
#pragma unroll
    for (int i = 0; i < 4; i++) {
        float d = v[i] - mu;
        q += d * d;
    }
#pragma unroll
    for (int o = 16; o > 0; o >>= 1) q += __shfl_xor_sync(0xffffffffu, q, o);
    if (lane == 0) sh[warp] = q;
    __syncthreads();
    if (warp == 0) {
        float t = (lane < 8) ? sh[lane] : 0.f;
#pragma unroll
        for (int o = 4; o > 0; o >>= 1) t += __shfl_xor_sync(0xffffffffu, t, o);
        if (lane == 0) sh[0] = t;
    }
    __syncthreads();
    float var = sh[0] * (1.0f / DMz);
    float rs = rsqrtf(var + LN_EPS);
    float4 gg = *(const float4*)(g + c);
    float4 bbv = *(const float4*)(bb + c);
    float o0 = (v[0] - mu) * rs * gg.x + bbv.x;
    float o1 = (v[1] - mu) * rs * gg.y + bbv.y;
    float o2 = (v[2] - mu) * rs * gg.z + bbv.z;
    float o3 = (v[3] - mu) * rs * gg.w + bbv.w;
    *(float4*)(out + (size_t)row * DMz + c) = make_float4(o0, o1, o2, o3);
    if (SPLIT) {
        uint32_t uh, ul;
        size_t o = (size_t)row * 512 + (c >> 1);
        split_pair(o0, o1, uh, ul);
        g_x1h[o] = uh; g_x1l[o] = ul;
        split_pair(o2, o3, uh, ul);
        g_x1h[o + 1] = uh; g_x1l[o + 1] = ul;
    }
}

// ---------------- launch ----------------
extern "C" void kernel_launch(void* const* d_in, const int* in_sizes, int n_in,
                              void* d_out, int out_size) {
    const float* x    = (const float*)d_in[0];
    const float* mask = (const float*)d_in[1];
    const float* Pq   = (const float*)d_in[2];
    const float* Vq   = (const float*)d_in[3];
    const float* Pk   = (const float*)d_in[4];
    const float* Vk   = (const float*)d_in[5];
    const float* Pv   = (const float*)d_in[6];
    const float* Vv   = (const float*)d_in[7];
    const float* bq   = (const float*)d_in[8];
    const float* bk   = (const float*)d_in[9];
    const float* bv   = (const float*)d_in[10];
    const float* Uo   = (const float*)d_in[11];
    const float* Vo   = (const float*)d_in[12];
    const float* bo   = (const float*)d_in[13];
    const float* U1   = (const float*)d_in[14];
    const float* V1   = (const float*)d_in[15];
    const float* b1   = (const float*)d_in[16];
    const float* U2   = (const float*)d_in[17];
    const float* V2   = (const float*)d_in[18];
    const float* b2   = (const float*)d_in[19];
    const float* ln1g = (const float*)d_in[20];
    const float* ln1b = (const float*)d_in[21];
    const float* ln2g = (const float*)d_in[22];
    const float* ln2b = (const float*)d_in[23];
    float* out = (float*)d_out;

#define SYM(p, s) cudaGetSymbolAddress((void**)&p, s)
    uint32_t *xh, *xl, *wch, *wcl, *Uoh, *Uol, *Voh, *Vol, *U1h, *U1l, *V1h, *V1l;
    uint32_t *U2h, *U2l, *V2h, *V2l, *ath, *atl, *t1h, *t1l, *x1h, *x1l;
    uint32_t *mdh, *mdl, *hdh, *hdl, *t2h, *t2l;
    float *T, *y1, *x1, *y2;
    SYM(xh, g_xh); SYM(xl, g_xl); SYM(wch, g_wch); SYM(wcl, g_wcl);
    SYM(Uoh, g_Uoh); SYM(Uol, g_Uol); SYM(Voh, g_Voh); SYM(Vol, g_Vol);
    SYM(U1h, g_U1h); SYM(U1l, g_U1l); SYM(V1h, g_V1h); SYM(V1l, g_V1l);
    SYM(U2h, g_U2h); SYM(U2l, g_U2l); SYM(V2h, g_V2h); SYM(V2l, g_V2l);
    SYM(ath, g_ath); SYM(atl, g_atl); SYM(t1h, g_t1h); SYM(t1l, g_t1l);
    SYM(x1h, g_x1h); SYM(x1l, g_x1l); SYM(mdh, g_mdh); SYM(mdl, g_mdl);
    SYM(hdh, g_hdh); SYM(hdl, g_hdl); SYM(t2h, g_t2h); SYM(t2l, g_t2l);
    SYM(T, g_T); SYM(y1, g_y1); SYM(x1, g_x1); SYM(y2, g_y2);
#undef SYM

    // operand conversion
    conv_x<<<BMr * 512 / 256, 256>>>(x);
    pack_w_split<<<512 * C3 / 256, 256>>>(Pq, Pk, Pv);
    convB<<<(512 * ROz + 255) / 256, 256>>>(Uo, Uoh, Uol, 512, ROz);
    convB<<<(192 * DMz + 255) / 256, 256>>>(Vo, Voh, Vol, 192, DMz);
    convB<<<(512 * RFz + 255) / 256, 256>>>(U1, U1h, U1l, 512, RFz);
    convB<<<(192 * DFFz + 255) / 256, 256>>>(V1, V1h, V1l, 192, DFFz);
    convB<<<(2048 * RFz + 255) / 256, 256>>>(U2, U2h, U2l, 2048, RFz);
    convB<<<(192 * DMz + 255) / 256, 256>>>(V2, V2h, V2l, 192, DMz);

    // qkv low-rank
    hgemm<128, true, false, 0><<<dim3(C3 / 128, BMr / 128), 256>>>(
        xh, xl, wch, wcl, T, nullptr, nullptr, C3, DMz, nullptr);
    qkv2_k<<<dim3(Mz / 8, ZT, 3), 256>>>(Vq, Vk, Vv, bq, bk, bv);

    // attention
    hscores<<<dim3(Mz / 128, Mz / 128, ZT), 256>>>();
    softmax_k<<<ZT * Mz, 128>>>(mask);
    hattnv<<<dim3(Mz / 128, ZT), 256>>>();

    // output projection + LN1
    hgemm<64, false, true, 0><<<dim3(ROz / 128, BMr / 64), 256>>>(
        ath, atl, Uoh, Uol, nullptr, t1h, t1l, ROz, DMz, nullptr);
    hgemm<128, true, false, 1><<<dim3(DMz / 128, BMr / 128), 256>>>(
        t1h, t1l, Voh, Vol, y1, nullptr, nullptr, DMz, ROz, bo);
    ln_k<true><<<BMr, 256>>>(x, y1, ln1g, ln1b, x1);

    // FFN
    hgemm<64, false, true, 0><<<dim3(RFz / 128, BMr / 64), 256>>>(
        x1h, x1l, U1h, U1l, nullptr, mdh, mdl, RFz, DMz, nullptr);
    hgemm<128, false, true, 2><<<dim3(DFFz / 128, BMr / 128), 256>>>(
        mdh, mdl, V1h, V1l, nullptr, hdh, hdl, DFFz, RFz, b1);
    hgemm<64, false, true, 0><<<dim3(RFz / 128, BMr / 64), 256>>>(
        hdh, hdl, U2h, U2l, nullptr, t2h, t2l, RFz, DFFz, nullptr);
    hgemm<128, true, false, 1><<<dim3(DMz / 128, BMr / 128), 256>>>(
        t2h, t2l, V2h, V2l, y2, nullptr, nullptr, DMz, RFz, b2);

    // LN2 -> out
    ln_k<false><<<BMr, 256>>>(x1, y2, ln2g, ln2b, out);
}

// round 9
// speedup vs baseline: 2.9555x; 1.6304x over previous
#include <cuda_runtime.h>
#include <cuda_fp16.h>
#include <math.h>
#include <stdint.h>

#define Bz 8
#define Mz 512
#define DMz 1024
#define Hz 16
#define DHz 64
#define DFFz 4096
#define RAz 32
#define RFz 384
#define ROz 384
#define BMr (Bz*Mz)          // 4096
#define C3 (3*Hz*RAz)        // 1536
#define ZT (Bz*Hz)           // 128
#define LN_EPS 1e-12f

// ---------------- scratch (device globals) ----------------
__device__ uint32_t g_xh[BMr*512],  g_xl[BMr*512];
__device__ uint32_t g_wch[512*C3],  g_wcl[512*C3];
__device__ float    g_T[BMr*C3];
__device__ uint32_t g_Qh[ZT*Mz*32], g_Ql[ZT*Mz*32];         // [z][512][32]
__device__ uint32_t g_Kh[ZT*Mz*32], g_Kl[ZT*Mz*32];
__device__ uint32_t g_Vh[ZT*256*64], g_Vl[ZT*256*64];       // B-fmt [z][256][64]
__device__ uint32_t g_ath[BMr*512], g_atl[BMr*512];         // attn A-fmt [4096][512]
__device__ uint32_t g_Uoh[512*ROz],  g_Uol[512*ROz];
__device__ uint32_t g_Voh[192*DMz],  g_Vol[192*DMz];
__device__ uint32_t g_U1h[512*RFz],  g_U1l[512*RFz];
__device__ uint32_t g_V1h[192*DFFz], g_V1l[192*DFFz];
__device__ uint32_t g_U2h[2048*RFz], g_U2l[2048*RFz];
__device__ uint32_t g_V2h[192*DMz],  g_V2l[192*DMz];
__device__ uint32_t g_t1h[BMr*192],  g_t1l[BMr*192];
__device__ float    g_y1[BMr*DMz];
__device__ float    g_x1[BMr*DMz];
__device__ uint32_t g_x1h[BMr*512],  g_x1l[BMr*512];
__device__ uint32_t g_mdh[BMr*192],  g_mdl[BMr*192];
__device__ uint32_t g_hdh[(size_t)BMr*2048], g_hdl[(size_t)BMr*2048];
__device__ uint32_t g_t2h[BMr*192],  g_t2l[BMr*192];
__device__ float    g_y2[BMr*DMz];

// ---------------- helpers ----------------
__device__ __forceinline__ float gelu_f(float x) {
    return 0.5f * x * (1.0f + erff(x * 0.70710678118654752440f));
}
__device__ __forceinline__ void split_pair(float x0, float x1, uint32_t& uh, uint32_t& ul) {
    __half h0 = __float2half_rn(x0);
    __half h1 = __float2half_rn(x1);
    __half l0 = __float2half_rn(x0 - __half2float(h0));
    __half l1 = __float2half_rn(x1 - __half2float(h1));
    __half2 hh = __halves2half2(h0, h1);
    __half2 ll = __halves2half2(l0, l1);
    uh = *(uint32_t*)&hh;
    ul = *(uint32_t*)&ll;
}
__device__ __forceinline__ void mma16(float* c, const uint32_t* a, const uint32_t* b) {
    asm volatile(
        "mma.sync.aligned.m16n8k16.row.col.f32.f16.f16.f32 "
        "{%0,%1,%2,%3}, {%4,%5,%6,%7}, {%8,%9}, {%0,%1,%2,%3};"
        : "+f"(c[0]), "+f"(c[1]), "+f"(c[2]), "+f"(c[3])
        : "r"(a[0]), "r"(a[1]), "r"(a[2]), "r"(a[3]), "r"(b[0]), "r"(b[1]));
}
__device__ __forceinline__ uint32_t smem_u32(const void* p) {
    return (uint32_t)__cvta_generic_to_shared(p);
}
__device__ __forceinline__ void cp16(uint32_t dst, const void* src) {
    asm volatile("cp.async.cg.shared.global [%0], [%1], 16;" :: "r"(dst), "l"(src));
}
#define CP_COMMIT() asm volatile("cp.async.commit_group;")
#define CP_WAIT1()  asm volatile("cp.async.wait_group 1;")

// ---------------- conversion kernels ----------------
__global__ void conv_x(const float* __restrict__ x) {
    int idx = blockIdx.x * blockDim.x + threadIdx.x;
    int row = idx >> 9, p = idx & 511;
    float2 v = *(const float2*)(x + (size_t)row * DMz + 2 * p);
    split_pair(v.x, v.y, g_xh[idx], g_xl[idx]);
}
__global__ void pack_w_split(const float* __restrict__ Pq, const float* __restrict__ Pk,
                             const float* __restrict__ Pv) {
    int idx = blockIdx.x * blockDim.x + threadIdx.x;
    int kp = idx / C3, c = idx % C3;
    int j = c / 512, hr = c % 512, h = hr >> 5, r = hr & 31;
    const float* P = (j == 0) ? Pq : ((j == 1) ? Pk : Pv);
    float v0 = P[((size_t)h * DMz + 2 * kp) * RAz + r];
    float v1 = P[((size_t)h * DMz + 2 * kp + 1) * RAz + r];
    split_pair(v0, v1, g_wch[idx], g_wcl[idx]);
}
__global__ void convB(const float* __restrict__ W, uint32_t* __restrict__ oh,
                      uint32_t* __restrict__ ol, int K2, int N) {
    int idx = blockIdx.x * blockDim.x + threadIdx.x;
    if (idx >= K2 * N) return;
    int kp = idx / N, n = idx % N;
    float v0 = W[(size_t)(2 * kp) * N + n];
    float v1 = W[(size_t)(2 * kp + 1) * N + n];
    split_pair(v0, v1, oh[idx], ol[idx]);
}

// =====================================================================
// Generic fp16x3 GEMM. CTAM in {128, 64}. A: [M][K/2] pairs. B: [K/2][N] pairs.
// =====================================================================
template <int CTAM, bool OF32, bool OSPL, int EPI>
__launch_bounds__(256, 2)
__global__ void hgemm(const uint32_t* __restrict__ Ah, const uint32_t* __restrict__ Al,
                      const uint32_t* __restrict__ Bh, const uint32_t* __restrict__ Bl,
                      float* __restrict__ Cf, uint32_t* __restrict__ Ch,
                      uint32_t* __restrict__ Cl, int N, int K,
                      const float* __restrict__ bias) {
    constexpr int MT = CTAM / 32;
    __shared__ uint32_t Ash[3][CTAM][8], Asl[3][CTAM][8];
    __shared__ uint32_t Bsh[3][8][128], Bsl[3][8][128];

    int tid = threadIdx.x, lane = tid & 31, wid = tid >> 5;
    int warp_m = (wid >> 2) * (CTAM / 2);
    int warp_n = (wid & 3) * 32;
    int by = blockIdx.y, bx = blockIdx.x;
    int kp2 = K >> 1;
    int mq = lane >> 2, kq = lane & 3, sw = mq & 4;
    int nk = K >> 4;

    auto load_stage = [&](int kt, int s) {
        if (tid < CTAM * 2) {
            int row = tid >> 1, hf = (tid & 1) * 4;
            int cc = hf ^ (row & 4);
            size_t so = (size_t)(by * CTAM + row) * kp2 + kt * 8 + hf;
            cp16(smem_u32(&Ash[s][row][cc]), Ah + so);
            cp16(smem_u32(&Asl[s][row][cc]), Al + so);
        }
        {
            int kp = tid >> 5, c0 = (tid & 31) * 4;
            int cc = c0 ^ (kp * 8);
            size_t so = (size_t)(kt * 8 + kp) * N + bx * 128 + c0;
            cp16(smem_u32(&Bsh[s][kp][cc]), Bh + so);
            cp16(smem_u32(&Bsl[s][kp][cc]), Bl + so);
        }
    };

    float acc[MT][4][4];
#pragma unroll
    for (int i = 0; i < MT; i++)
#pragma unroll
        for (int j = 0; j < 4; j++)
#pragma unroll
            for (int t = 0; t < 4; t++) acc[i][j][t] = 0.f;

    load_stage(0, 0); CP_COMMIT();
    load_stage(1, 1); CP_COMMIT();

    for (int kt = 0; kt < nk; kt++) {
        CP_WAIT1();
        __syncthreads();
        int s = kt % 3;
        uint32_t fbh[4][2], fbl[4][2];
#pragma unroll
        for (int nt = 0; nt < 4; nt++) {
            int n = warp_n + nt * 8 + mq;
            int c1 = n ^ (kq * 8);
            fbh[nt][0] = Bsh[s][kq][c1];
            fbh[nt][1] = Bsh[s][kq + 4][c1 ^ 32];
            fbl[nt][0] = Bsl[s][kq][c1];
            fbl[nt][1] = Bsl[s][kq + 4][c1 ^ 32];
        }
#pragma unroll
        for (int mt = 0; mt < MT; mt++) {
            int r0 = warp_m + mt * 16 + mq;
            uint32_t fah[4], fal[4];
            fah[0] = Ash[s][r0][kq ^ sw];
            fah[1] = Ash[s][r0 + 8][kq ^ sw];
            fah[2] = Ash[s][r0][(kq + 4) ^ sw];
            fah[3] = Ash[s][r0 + 8][(kq + 4) ^ sw];
            fal[0] = Asl[s][r0][kq ^ sw];
            fal[1] = Asl[s][r0 + 8][kq ^ sw];
            fal[2] = Asl[s][r0][(kq + 4) ^ sw];
            fal[3] = Asl[s][r0 + 8][(kq + 4) ^ sw];
#pragma unroll
            for (int nt = 0; nt < 4; nt++) {
                mma16(acc[mt][nt], fah, fbh[nt]);
                mma16(acc[mt][nt], fah, fbl[nt]);
                mma16(acc[mt][nt], fal, fbh[nt]);
            }
        }
        if (kt + 2 < nk) load_stage(kt + 2, (kt + 2) % 3);
        CP_COMMIT();
    }

#pragma unroll
    for (int mt = 0; mt < MT; mt++)
#pragma unroll
        for (int nt = 0; nt < 4; nt++) {
            int row = by * CTAM + warp_m + mt * 16 + mq;
            int col = bx * 128 + warp_n + nt * 8 + kq * 2;
            float v0 = acc[mt][nt][0], v1 = acc[mt][nt][1];
            float v2 = acc[mt][nt][2], v3 = acc[mt][nt][3];
            if (EPI >= 1) {
                float b0 = bias[col], b1 = bias[col + 1];
                v0 += b0; v1 += b1; v2 += b0; v3 += b1;
            }
            if (EPI == 2) {
                v0 = gelu_f(v0); v1 = gelu_f(v1); v2 = gelu_f(v2); v3 = gelu_f(v3);
            }
            if (OF32) {
                *(float2*)(Cf + (size_t)row * N + col) = make_float2(v0, v1);
                *(float2*)(Cf + (size_t)(row + 8) * N + col) = make_float2(v2, v3);
            }
            if (OSPL) {
                uint32_t uh, ul;
                size_t o = (size_t)row * (N >> 1) + (col >> 1);
                split_pair(v0, v1, uh, ul);
                Ch[o] = uh; Cl[o] = ul;
                o = (size_t)(row + 8) * (N >> 1) + (col >> 1);
                split_pair(v2, v3, uh, ul);
                Ch[o] = uh; Cl[o] = ul;
            }
        }
}

// =====================================================================
// Fused flash attention: per (m-tile 128, z): softmax(QK^T/8 + mask) @ V.
// Q pinned in smem; 4 KV tiles of 128 keys, 2-stage cp.async double buffer.
// Each warp owns 16 full rows. P stays in registers (C-frag -> A-frag).
// Writes split attn pairs to g_ath/g_atl.
// =====================================================================
#define FLASH_SMEM_BYTES 165888
__launch_bounds__(256, 1)
__global__ void hflash(const float* __restrict__ mask) {
    extern __shared__ uint32_t dsm[];
    uint32_t* Qh = dsm;                    // [128][32]
    uint32_t* Ql = dsm + 4096;
    uint32_t* Khs[2] = {dsm + 8192,  dsm + 12288};   // [128][32] each
    uint32_t* Kls[2] = {dsm + 16384, dsm + 20480};
    uint32_t* Vhs[2] = {dsm + 24576, dsm + 28672};   // [64][64] each
    uint32_t* Vls[2] = {dsm + 32768, dsm + 36864};
    float* mk = (float*)(dsm + 40960);     // [512]

    int tid = threadIdx.x, lane = tid & 31, w = tid >> 5;
    int mq = lane >> 2, kq = lane & 3;
    int by = blockIdx.x, z = blockIdx.y;
    int b = z >> 4, h = z & 15;

    const uint32_t* Qhb = g_Qh + (size_t)z * Mz * 32;
    const uint32_t* Qlb = g_Ql + (size_t)z * Mz * 32;
    const uint32_t* Khb = g_Kh + (size_t)z * Mz * 32;
    const uint32_t* Klb = g_Kl + (size_t)z * Mz * 32;
    const uint32_t* Vhb = g_Vh + (size_t)z * 256 * 64;
    const uint32_t* Vlb = g_Vl + (size_t)z * 256 * 64;

    // mask tile (plain stores; visible after first __syncthreads)
    {
        float2 mv = *(const float2*)(mask + (size_t)b * Mz + tid * 2);
        *(float2*)(mk + tid * 2) = mv;
    }

    auto load_kv = [&](int j, int s) {
#pragma unroll
        for (int i = 0; i < 4; i++) {
            int g = tid + i * 256;           // 1024 groups
            int row = g >> 3, q0 = (g & 7) * 4;
            int cc = q0 ^ ((row & 7) * 4);
            size_t so = (size_t)(j * 128 + row) * 32 + q0;
            cp16(smem_u32(&Khs[s][row * 32 + cc]), Khb + so);
            cp16(smem_u32(&Kls[s][row * 32 + cc]), Klb + so);
        }
#pragma unroll
        for (int i = 0; i < 4; i++) {
            int g = tid + i * 256;           // 1024 groups
            int pr = g >> 4, c0 = (g & 15) * 4;
            int cc = c0 ^ ((pr & 7) * 8);
            size_t so = (size_t)(j * 64 + pr) * 64 + c0;
            cp16(smem_u32(&Vhs[s][pr * 64 + cc]), Vhb + so);
            cp16(smem_u32(&Vls[s][pr * 64 + cc]), Vlb + so);
        }
    };

    // prologue: Q + stage0 + stage1
#pragma unroll
    for (int i = 0; i < 4; i++) {
        int g = tid + i * 256;
        int row = g >> 3, q0 = (g & 7) * 4;
        int cc = q0 ^ ((row & 7) * 4);
        size_t so = (size_t)(by * 128 + row) * 32 + q0;
        cp16(smem_u32(&Qh[row * 32 + cc]), Qhb + so);
        cp16(smem_u32(&Ql[row * 32 + cc]), Qlb + so);
    }
    load_kv(0, 0); CP_COMMIT();   // group: Q + KV0
    load_kv(1, 1); CP_COMMIT();

    float sacc[16][4];
    float oacc[8][4];
#pragma unroll
    for (int i = 0; i < 8; i++)
#pragma unroll
        for (int t = 0; t < 4; t++) oacc[i][t] = 0.f;
    float rmax0 = -1e30f, rmax1 = -1e30f;
    float rsum0 = 0.f, rsum1 = 0.f;
    uint32_t qh[4][4], ql[4][4];

    for (int j = 0; j < 4; j++) {
        CP_WAIT1();
        __syncthreads();
        int s = j & 1;
        if (j == 0) {
            int r0 = w * 16 + mq, r1 = r0 + 8;
#pragma unroll
            for (int c = 0; c < 4; c++) {
                int p0 = (c * 8 + kq) ^ (mq * 4);
                int p1 = (c * 8 + 4 + kq) ^ (mq * 4);
                qh[c][0] = Qh[r0 * 32 + p0];
                qh[c][1] = Qh[r1 * 32 + p0];
                qh[c][2] = Qh[r0 * 32 + p1];
                qh[c][3] = Qh[r1 * 32 + p1];
                ql[c][0] = Ql[r0 * 32 + p0];
                ql[c][1] = Ql[r1 * 32 + p0];
                ql[c][2] = Ql[r0 * 32 + p1];
                ql[c][3] = Ql[r1 * 32 + p1];
            }
        }
        // ---- S = Q K^T ----
#pragma unroll
        for (int nt = 0; nt < 16; nt++)
#pragma unroll
            for (int t = 0; t < 4; t++) sacc[nt][t] = 0.f;
#pragma unroll
        for (int c = 0; c < 4; c++) {
#pragma unroll
            for (int nt = 0; nt < 16; nt++) {
                int n = nt * 8 + mq;
                int p0 = (c * 8 + kq) ^ (mq * 4);
                int p1 = (c * 8 + 4 + kq) ^ (mq * 4);
                uint32_t bh[2], bl[2];
                bh[0] = Khs[s][n * 32 + p0];
                bh[1] = Khs[s][n * 32 + p1];
                bl[0] = Kls[s][n * 32 + p0];
                bl[1] = Kls[s][n * 32 + p1];
                mma16(sacc[nt], qh[c], bh);
                mma16(sacc[nt], qh[c], bl);
                mma16(sacc[nt], ql[c], bh);
            }
        }
        // ---- scale + mask + online softmax ----
        float tm0 = -1e30f, tm1 = -1e30f;
#pragma unroll
        for (int nt = 0; nt < 16; nt++) {
            int n0 = j * 128 + nt * 8 + kq * 2;
            float m0 = mk[n0], m1 = mk[n0 + 1];
            sacc[nt][0] = sacc[nt][0] * 0.125f + m0;
            sacc[nt][1] = sacc[nt][1] * 0.125f + m1;
            sacc[nt][2] = sacc[nt][2] * 0.125f + m0;
            sacc[nt][3] = sacc[nt][3] * 0.125f + m1;
            tm0 = fmaxf(tm0, fmaxf(sacc[nt][0], sacc[nt][1]));
            tm1 = fmaxf(tm1, fmaxf(sacc[nt][2], sacc[nt][3]));
        }
        tm0 = fmaxf(tm0, __shfl_xor_sync(0xffffffffu, tm0, 1));
        tm0 = fmaxf(tm0, __shfl_xor_sync(0xffffffffu, tm0, 2));
        tm1 = fmaxf(tm1, __shfl_xor_sync(0xffffffffu, tm1, 1));
        tm1 = fmaxf(tm1, __shfl_xor_sync(0xffffffffu, tm1, 2));
        float nm0 = fmaxf(rmax0, tm0), nm1 = fmaxf(rmax1, tm1);
        float f0 = __expf(rmax0 - nm0), f1 = __expf(rmax1 - nm1);
        rmax0 = nm0; rmax1 = nm1;
        rsum0 *= f0; rsum1 *= f1;
#pragma unroll
        for (int nt = 0; nt < 8; nt++) {
            oacc[nt][0] *= f0; oacc[nt][1] *= f0;
            oacc[nt][2] *= f1; oacc[nt][3] *= f1;
        }
        float ps0 = 0.f, ps1 = 0.f;
#pragma unroll
        for (int nt = 0; nt < 16; nt++) {
            sacc[nt][0] = __expf(sacc[nt][0] - nm0);
            sacc[nt][1] = __expf(sacc[nt][1] - nm0);
            sacc[nt][2] = __expf(sacc[nt][2] - nm1);
            sacc[nt][3] = __expf(sacc[nt][3] - nm1);
            ps0 += sacc[nt][0] + sacc[nt][1];
            ps1 += sacc[nt][2] + sacc[nt][3];
        }
        rsum0 += ps0; rsum1 += ps1;
        // ---- O += P V  (P from registers: C-frag -> A-frag) ----
#pragma unroll
        for (int cc = 0; cc < 8; cc++) {
            uint32_t pah[4], pal[4];
            split_pair(sacc[2 * cc][0],     sacc[2 * cc][1],     pah[0], pal[0]);
            split_pair(sacc[2 * cc][2],     sacc[2 * cc][3],     pah[1], pal[1]);
            split_pair(sacc[2 * cc + 1][0], sacc[2 * cc + 1][1], pah[2], pal[2]);
            split_pair(sacc[2 * cc + 1][2], sacc[2 * cc + 1][3], pah[3], pal[3]);
#pragma unroll
            for (int nt = 0; nt < 8; nt++) {
                int n = nt * 8 + mq;
                int pr0 = cc * 8 + kq, pr1 = pr0 + 4;
                uint32_t vh2[2], vl2[2];
                vh2[0] = Vhs[s][pr0 * 64 + (n ^ (kq * 8))];
                vh2[1] = Vhs[s][pr1 * 64 + (n ^ ((kq + 4) * 8))];
                vl2[0] = Vls[s][pr0 * 64 + (n ^ (kq * 8))];
                vl2[1] = Vls[s][pr1 * 64 + (n ^ ((kq + 4) * 8))];
                mma16(oacc[nt], pah, vh2);
                mma16(oacc[nt], pah, vl2);
                mma16(oacc[nt], pal, vh2);
            }
        }
        __syncthreads();
        if (j + 2 < 4) load_kv(j + 2, s);
        CP_COMMIT();
    }

    // ---- epilogue ----
    rsum0 += __shfl_xor_sync(0xffffffffu, rsum0, 1);
    rsum0 += __shfl_xor_sync(0xffffffffu, rsum0, 2);
    rsum1 += __shfl_xor_sync(0xffffffffu, rsum1, 1);
    rsum1 += __shfl_xor_sync(0xffffffffu, rsum1, 2);
    float inv0 = 1.0f / rsum0, inv1 = 1.0f / rsum1;
    int m0 = by * 128 + w * 16 + mq;
#pragma unroll
    for (int nt = 0; nt < 8; nt++) {
        int d = nt * 8 + kq * 2;
        int colp = (h * DHz + d) >> 1;
        uint32_t uh, ul;
        split_pair(oacc[nt][0] * inv0, oacc[nt][1] * inv0, uh, ul);
        size_t o = (size_t)(b * Mz + m0) * 512 + colp;
        g_ath[o] = uh; g_atl[o] = ul;
        split_pair(oacc[nt][2] * inv1, oacc[nt][3] * inv1, uh, ul);
        o = (size_t)(b * Mz + m0 + 8) * 512 + colp;
        g_ath[o] = uh; g_atl[o] = ul;
    }
}

// ---------------- rank-32 expansion + split-pack ----------------
__launch_bounds__(256)
__global__ void qkv2_k(const float* __restrict__ Vq, const float* __restrict__ Vk,
                       const float* __restrict__ Vv, const float* __restrict__ bq,
                       const float* __restrict__ bk, const float* __restrict__ bv) {
    __shared__ float Vs[RAz][DHz];
    __shared__ float tile[8][65];
    int z = blockIdx.y, j = blockIdx.z;
    int b = z / Hz, h = z % Hz;
    const float* Vm = (j == 0) ? Vq : ((j == 1) ? Vk : Vv);
    const float* bm = (j == 0) ? bq : ((j == 1) ? bk : bv);
    int tid = threadIdx.x;
#pragma unroll
    for (int i = 0; i < 8; i++) {
        int idx = tid + i * 256;
        Vs[idx >> 6][idx & 63] = Vm[(size_t)h * RAz * DHz + idx];
    }
    __syncthreads();

    int m0 = blockIdx.x * 8;
    int d = tid & 63, ml = tid >> 6;
#pragma unroll
    for (int rr = 0; rr < 2; rr++) {
        int r = ml + rr * 4;
        int m = m0 + r;
        const float* trow = g_T + ((size_t)(b * Mz + m)) * C3 + j * 512 + h * RAz;
        float acc = bm[h * DHz + d];
#pragma unroll
        for (int k = 0; k < RAz; k++) acc += trow[k] * Vs[k][d];
        tile[r][d] = acc;
    }
    __syncthreads();

    if (j < 2) {
        int m = tid >> 5, dp = tid & 31;
        uint32_t uh, ul;
        split_pair(tile[m][2 * dp], tile[m][2 * dp + 1], uh, ul);
        size_t o = ((size_t)z * Mz + m0 + m) * 32 + dp;
        if (j == 0) { g_Qh[o] = uh; g_Ql[o] = ul; }
        else        { g_Kh[o] = uh; g_Kl[o] = ul; }
    } else {
        int mp = tid >> 6, dd = tid & 63;
        uint32_t uh, ul;
        split_pair(tile[2 * mp][dd], tile[2 * mp + 1][dd], uh, ul);
        size_t o = ((size_t)z * 256 + (m0 >> 1) + mp) * 64 + dd;
        g_Vh[o] = uh; g_Vl[o] = ul;
    }
}

// ---------------- residual + LayerNorm ----------------
template <bool SPLIT>
__launch_bounds__(256)
__global__ void ln_k(const float* __restrict__ a, const float* __restrict__ r,
                     const float* __restrict__ g, const float* __restrict__ bb,
                     float* __restrict__ out) {
    __shared__ float sh[8];
    int row = blockIdx.x;
    int tid = threadIdx.x;
    int lane = tid & 31, warp = tid >> 5;
    int c = tid * 4;
    float4 xa = *(const float4*)(a + (size_t)row * DMz + c);
    float4 ya = *(const float4*)(r + (size_t)row * DMz + c);
    float v[4] = {xa.x + ya.x, xa.y + ya.y, xa.z + ya.z, xa.w + ya.w};
    float s = v[0] + v[1] + v[2] + v[3];
#pragma unroll
    for (int o = 16; o > 0; o >>= 1) s += __shfl_xor_sync(0xffffffffu, s, o);
    if (lane == 0) sh[warp] = s;
    __syncthreads();
    if (warp == 0) {
        float t = (lane < 8) ? sh[lane] : 0.f;
#pragma unroll
        for (int o = 4; o > 0; o >>= 1) t += __shfl_xor_sync(0xffffffffu, t, o);
        if (lane == 0) sh[0] = t;
    }
    __syncthreads();
    float mu = sh[0] * (1.0f / DMz);
    __syncthreads();

    float q = 0.f;
#pragma unroll
    for (int i = 0; i < 4; i++) {
        float d = v[i] - mu;
        q += d * d;
    }
#pragma unroll
    for (int o = 16; o > 0; o >>= 1) q += __shfl_xor_sync(0xffffffffu, q, o);
    if (lane == 0) sh[warp] = q;
    __syncthreads();
    if (warp == 0) {
        float t = (lane < 8) ? sh[lane] : 0.f;
#pragma unroll
        for (int o = 4; o > 0; o >>= 1) t += __shfl_xor_sync(0xffffffffu, t, o);
        if (lane == 0) sh[0] = t;
    }
    __syncthreads();
    float var = sh[0] * (1.0f / DMz);
    float rs = rsqrtf(var + LN_EPS);
    float4 gg = *(const float4*)(g + c);
    float4 bbv = *(const float4*)(bb + c);
    float o0 = (v[0] - mu) * rs * gg.x + bbv.x;
    float o1 = (v[1] - mu) * rs * gg.y + bbv.y;
    float o2 = (v[2] - mu) * rs * gg.z + bbv.z;
    float o3 = (v[3] - mu) * rs * gg.w + bbv.w;
    *(float4*)(out + (size_t)row * DMz + c) = make_float4(o0, o1, o2, o3);
    if (SPLIT) {
        uint32_t uh, ul;
        size_t o = (size_t)row * 512 + (c >> 1);
        split_pair(o0, o1, uh, ul);
        g_x1h[o] = uh; g_x1l[o] = ul;
        split_pair(o2, o3, uh, ul);
        g_x1h[o + 1] = uh; g_x1l[o + 1] = ul;
    }
}

// ---------------- launch ----------------
extern "C" void kernel_launch(void* const* d_in, const int* in_sizes, int n_in,
                              void* d_out, int out_size) {
    const float* x    = (const float*)d_in[0];
    const float* mask = (const float*)d_in[1];
    const float* Pq   = (const float*)d_in[2];
    const float* Vq   = (const float*)d_in[3];
    const float* Pk   = (const float*)d_in[4];
    const float* Vk   = (const float*)d_in[5];
    const float* Pv   = (const float*)d_in[6];
    const float* Vv   = (const float*)d_in[7];
    const float* bq   = (const float*)d_in[8];
    const float* bk   = (const float*)d_in[9];
    const float* bv   = (const float*)d_in[10];
    const float* Uo   = (const float*)d_in[11];
    const float* Vo   = (const float*)d_in[12];
    const float* bo   = (const float*)d_in[13];
    const float* U1   = (const float*)d_in[14];
    const float* V1   = (const float*)d_in[15];
    const float* b1   = (const float*)d_in[16];
    const float* U2   = (const float*)d_in[17];
    const float* V2   = (const float*)d_in[18];
    const float* b2   = (const float*)d_in[19];
    const float* ln1g = (const float*)d_in[20];
    const float* ln1b = (const float*)d_in[21];
    const float* ln2g = (const float*)d_in[22];
    const float* ln2b = (const float*)d_in[23];
    float* out = (float*)d_out;

#define SYM(p, s) cudaGetSymbolAddress((void**)&p, s)
    uint32_t *xh, *xl, *wch, *wcl, *Uoh, *Uol, *Voh, *Vol, *U1h, *U1l, *V1h, *V1l;
    uint32_t *U2h, *U2l, *V2h, *V2l, *ath, *atl, *t1h, *t1l, *x1h, *x1l;
    uint32_t *mdh, *mdl, *hdh, *hdl, *t2h, *t2l;
    float *T, *y1, *x1, *y2;
    SYM(xh, g_xh); SYM(xl, g_xl); SYM(wch, g_wch); SYM(wcl, g_wcl);
    SYM(Uoh, g_Uoh); SYM(Uol, g_Uol); SYM(Voh, g_Voh); SYM(Vol, g_Vol);
    SYM(U1h, g_U1h); SYM(U1l, g_U1l); SYM(V1h, g_V1h); SYM(V1l, g_V1l);
    SYM(U2h, g_U2h); SYM(U2l, g_U2l); SYM(V2h, g_V2h); SYM(V2l, g_V2l);
    SYM(ath, g_ath); SYM(atl, g_atl); SYM(t1h, g_t1h); SYM(t1l, g_t1l);
    SYM(x1h, g_x1h); SYM(x1l, g_x1l); SYM(mdh, g_mdh); SYM(mdl, g_mdl);
    SYM(hdh, g_hdh); SYM(hdl, g_hdl); SYM(t2h, g_t2h); SYM(t2l, g_t2l);
    SYM(T, g_T); SYM(y1, g_y1); SYM(x1, g_x1); SYM(y2, g_y2);
#undef SYM

    cudaFuncSetAttribute(hflash, cudaFuncAttributeMaxDynamicSharedMemorySize,
                         FLASH_SMEM_BYTES);

    // operand conversion
    conv_x<<<BMr * 512 / 256, 256>>>(x);
    pack_w_split<<<512 * C3 / 256, 256>>>(Pq, Pk, Pv);
    convB<<<(512 * ROz + 255) / 256, 256>>>(Uo, Uoh, Uol, 512, ROz);
    convB<<<(192 * DMz + 255) / 256, 256>>>(Vo, Voh, Vol, 192, DMz);
    convB<<<(512 * RFz + 255) / 256, 256>>>(U1, U1h, U1l, 512, RFz);
    convB<<<(192 * DFFz + 255) / 256, 256>>>(V1, V1h, V1l, 192, DFFz);
    convB<<<(2048 * RFz + 255) / 256, 256>>>(U2, U2h, U2l, 2048, RFz);
    convB<<<(192 * DMz + 255) / 256, 256>>>(V2, V2h, V2l, 192, DMz);

    // qkv low-rank
    hgemm<128, true, false, 0><<<dim3(C3 / 128, BMr / 128), 256>>>(
        xh, xl, wch, wcl, T, nullptr, nullptr, C3, DMz, nullptr);
    qkv2_k<<<dim3(Mz / 8, ZT, 3), 256>>>(Vq, Vk, Vv, bq, bk, bv);

    // fused attention
    hflash<<<dim3(Mz / 128, ZT), 256, FLASH_SMEM_BYTES>>>(mask);

    // output projection + LN1
    hgemm<64, false, true, 0><<<dim3(ROz / 128, BMr / 64), 256>>>(
        ath, atl, Uoh, Uol, nullptr, t1h, t1l, ROz, DMz, nullptr);
    hgemm<128, true, false, 1><<<dim3(DMz / 128, BMr / 128), 256>>>(
        t1h, t1l, Voh, Vol, y1, nullptr, nullptr, DMz, ROz, bo);
    ln_k<true><<<BMr, 256>>>(x, y1, ln1g, ln1b, x1);

    // FFN
    hgemm<64, false, true, 0><<<dim3(RFz / 128, BMr / 64), 256>>>(
        x1h, x1l, U1h, U1l, nullptr, mdh, mdl, RFz, DMz, nullptr);
    hgemm<128, false, true, 2><<<dim3(DFFz / 128, BMr / 128), 256>>>(
        mdh, mdl, V1h, V1l, nullptr, hdh, hdl, DFFz, RFz, b1);
    hgemm<64, false, true, 0><<<dim3(RFz / 128, BMr / 64), 256>>>(
        hdh, hdl, U2h, U2l, nullptr, t2h, t2l, RFz, DFFz, nullptr);
    hgemm<128, true, false, 1><<<dim3(DMz / 128, BMr / 128), 256>>>(
        t2h, t2l, V2h, V2l, y2, nullptr, nullptr, DMz, RFz, b2);

    // LN2 -> out
    ln_k<false><<<BMr, 256>>>(x1, y2, ln2g, ln2b, out);
}

// round 13
// speedup vs baseline: 3.7277x; 1.2613x over previous
#include <cuda_runtime.h>
#include <cuda_fp16.h>
#include <math.h>
#include <stdint.h>

#define Bz 8
#define Mz 512
#define DMz 1024
#define Hz 16
#define DHz 64
#define DFFz 4096
#define RAz 32
#define RFz 384
#define ROz 384
#define BMr (Bz*Mz)          // 4096
#define C3 (3*Hz*RAz)        // 1536
#define ZT (Bz*Hz)           // 128
#define LN_EPS 1e-12f

// ---------------- scratch (device globals) ----------------
// A-side operands: split pairs (hi, lo). B-side operands: fp16 hi only.
__device__ uint32_t g_xh[BMr*512],  g_xl[BMr*512];
__device__ uint32_t g_wch[512*C3];
__device__ float    g_T[BMr*C3];
__device__ uint32_t g_Qh[ZT*Mz*32], g_Ql[ZT*Mz*32];         // [z][512][32] (A-side)
__device__ uint32_t g_Kh[ZT*Mz*32];                          // B-side
__device__ uint32_t g_Vh[ZT*256*64];                         // B-fmt [z][256][64]
__device__ uint32_t g_ath[BMr*512], g_atl[BMr*512];         // attn A-fmt
__device__ uint32_t g_Uoh[512*ROz];
__device__ uint32_t g_Voh[192*DMz];
__device__ uint32_t g_U1h[512*RFz];
__device__ uint32_t g_V1h[192*DFFz];
__device__ uint32_t g_U2h[2048*RFz];
__device__ uint32_t g_V2h[192*DMz];
__device__ uint32_t g_t1h[BMr*192],  g_t1l[BMr*192];
__device__ float    g_y1[BMr*DMz];
__device__ float    g_x1[BMr*DMz];
__device__ uint32_t g_x1h[BMr*512],  g_x1l[BMr*512];
__device__ uint32_t g_mdh[BMr*192],  g_mdl[BMr*192];
__device__ uint32_t g_hdh[(size_t)BMr*2048], g_hdl[(size_t)BMr*2048];
__device__ uint32_t g_t2h[BMr*192],  g_t2l[BMr*192];
__device__ float    g_y2[BMr*DMz];

// ---------------- helpers ----------------
__device__ __forceinline__ float gelu_f(float x) {
    return 0.5f * x * (1.0f + erff(x * 0.70710678118654752440f));
}
__device__ __forceinline__ void split_pair(float x0, float x1, uint32_t& uh, uint32_t& ul) {
    __half h0 = __float2half_rn(x0);
    __half h1 = __float2half_rn(x1);
    __half l0 = __float2half_rn(x0 - __half2float(h0));
    __half l1 = __float2half_rn(x1 - __half2float(h1));
    __half2 hh = __halves2half2(h0, h1);
    __half2 ll = __halves2half2(l0, l1);
    uh = *(uint32_t*)&hh;
    ul = *(uint32_t*)&ll;
}
__device__ __forceinline__ uint32_t cvt_pair(float x0, float x1) {
    __half2 hh = __halves2half2(__float2half_rn(x0), __float2half_rn(x1));
    return *(uint32_t*)&hh;
}
__device__ __forceinline__ void mma16(float* c, const uint32_t* a, const uint32_t* b) {
    asm volatile(
        "mma.sync.aligned.m16n8k16.row.col.f32.f16.f16.f32 "
        "{%0,%1,%2,%3}, {%4,%5,%6,%7}, {%8,%9}, {%0,%1,%2,%3};"
        : "+f"(c[0]), "+f"(c[1]), "+f"(c[2]), "+f"(c[3])
        : "r"(a[0]), "r"(a[1]), "r"(a[2]), "r"(a[3]), "r"(b[0]), "r"(b[1]));
}
__device__ __forceinline__ uint32_t smem_u32(const void* p) {
    return (uint32_t)__cvta_generic_to_shared(p);
}
__device__ __forceinline__ void cp16(uint32_t dst, const void* src) {
    asm volatile("cp.async.cg.shared.global [%0], [%1], 16;" :: "r"(dst), "l"(src));
}
#define CP_COMMIT() asm volatile("cp.async.commit_group;")
#define CP_WAIT1()  asm volatile("cp.async.wait_group 1;")

// ---------------- conversion kernels ----------------
__global__ void conv_x(const float* __restrict__ x) {
    int idx = blockIdx.x * blockDim.x + threadIdx.x;
    int row = idx >> 9, p = idx & 511;
    float2 v = *(const float2*)(x + (size_t)row * DMz + 2 * p);
    split_pair(v.x, v.y, g_xh[idx], g_xl[idx]);
}
__global__ void pack_w_split(const float* __restrict__ Pq, const float* __restrict__ Pk,
                             const float* __restrict__ Pv) {
    int idx = blockIdx.x * blockDim.x + threadIdx.x;
    int kp = idx / C3, c = idx % C3;
    int j = c / 512, hr = c % 512, h = hr >> 5, r = hr & 31;
    const float* P = (j == 0) ? Pq : ((j == 1) ? Pk : Pv);
    float v0 = P[((size_t)h * DMz + 2 * kp) * RAz + r];
    float v1 = P[((size_t)h * DMz + 2 * kp + 1) * RAz + r];
    g_wch[idx] = cvt_pair(v0, v1);
}
__global__ void convB(const float* __restrict__ W, uint32_t* __restrict__ oh,
                      int K2, int N) {
    int idx = blockIdx.x * blockDim.x + threadIdx.x;
    if (idx >= K2 * N) return;
    int kp = idx / N, n = idx % N;
    float v0 = W[(size_t)(2 * kp) * N + n];
    float v1 = W[(size_t)(2 * kp + 1) * N + n];
    oh[idx] = cvt_pair(v0, v1);
}

// =====================================================================
// fp16x2 GEMM: A split (hi+lo), B fp16. CTAM in {128, 64}.
// A: [M][K/2] pairs. B: [K/2][N] pairs. 2 mma per fragment pair.
// =====================================================================
template <int CTAM, bool OF32, bool OSPL, int EPI>
__launch_bounds__(256, 2)
__global__ void hgemm(const uint32_t* __restrict__ Ah, const uint32_t* __restrict__ Al,
                      const uint32_t* __restrict__ Bh,
                      float* __restrict__ Cf, uint32_t* __restrict__ Ch,
                      uint32_t* __restrict__ Cl, int N, int K,
                      const float* __restrict__ bias) {
    constexpr int MT = CTAM / 32;
    __shared__ uint32_t Ash[3][CTAM][8], Asl[3][CTAM][8];
    __shared__ uint32_t Bsh[3][8][128];

    int tid = threadIdx.x, lane = tid & 31, wid = tid >> 5;
    int warp_m = (wid >> 2) * (CTAM / 2);
    int warp_n = (wid & 3) * 32;
    int by = blockIdx.y, bx = blockIdx.x;
    int kp2 = K >> 1;
    int mq = lane >> 2, kq = lane & 3, sw = mq & 4;
    int nk = K >> 4;

    auto load_stage = [&](int kt, int s) {
        if (tid < CTAM * 2) {
            int row = tid >> 1, hf = (tid & 1) * 4;
            int cc = hf ^ (row & 4);
            size_t so = (size_t)(by * CTAM + row) * kp2 + kt * 8 + hf;
            cp16(smem_u32(&Ash[s][row][cc]), Ah + so);
            cp16(smem_u32(&Asl[s][row][cc]), Al + so);
        }
        {
            int kp = tid >> 5, c0 = (tid & 31) * 4;
            int cc = c0 ^ (kp * 8);
            size_t so = (size_t)(kt * 8 + kp) * N + bx * 128 + c0;
            cp16(smem_u32(&Bsh[s][kp][cc]), Bh + so);
        }
    };

    float acc[MT][4][4];
#pragma unroll
    for (int i = 0; i < MT; i++)
#pragma unroll
        for (int j = 0; j < 4; j++)
#pragma unroll
            for (int t = 0; t < 4; t++) acc[i][j][t] = 0.f;

    load_stage(0, 0); CP_COMMIT();
    load_stage(1, 1); CP_COMMIT();

    for (int kt = 0; kt < nk; kt++) {
        CP_WAIT1();
        __syncthreads();
        int s = kt % 3;
        uint32_t fbh[4][2];
#pragma unroll
        for (int nt = 0; nt < 4; nt++) {
            int n = warp_n + nt * 8 + mq;
            int c1 = n ^ (kq * 8);
            fbh[nt][0] = Bsh[s][kq][c1];
            fbh[nt][1] = Bsh[s][kq + 4][c1 ^ 32];
        }
#pragma unroll
        for (int mt = 0; mt < MT; mt++) {
            int r0 = warp_m + mt * 16 + mq;
            uint32_t fah[4], fal[4];
            fah[0] = Ash[s][r0][kq ^ sw];
            fah[1] = Ash[s][r0 + 8][kq ^ sw];
            fah[2] = Ash[s][r0][(kq + 4) ^ sw];
            fah[3] = Ash[s][r0 + 8][(kq + 4) ^ sw];
            fal[0] = Asl[s][r0][kq ^ sw];
            fal[1] = Asl[s][r0 + 8][kq ^ sw];
            fal[2] = Asl[s][r0][(kq + 4) ^ sw];
            fal[3] = Asl[s][r0 + 8][(kq + 4) ^ sw];
#pragma unroll
            for (int nt = 0; nt < 4; nt++) {
                mma16(acc[mt][nt], fah, fbh[nt]);
                mma16(acc[mt][nt], fal, fbh[nt]);
            }
        }
        if (kt + 2 < nk) load_stage(kt + 2, (kt + 2) % 3);
        CP_COMMIT();
    }

#pragma unroll
    for (int mt = 0; mt < MT; mt++)
#pragma unroll
        for (int nt = 0; nt < 4; nt++) {
            int row = by * CTAM + warp_m + mt * 16 + mq;
            int col = bx * 128 + warp_n + nt * 8 + kq * 2;
            float v0 = acc[mt][nt][0], v1 = acc[mt][nt][1];
            float v2 = acc[mt][nt][2], v3 = acc[mt][nt][3];
            if (EPI >= 1) {
                float b0 = bias[col], b1 = bias[col + 1];
                v0 += b0; v1 += b1; v2 += b0; v3 += b1;
            }
            if (EPI == 2) {
                v0 = gelu_f(v0); v1 = gelu_f(v1); v2 = gelu_f(v2); v3 = gelu_f(v3);
            }
            if (OF32) {
                *(float2*)(Cf + (size_t)row * N + col) = make_float2(v0, v1);
                *(float2*)(Cf + (size_t)(row + 8) * N + col) = make_float2(v2, v3);
            }
            if (OSPL) {
                uint32_t uh, ul;
                size_t o = (size_t)row * (N >> 1) + (col >> 1);
                split_pair(v0, v1, uh, ul);
                Ch[o] = uh; Cl[o] = ul;
                o = (size_t)(row + 8) * (N >> 1) + (col >> 1);
                split_pair(v2, v3, uh, ul);
                Ch[o] = uh; Cl[o] = ul;
            }
        }
}

// =====================================================================
// Fused flash attention. Q split (A-side); K, V fp16 (B-side).
// =====================================================================
#define FLASH_SMEM_BYTES 100352
__launch_bounds__(256, 1)
__global__ void hflash(const float* __restrict__ mask) {
    extern __shared__ uint32_t dsm[];
    uint32_t* Qh = dsm;                              // [128][32]
    uint32_t* Ql = dsm + 4096;
    uint32_t* Khs[2] = {dsm + 8192,  dsm + 12288};   // [128][32] each
    uint32_t* Vhs[2] = {dsm + 16384, dsm + 20480};   // [64][64] each
    float* mk = (float*)(dsm + 24576);               // [512]

    int tid = threadIdx.x, lane = tid & 31, w = tid >> 5;
    int mq = lane >> 2, kq = lane & 3;
    int by = blockIdx.x, z = blockIdx.y;
    int b = z >> 4, h = z & 15;

    const uint32_t* Qhb = g_Qh + (size_t)z * Mz * 32;
    const uint32_t* Qlb = g_Ql + (size_t)z * Mz * 32;
    const uint32_t* Khb = g_Kh + (size_t)z * Mz * 32;
    const uint32_t* Vhb = g_Vh + (size_t)z * 256 * 64;

    {
        float2 mv = *(const float2*)(mask + (size_t)b * Mz + tid * 2);
        *(float2*)(mk + tid * 2) = mv;
    }

    auto load_kv = [&](int j, int s) {
#pragma unroll
        for (int i = 0; i < 4; i++) {
            int g = tid + i * 256;
            int row = g >> 3, q0 = (g & 7) * 4;
            int cc = q0 ^ ((row & 7) * 4);
            size_t so = (size_t)(j * 128 + row) * 32 + q0;
            cp16(smem_u32(&Khs[s][row * 32 + cc]), Khb + so);
        }
#pragma unroll
        for (int i = 0; i < 4; i++) {
            int g = tid + i * 256;
            int pr = g >> 4, c0 = (g & 15) * 4;
            int cc = c0 ^ ((pr & 7) * 8);
            size_t so = (size_t)(j * 64 + pr) * 64 + c0;
            cp16(smem_u32(&Vhs[s][pr * 64 + cc]), Vhb + so);
        }
    };

#pragma unroll
    for (int i = 0; i < 4; i++) {
        int g = tid + i * 256;
        int row = g >> 3, q0 = (g & 7) * 4;
        int cc = q0 ^ ((row & 7) * 4);
        size_t so = (size_t)(by * 128 + row) * 32 + q0;
        cp16(smem_u32(&Qh[row * 32 + cc]), Qhb + so);
        cp16(smem_u32(&Ql[row * 32 + cc]), Qlb + so);
    }
    load_kv(0, 0); CP_COMMIT();
    load_kv(1, 1); CP_COMMIT();

    float sacc[16][4];
    float oacc[8][4];
#pragma unroll
    for (int i = 0; i < 8; i++)
#pragma unroll
        for (int t = 0; t < 4; t++) oacc[i][t] = 0.f;
    float rmax0 = -1e30f, rmax1 = -1e30f;
    float rsum0 = 0.f, rsum1 = 0.f;
    uint32_t qh[4][4], ql[4][4];

    for (int j = 0; j < 4; j++) {
        CP_WAIT1();
        __syncthreads();
        int s = j & 1;
        if (j == 0) {
            int r0 = w * 16 + mq, r1 = r0 + 8;
#pragma unroll
            for (int c = 0; c < 4; c++) {
                int p0 = (c * 8 + kq) ^ (mq * 4);
                int p1 = (c * 8 + 4 + kq) ^ (mq * 4);
                qh[c][0] = Qh[r0 * 32 + p0];
                qh[c][1] = Qh[r1 * 32 + p0];
                qh[c][2] = Qh[r0 * 32 + p1];
                qh[c][3] = Qh[r1 * 32 + p1];
                ql[c][0] = Ql[r0 * 32 + p0];
                ql[c][1] = Ql[r1 * 32 + p0];
                ql[c][2] = Ql[r0 * 32 + p1];
                ql[c][3] = Ql[r1 * 32 + p1];
            }
        }
        // ---- S = Q K^T ----
#pragma unroll
        for (int nt = 0; nt < 16; nt++)
#pragma unroll
            for (int t = 0; t < 4; t++) sacc[nt][t] = 0.f;
#pragma unroll
        for (int c = 0; c < 4; c++) {
#pragma unroll
            for (int nt = 0; nt < 16; nt++) {
                int n = nt * 8 + mq;
                int p0 = (c * 8 + kq) ^ (mq * 4);
                int p1 = (c * 8 + 4 + kq) ^ (mq * 4);
                uint32_t bh[2];
                bh[0] = Khs[s][n * 32 + p0];
                bh[1] = Khs[s][n * 32 + p1];
                mma16(sacc[nt], qh[c], bh);
                mma16(sacc[nt], ql[c], bh);
            }
        }
        // ---- scale + mask + online softmax ----
        float tm0 = -1e30f, tm1 = -1e30f;
#pragma unroll
        for (int nt = 0; nt < 16; nt++) {
            int n0 = j * 128 + nt * 8 + kq * 2;
            float m0 = mk[n0], m1 = mk[n0 + 1];
            sacc[nt][0] = sacc[nt][0] * 0.125f + m0;
            sacc[nt][1] = sacc[nt][1] * 0.125f + m1;
            sacc[nt][2] = sacc[nt][2] * 0.125f + m0;
            sacc[nt][3] = sacc[nt][3] * 0.125f + m1;
            tm0 = fmaxf(tm0, fmaxf(sacc[nt][0], sacc[nt][1]));
            tm1 = fmaxf(tm1, fmaxf(sacc[nt][2], sacc[nt][3]));
        }
        tm0 = fmaxf(tm0, __shfl_xor_sync(0xffffffffu, tm0, 1));
        tm0 = fmaxf(tm0, __shfl_xor_sync(0xffffffffu, tm0, 2));
        tm1 = fmaxf(tm1, __shfl_xor_sync(0xffffffffu, tm1, 1));
        tm1 = fmaxf(tm1, __shfl_xor_sync(0xffffffffu, tm1, 2));
        float nm0 = fmaxf(rmax0, tm0), nm1 = fmaxf(rmax1, tm1);
        float f0 = __expf(rmax0 - nm0), f1 = __expf(rmax1 - nm1);
        rmax0 = nm0; rmax1 = nm1;
        rsum0 *= f0; rsum1 *= f1;
#pragma unroll
        for (int nt = 0; nt < 8; nt++) {
            oacc[nt][0] *= f0; oacc[nt][1] *= f0;
            oacc[nt][2] *= f1; oacc[nt][3] *= f1;
        }
        float ps0 = 0.f, ps1 = 0.f;
#pragma unroll
        for (int nt = 0; nt < 16; nt++) {
            sacc[nt][0] = __expf(sacc[nt][0] - nm0);
            sacc[nt][1] = __expf(sacc[nt][1] - nm0);
            sacc[nt][2] = __expf(sacc[nt][2] - nm1);
            sacc[nt][3] = __expf(sacc[nt][3] - nm1);
            ps0 += sacc[nt][0] + sacc[nt][1];
            ps1 += sacc[nt][2] + sacc[nt][3];
        }
        rsum0 += ps0; rsum1 += ps1;
        // ---- O += P V ----
#pragma unroll
        for (int cc = 0; cc < 8; cc++) {
            uint32_t pah[4], pal[4];
            split_pair(sacc[2 * cc][0],     sacc[2 * cc][1],     pah[0], pal[0]);
            split_pair(sacc[2 * cc][2],     sacc[2 * cc][3],     pah[1], pal[1]);
            split_pair(sacc[2 * cc + 1][0], sacc[2 * cc + 1][1], pah[2], pal[2]);
            split_pair(sacc[2 * cc + 1][2], sacc[2 * cc + 1][3], pah[3], pal[3]);
#pragma unroll
            for (int nt = 0; nt < 8; nt++) {
                int n = nt * 8 + mq;
                int pr0 = cc * 8 + kq, pr1 = pr0 + 4;
                uint32_t vh2[2];
                vh2[0] = Vhs[s][pr0 * 64 + (n ^ (kq * 8))];
                vh2[1] = Vhs[s][pr1 * 64 + (n ^ ((kq + 4) * 8))];
                mma16(oacc[nt], pah, vh2);
                mma16(oacc[nt], pal, vh2);
            }
        }
        __syncthreads();
        if (j + 2 < 4) load_kv(j + 2, s);
        CP_COMMIT();
    }

    // ---- epilogue ----
    rsum0 += __shfl_xor_sync(0xffffffffu, rsum0, 1);
    rsum0 += __shfl_xor_sync(0xffffffffu, rsum0, 2);
    rsum1 += __shfl_xor_sync(0xffffffffu, rsum1, 1);
    rsum1 += __shfl_xor_sync(0xffffffffu, rsum1, 2);
    float inv0 = 1.0f / rsum0, inv1 = 1.0f / rsum1;
    int m0 = by * 128 + w * 16 + mq;
#pragma unroll
    for (int nt = 0; nt < 8; nt++) {
        int d = nt * 8 + kq * 2;
        int colp = (h * DHz + d) >> 1;
        uint32_t uh, ul;
        split_pair(oacc[nt][0] * inv0, oacc[nt][1] * inv0, uh, ul);
        size_t o = (size_t)(b * Mz + m0) * 512 + colp;
        g_ath[o] = uh; g_atl[o] = ul;
        split_pair(oacc[nt][2] * inv1, oacc[nt][3] * inv1, uh, ul);
        o = (size_t)(b * Mz + m0 + 8) * 512 + colp;
        g_ath[o] = uh; g_atl[o] = ul;
    }
}

// ---------------- rank-32 expansion + pack ----------------
__launch_bounds__(256)
__global__ void qkv2_k(const float* __restrict__ Vq, const float* __restrict__ Vk,
                       const float* __restrict__ Vv, const float* __restrict__ bq,
                       const float* __restrict__ bk, const float* __restrict__ bv) {
    __shared__ float Vs[RAz][DHz];
    __shared__ float tile[8][65];
    int z = blockIdx.y, j = blockIdx.z;
    int b = z / Hz, h = z % Hz;
    const float* Vm = (j == 0) ? Vq : ((j == 1) ? Vk : Vv);
    const float* bm = (j == 0) ? bq : ((j == 1) ? bk : bv);
    int tid = threadIdx.x;
#pragma unroll
    for (int i = 0; i < 8; i++) {
        int idx = tid + i * 256;
        Vs[idx >> 6][idx & 63] = Vm[(size_t)h * RAz * DHz + idx];
    }
    __syncthreads();

    int m0 = blockIdx.x * 8;
    int d = tid & 63, ml = tid >> 6;
#pragma unroll
    for (int rr = 0; rr < 2; rr++) {
        int r = ml + rr * 4;
        int m = m0 + r;
        const float* trow = g_T + ((size_t)(b * Mz + m)) * C3 + j * 512 + h * RAz;
        float acc = bm[h * DHz + d];
#pragma unroll
        for (int k = 0; k < RAz; k++) acc += trow[k] * Vs[k][d];
        tile[r][d] = acc;
    }
    __syncthreads();

    if (j == 0) {
        int m = tid >> 5, dp = tid & 31;
        uint32_t uh, ul;
        split_pair(tile[m][2 * dp], tile[m][2 * dp + 1], uh, ul);
        size_t o = ((size_t)z * Mz + m0 + m) * 32 + dp;
        g_Qh[o] = uh; g_Ql[o] = ul;
    } else if (j == 1) {
        int m = tid >> 5, dp = tid & 31;
        size_t o = ((size_t)z * Mz + m0 + m) * 32 + dp;
        g_Kh[o] = cvt_pair(tile[m][2 * dp], tile[m][2 * dp + 1]);
    } else {
        int mp = tid >> 6, dd = tid & 63;
        size_t o = ((size_t)z * 256 + (m0 >> 1) + mp) * 64 + dd;
        g_Vh[o] = cvt_pair(tile[2 * mp][dd], tile[2 * mp + 1][dd]);
    }
}

// ---------------- residual + LayerNorm ----------------
template <bool SPLIT>
__launch_bounds__(256)
__global__ void ln_k(const float* __restrict__ a, const float* __restrict__ r,
                     const float* __restrict__ g, const float* __restrict__ bb,
                     float* __restrict__ out) {
    __shared__ float sh[8];
    int row = blockIdx.x;
    int tid = threadIdx.x;
    int lane = tid & 31, warp = tid >> 5;
    int c = tid * 4;
    float4 xa = *(const float4*)(a + (size_t)row * DMz + c);
    float4 ya = *(const float4*)(r + (size_t)row * DMz + c);
    float v[4] = {xa.x + ya.x, xa.y + ya.y, xa.z + ya.z, xa.w + ya.w};
    float s = v[0] + v[1] + v[2] + v[3];
#pragma unroll
    for (int o = 16; o > 0; o >>= 1) s += __shfl_xor_sync(0xffffffffu, s, o);
    if (lane == 0) sh[warp] = s;
    __syncthreads();
    if (warp == 0) {
        float t = (lane < 8) ? sh[lane] : 0.f;
#pragma unroll
        for (int o = 4; o > 0; o >>= 1) t += __shfl_xor_sync(0xffffffffu, t, o);
        if (lane == 0) sh[0] = t;
    }
    __syncthreads();
    float mu = sh[0] * (1.0f / DMz);
    __syncthreads();

    float q = 0.f;
#pragma unroll
    for (int i = 0; i < 4; i++) {
        float d = v[i] - mu;
        q += d * d;
    }
#pragma unroll
    for (int o = 16; o > 0; o >>= 1) q += __shfl_xor_sync(0xffffffffu, q, o);
    if (lane == 0) sh[warp] = q;
    __syncthreads();
    if (warp == 0) {
        float t = (lane < 8) ? sh[lane] : 0.f;
#pragma unroll
        for (int o = 4; o > 0; o >>= 1) t += __shfl_xor_sync(0xffffffffu, t, o);
        if (lane == 0) sh[0] = t;
    }
    __syncthreads();
    float var = sh[0] * (1.0f / DMz);
    float rs = rsqrtf(var + LN_EPS);
    float4 gg = *(const float4*)(g + c);
    float4 bbv = *(const float4*)(bb + c);
    float o0 = (v[0] - mu) * rs * gg.x + bbv.x;
    float o1 = (v[1] - mu) * rs * gg.y + bbv.y;
    float o2 = (v[2] - mu) * rs * gg.z + bbv.z;
    float o3 = (v[3] - mu) * rs * gg.w + bbv.w;
    *(float4*)(out + (size_t)row * DMz + c) = make_float4(o0, o1, o2, o3);
    if (SPLIT) {
        uint32_t uh, ul;
        size_t o = (size_t)row * 512 + (c >> 1);
        split_pair(o0, o1, uh, ul);
        g_x1h[o] = uh; g_x1l[o] = ul;
        split_pair(o2, o3, uh, ul);
        g_x1h[o + 1] = uh; g_x1l[o + 1] = ul;
    }
}

// ---------------- launch ----------------
extern "C" void kernel_launch(void* const* d_in, const int* in_sizes, int n_in,
                              void* d_out, int out_size) {
    const float* x    = (const float*)d_in[0];
    const float* mask = (const float*)d_in[1];
    const float* Pq   = (const float*)d_in[2];
    const float* Vq   = (const float*)d_in[3];
    const float* Pk   = (const float*)d_in[4];
    const float* Vk   = (const float*)d_in[5];
    const float* Pv   = (const float*)d_in[6];
    const float* Vv   = (const float*)d_in[7];
    const float* bq   = (const float*)d_in[8];
    const float* bk   = (const float*)d_in[9];
    const float* bv   = (const float*)d_in[10];
    const float* Uo   = (const float*)d_in[11];
    const float* Vo   = (const float*)d_in[12];
    const float* bo   = (const float*)d_in[13];
    const float* U1   = (const float*)d_in[14];
    const float* V1   = (const float*)d_in[15];
    const float* b1   = (const float*)d_in[16];
    const float* U2   = (const float*)d_in[17];
    const float* V2   = (const float*)d_in[18];
    const float* b2   = (const float*)d_in[19];
    const float* ln1g = (const float*)d_in[20];
    const float* ln1b = (const float*)d_in[21];
    const float* ln2g = (const float*)d_in[22];
    const float* ln2b = (const float*)d_in[23];
    float* out = (float*)d_out;

#define SYM(p, s) cudaGetSymbolAddress((void**)&p, s)
    uint32_t *xh, *xl, *wch, *Uoh, *Voh, *U1h, *V1h, *U2h, *V2h;
    uint32_t *ath, *atl, *t1h, *t1l, *x1h, *x1l;
    uint32_t *mdh, *mdl, *hdh, *hdl, *t2h, *t2l;
    float *T, *y1, *x1, *y2;
    SYM(xh, g_xh); SYM(xl, g_xl); SYM(wch, g_wch);
    SYM(Uoh, g_Uoh); SYM(Voh, g_Voh);
    SYM(U1h, g_U1h); SYM(V1h, g_V1h);
    SYM(U2h, g_U2h); SYM(V2h, g_V2h);
    SYM(ath, g_ath); SYM(atl, g_atl); SYM(t1h, g_t1h); SYM(t1l, g_t1l);
    SYM(x1h, g_x1h); SYM(x1l, g_x1l); SYM(mdh, g_mdh); SYM(mdl, g_mdl);
    SYM(hdh, g_hdh); SYM(hdl, g_hdl); SYM(t2h, g_t2h); SYM(t2l, g_t2l);
    SYM(T, g_T); SYM(y1, g_y1); SYM(x1, g_x1); SYM(y2, g_y2);
#undef SYM

    cudaFuncSetAttribute(hflash, cudaFuncAttributeMaxDynamicSharedMemorySize,
                         FLASH_SMEM_BYTES);

    // operand conversion
    conv_x<<<BMr * 512 / 256, 256>>>(x);
    pack_w_split<<<512 * C3 / 256, 256>>>(Pq, Pk, Pv);
    convB<<<(512 * ROz + 255) / 256, 256>>>(Uo, Uoh, 512, ROz);
    convB<<<(192 * DMz + 255) / 256, 256>>>(Vo, Voh, 192, DMz);
    convB<<<(512 * RFz + 255) / 256, 256>>>(U1, U1h, 512, RFz);
    convB<<<(192 * DFFz + 255) / 256, 256>>>(V1, V1h, 192, DFFz);
    convB<<<(2048 * RFz + 255) / 256, 256>>>(U2, U2h, 2048, RFz);
    convB<<<(192 * DMz + 255) / 256, 256>>>(V2, V2h, 192, DMz);

    // qkv low-rank
    hgemm<128, true, false, 0><<<dim3(C3 / 128, BMr / 128), 256>>>(
        xh, xl, wch, T, nullptr, nullptr, C3, DMz, nullptr);
    qkv2_k<<<dim3(Mz / 8, ZT, 3), 256>>>(Vq, Vk, Vv, bq, bk, bv);

    // fused attention
    hflash<<<dim3(Mz / 128, ZT), 256, FLASH_SMEM_BYTES>>>(mask);

    // output projection + LN1
    hgemm<64, false, true, 0><<<dim3(ROz / 128, BMr / 64), 256>>>(
        ath, atl, Uoh, nullptr, t1h, t1l, ROz, DMz, nullptr);
    hgemm<128, true, false, 1><<<dim3(DMz / 128, BMr / 128), 256>>>(
        t1h, t1l, Voh, y1, nullptr, nullptr, DMz, ROz, bo);
    ln_k<true><<<BMr, 256>>>(x, y1, ln1g, ln1b, x1);

    // FFN
    hgemm<64, false, true, 0><<<dim3(RFz / 128, BMr / 64), 256>>>(
        x1h, x1l, U1h, nullptr, mdh, mdl, RFz, DMz, nullptr);
    hgemm<128, false, true, 2><<<dim3(DFFz / 128, BMr / 128), 256>>>(
        mdh, mdl, V1h, nullptr, hdh, hdl, DFFz, RFz, b1);
    hgemm<64, false, true, 0><<<dim3(RFz / 128, BMr / 64), 256>>>(
        hdh, hdl, U2h, nullptr, t2h, t2l, RFz, DFFz, nullptr);
    hgemm<128, true, false, 1><<<dim3(DMz / 128, BMr / 128), 256>>>(
        t2h, t2l, V2h, y2, nullptr, nullptr, DMz, RFz, b2);

    // LN2 -> out
    ln_k<false><<<BMr, 256>>>(x1, y2, ln2g, ln2b, out);
}

// round 14
// speedup vs baseline: 4.8885x; 1.3114x over previous
#include <cuda_runtime.h>
#include <cuda_fp16.h>
#include <math.h>
#include <stdint.h>

#define Bz 8
#define Mz 512
#define DMz 1024
#define Hz 16
#define DHz 64
#define DFFz 4096
#define RAz 32
#define RFz 384
#define ROz 384
#define BMr (Bz*Mz)          // 4096
#define C3 (3*Hz*RAz)        // 1536
#define ZT (Bz*Hz)           // 128
#define LN_EPS 1e-12f

// ---------------- scratch (device globals) ----------------
// all mma operands plain fp16 pairs (half2 along K)
__device__ uint32_t g_xh[BMr*512];
__device__ uint32_t g_wch[512*C3];
__device__ float    g_T[BMr*C3];
__device__ uint32_t g_Qh[ZT*Mz*32];
__device__ uint32_t g_Kh[ZT*Mz*32];
__device__ uint32_t g_Vh[ZT*256*64];
__device__ uint32_t g_ath[BMr*512];
__device__ uint32_t g_Uoh[512*ROz];
__device__ uint32_t g_Voh[192*DMz];
__device__ uint32_t g_U1h[512*RFz];
__device__ uint32_t g_V1h[192*DFFz];
__device__ uint32_t g_U2h[2048*RFz];
__device__ uint32_t g_V2h[192*DMz];
__device__ uint32_t g_t1h[BMr*192];
__device__ float    g_y1[BMr*DMz];
__device__ float    g_x1[BMr*DMz];
__device__ uint32_t g_x1h[BMr*512];
__device__ uint32_t g_mdh[BMr*192];
__device__ uint32_t g_hdh[(size_t)BMr*2048];
__device__ uint32_t g_t2h[BMr*192];
__device__ float    g_y2[BMr*DMz];

// ---------------- helpers ----------------
__device__ __forceinline__ float gelu_f(float x) {
    return 0.5f * x * (1.0f + erff(x * 0.70710678118654752440f));
}
__device__ __forceinline__ uint32_t cvt_pair(float x0, float x1) {
    __half2 hh = __halves2half2(__float2half_rn(x0), __float2half_rn(x1));
    return *(uint32_t*)&hh;
}
__device__ __forceinline__ void mma16(float* c, const uint32_t* a, const uint32_t* b) {
    asm volatile(
        "mma.sync.aligned.m16n8k16.row.col.f32.f16.f16.f32 "
        "{%0,%1,%2,%3}, {%4,%5,%6,%7}, {%8,%9}, {%0,%1,%2,%3};"
        : "+f"(c[0]), "+f"(c[1]), "+f"(c[2]), "+f"(c[3])
        : "r"(a[0]), "r"(a[1]), "r"(a[2]), "r"(a[3]), "r"(b[0]), "r"(b[1]));
}
__device__ __forceinline__ uint32_t smem_u32(const void* p) {
    return (uint32_t)__cvta_generic_to_shared(p);
}
__device__ __forceinline__ void cp16(uint32_t dst, const void* src) {
    asm volatile("cp.async.cg.shared.global [%0], [%1], 16;" :: "r"(dst), "l"(src));
}
#define CP_COMMIT() asm volatile("cp.async.commit_group;")
#define CP_WAIT1()  asm volatile("cp.async.wait_group 1;")

// ---------------- conversion kernels ----------------
__global__ void conv_x(const float* __restrict__ x) {
    int idx = blockIdx.x * blockDim.x + threadIdx.x;
    int row = idx >> 9, p = idx & 511;
    float2 v = *(const float2*)(x + (size_t)row * DMz + 2 * p);
    g_xh[idx] = cvt_pair(v.x, v.y);
}
__global__ void pack_w_split(const float* __restrict__ Pq, const float* __restrict__ Pk,
                             const float* __restrict__ Pv) {
    int idx = blockIdx.x * blockDim.x + threadIdx.x;
    int kp = idx / C3, c = idx % C3;
    int j = c / 512, hr = c % 512, h = hr >> 5, r = hr & 31;
    const float* P = (j == 0) ? Pq : ((j == 1) ? Pk : Pv);
    float v0 = P[((size_t)h * DMz + 2 * kp) * RAz + r];
    float v1 = P[((size_t)h * DMz + 2 * kp + 1) * RAz + r];
    g_wch[idx] = cvt_pair(v0, v1);
}
__global__ void convB(const float* __restrict__ W, uint32_t* __restrict__ oh,
                      int K2, int N) {
    int idx = blockIdx.x * blockDim.x + threadIdx.x;
    if (idx >= K2 * N) return;
    int kp = idx / N, n = idx % N;
    float v0 = W[(size_t)(2 * kp) * N + n];
    float v1 = W[(size_t)(2 * kp + 1) * N + n];
    oh[idx] = cvt_pair(v0, v1);
}

// =====================================================================
// fp16 GEMM. CTAM in {128, 64}. A: [M][K/2] pairs. B: [K/2][N] pairs.
// 1 mma per fragment pair.
// =====================================================================
template <int CTAM, bool OF32, bool OSPL, int EPI>
__launch_bounds__(256, 2)
__global__ void hgemm(const uint32_t* __restrict__ Ah, const uint32_t* __restrict__ Bh,
                      float* __restrict__ Cf, uint32_t* __restrict__ Ch,
                      int N, int K, const float* __restrict__ bias) {
    constexpr int MT = CTAM / 32;
    __shared__ uint32_t Ash[3][CTAM][8];
    __shared__ uint32_t Bsh[3][8][128];

    int tid = threadIdx.x, lane = tid & 31, wid = tid >> 5;
    int warp_m = (wid >> 2) * (CTAM / 2);
    int warp_n = (wid & 3) * 32;
    int by = blockIdx.y, bx = blockIdx.x;
    int kp2 = K >> 1;
    int mq = lane >> 2, kq = lane & 3, sw = mq & 4;
    int nk = K >> 4;

    auto load_stage = [&](int kt, int s) {
        if (tid < CTAM * 2) {
            int row = tid >> 1, hf = (tid & 1) * 4;
            int cc = hf ^ (row & 4);
            size_t so = (size_t)(by * CTAM + row) * kp2 + kt * 8 + hf;
            cp16(smem_u32(&Ash[s][row][cc]), Ah + so);
        }
        {
            int kp = tid >> 5, c0 = (tid & 31) * 4;
            int cc = c0 ^ (kp * 8);
            size_t so = (size_t)(kt * 8 + kp) * N + bx * 128 + c0;
            cp16(smem_u32(&Bsh[s][kp][cc]), Bh + so);
        }
    };

    float acc[MT][4][4];
#pragma unroll
    for (int i = 0; i < MT; i++)
#pragma unroll
        for (int j = 0; j < 4; j++)
#pragma unroll
            for (int t = 0; t < 4; t++) acc[i][j][t] = 0.f;

    load_stage(0, 0); CP_COMMIT();
    load_stage(1, 1); CP_COMMIT();

    for (int kt = 0; kt < nk; kt++) {
        CP_WAIT1();
        __syncthreads();
        int s = kt % 3;
        uint32_t fbh[4][2];
#pragma unroll
        for (int nt = 0; nt < 4; nt++) {
            int n = warp_n + nt * 8 + mq;
            int c1 = n ^ (kq * 8);
            fbh[nt][0] = Bsh[s][kq][c1];
            fbh[nt][1] = Bsh[s][kq + 4][c1 ^ 32];
        }
#pragma unroll
        for (int mt = 0; mt < MT; mt++) {
            int r0 = warp_m + mt * 16 + mq;
            uint32_t fah[4];
            fah[0] = Ash[s][r0][kq ^ sw];
            fah[1] = Ash[s][r0 + 8][kq ^ sw];
            fah[2] = Ash[s][r0][(kq + 4) ^ sw];
            fah[3] = Ash[s][r0 + 8][(kq + 4) ^ sw];
#pragma unroll
            for (int nt = 0; nt < 4; nt++) {
                mma16(acc[mt][nt], fah, fbh[nt]);
            }
        }
        if (kt + 2 < nk) load_stage(kt + 2, (kt + 2) % 3);
        CP_COMMIT();
    }

#pragma unroll
    for (int mt = 0; mt < MT; mt++)
#pragma unroll
        for (int nt = 0; nt < 4; nt++) {
            int row = by * CTAM + warp_m + mt * 16 + mq;
            int col = bx * 128 + warp_n + nt * 8 + kq * 2;
            float v0 = acc[mt][nt][0], v1 = acc[mt][nt][1];
            float v2 = acc[mt][nt][2], v3 = acc[mt][nt][3];
            if (EPI >= 1) {
                float b0 = bias[col], b1 = bias[col + 1];
                v0 += b0; v1 += b1; v2 += b0; v3 += b1;
            }
            if (EPI == 2) {
                v0 = gelu_f(v0); v1 = gelu_f(v1); v2 = gelu_f(v2); v3 = gelu_f(v3);
            }
            if (OF32) {
                *(float2*)(Cf + (size_t)row * N + col) = make_float2(v0, v1);
                *(float2*)(Cf + (size_t)(row + 8) * N + col) = make_float2(v2, v3);
            }
            if (OSPL) {
                size_t o = (size_t)row * (N >> 1) + (col >> 1);
                Ch[o] = cvt_pair(v0, v1);
                o = (size_t)(row + 8) * (N >> 1) + (col >> 1);
                Ch[o] = cvt_pair(v2, v3);
            }
        }
}

// =====================================================================
// Fused flash attention, pure fp16 operands.
// =====================================================================
#define FLASH_SMEM_BYTES 83968
__launch_bounds__(256, 1)
__global__ void hflash(const float* __restrict__ mask) {
    extern __shared__ uint32_t dsm[];
    uint32_t* Qh = dsm;                              // [128][32]
    uint32_t* Khs[2] = {dsm + 4096,  dsm + 8192};    // [128][32] each
    uint32_t* Vhs[2] = {dsm + 12288, dsm + 16384};   // [64][64] each
    float* mk = (float*)(dsm + 20480);               // [512]

    int tid = threadIdx.x, lane = tid & 31, w = tid >> 5;
    int mq = lane >> 2, kq = lane & 3;
    int by = blockIdx.x, z = blockIdx.y;
    int b = z >> 4, h = z & 15;

    const uint32_t* Qhb = g_Qh + (size_t)z * Mz * 32;
    const uint32_t* Khb = g_Kh + (size_t)z * Mz * 32;
    const uint32_t* Vhb = g_Vh + (size_t)z * 256 * 64;

    {
        float2 mv = *(const float2*)(mask + (size_t)b * Mz + tid * 2);
        *(float2*)(mk + tid * 2) = mv;
    }

    auto load_kv = [&](int j, int s) {
#pragma unroll
        for (int i = 0; i < 4; i++) {
            int g = tid + i * 256;
            int row = g >> 3, q0 = (g & 7) * 4;
            int cc = q0 ^ ((row & 7) * 4);
            size_t so = (size_t)(j * 128 + row) * 32 + q0;
            cp16(smem_u32(&Khs[s][row * 32 + cc]), Khb + so);
        }
#pragma unroll
        for (int i = 0; i < 4; i++) {
            int g = tid + i * 256;
            int pr = g >> 4, c0 = (g & 15) * 4;
            int cc = c0 ^ ((pr & 7) * 8);
            size_t so = (size_t)(j * 64 + pr) * 64 + c0;
            cp16(smem_u32(&Vhs[s][pr * 64 + cc]), Vhb + so);
        }
    };

#pragma unroll
    for (int i = 0; i < 4; i++) {
        int g = tid + i * 256;
        int row = g >> 3, q0 = (g & 7) * 4;
        int cc = q0 ^ ((row & 7) * 4);
        size_t so = (size_t)(by * 128 + row) * 32 + q0;
        cp16(smem_u32(&Qh[row * 32 + cc]), Qhb + so);
    }
    load_kv(0, 0); CP_COMMIT();
    load_kv(1, 1); CP_COMMIT();

    float sacc[16][4];
    float oacc[8][4];
#pragma unroll
    for (int i = 0; i < 8; i++)
#pragma unroll
        for (int t = 0; t < 4; t++) oacc[i][t] = 0.f;
    float rmax0 = -1e30f, rmax1 = -1e30f;
    float rsum0 = 0.f, rsum1 = 0.f;
    uint32_t qh[4][4];

    for (int j = 0; j < 4; j++) {
        CP_WAIT1();
        __syncthreads();
        int s = j & 1;
        if (j == 0) {
            int r0 = w * 16 + mq, r1 = r0 + 8;
#pragma unroll
            for (int c = 0; c < 4; c++) {
                int p0 = (c * 8 + kq) ^ (mq * 4);
                int p1 = (c * 8 + 4 + kq) ^ (mq * 4);
                qh[c][0] = Qh[r0 * 32 + p0];
                qh[c][1] = Qh[r1 * 32 + p0];
                qh[c][2] = Qh[r0 * 32 + p1];
                qh[c][3] = Qh[r1 * 32 + p1];
            }
        }
        // ---- S = Q K^T ----
#pragma unroll
        for (int nt = 0; nt < 16; nt++)
#pragma unroll
            for (int t = 0; t < 4; t++) sacc[nt][t] = 0.f;
#pragma unroll
        for (int c = 0; c < 4; c++) {
#pragma unroll
            for (int nt = 0; nt < 16; nt++) {
                int n = nt * 8 + mq;
                int p0 = (c * 8 + kq) ^ (mq * 4);
                int p1 = (c * 8 + 4 + kq) ^ (mq * 4);
                uint32_t bh[2];
                bh[0] = Khs[s][n * 32 + p0];
                bh[1] = Khs[s][n * 32 + p1];
                mma16(sacc[nt], qh[c], bh);
            }
        }
        // ---- scale + mask + online softmax ----
        float tm0 = -1e30f, tm1 = -1e30f;
#pragma unroll
        for (int nt = 0; nt < 16; nt++) {
            int n0 = j * 128 + nt * 8 + kq * 2;
            float m0 = mk[n0], m1 = mk[n0 + 1];
            sacc[nt][0] = sacc[nt][0] * 0.125f + m0;
            sacc[nt][1] = sacc[nt][1] * 0.125f + m1;
            sacc[nt][2] = sacc[nt][2] * 0.125f + m0;
            sacc[nt][3] = sacc[nt][3] * 0.125f + m1;
            tm0 = fmaxf(tm0, fmaxf(sacc[nt][0], sacc[nt][1]));
            tm1 = fmaxf(tm1, fmaxf(sacc[nt][2], sacc[nt][3]));
        }
        tm0 = fmaxf(tm0, __shfl_xor_sync(0xffffffffu, tm0, 1));
        tm0 = fmaxf(tm0, __shfl_xor_sync(0xffffffffu, tm0, 2));
        tm1 = fmaxf(tm1, __shfl_xor_sync(0xffffffffu, tm1, 1));
        tm1 = fmaxf(tm1, __shfl_xor_sync(0xffffffffu, tm1, 2));
        float nm0 = fmaxf(rmax0, tm0), nm1 = fmaxf(rmax1, tm1);
        float f0 = __expf(rmax0 - nm0), f1 = __expf(rmax1 - nm1);
        rmax0 = nm0; rmax1 = nm1;
        rsum0 *= f0; rsum1 *= f1;
#pragma unroll
        for (int nt = 0; nt < 8; nt++) {
            oacc[nt][0] *= f0; oacc[nt][1] *= f0;
            oacc[nt][2] *= f1; oacc[nt][3] *= f1;
        }
        float ps0 = 0.f, ps1 = 0.f;
#pragma unroll
        for (int nt = 0; nt < 16; nt++) {
            sacc[nt][0] = __expf(sacc[nt][0] - nm0);
            sacc[nt][1] = __expf(sacc[nt][1] - nm0);
            sacc[nt][2] = __expf(sacc[nt][2] - nm1);
            sacc[nt][3] = __expf(sacc[nt][3] - nm1);
            ps0 += sacc[nt][0] + sacc[nt][1];
            ps1 += sacc[nt][2] + sacc[nt][3];
        }
        rsum0 += ps0; rsum1 += ps1;
        // ---- O += P V ----
#pragma unroll
        for (int cc = 0; cc < 8; cc++) {
            uint32_t pah[4];
            pah[0] = cvt_pair(sacc[2 * cc][0],     sacc[2 * cc][1]);
            pah[1] = cvt_pair(sacc[2 * cc][2],     sacc[2 * cc][3]);
            pah[2] = cvt_pair(sacc[2 * cc + 1][0], sacc[2 * cc + 1][1]);
            pah[3] = cvt_pair(sacc[2 * cc + 1][2], sacc[2 * cc + 1][3]);
#pragma unroll
            for (int nt = 0; nt < 8; nt++) {
                int n = nt * 8 + mq;
                int pr0 = cc * 8 + kq, pr1 = pr0 + 4;
                uint32_t vh2[2];
                vh2[0] = Vhs[s][pr0 * 64 + (n ^ (kq * 8))];
                vh2[1] = Vhs[s][pr1 * 64 + (n ^ ((kq + 4) * 8))];
                mma16(oacc[nt], pah, vh2);
            }
        }
        __syncthreads();
        if (j + 2 < 4) load_kv(j + 2, s);
        CP_COMMIT();
    }

    // ---- epilogue ----
    rsum0 += __shfl_xor_sync(0xffffffffu, rsum0, 1);
    rsum0 += __shfl_xor_sync(0xffffffffu, rsum0, 2);
    rsum1 += __shfl_xor_sync(0xffffffffu, rsum1, 1);
    rsum1 += __shfl_xor_sync(0xffffffffu, rsum1, 2);
    float inv0 = 1.0f / rsum0, inv1 = 1.0f / rsum1;
    int m0 = by * 128 + w * 16 + mq;
#pragma unroll
    for (int nt = 0; nt < 8; nt++) {
        int d = nt * 8 + kq * 2;
        int colp = (h * DHz + d) >> 1;
        size_t o = (size_t)(b * Mz + m0) * 512 + colp;
        g_ath[o] = cvt_pair(oacc[nt][0] * inv0, oacc[nt][1] * inv0);
        o = (size_t)(b * Mz + m0 + 8) * 512 + colp;
        g_ath[o] = cvt_pair(oacc[nt][2] * inv1, oacc[nt][3] * inv1);
    }
}

// ---------------- rank-32 expansion + pack ----------------
__launch_bounds__(256)
__global__ void qkv2_k(const float* __restrict__ Vq, const float* __restrict__ Vk,
                       const float* __restrict__ Vv, const float* __restrict__ bq,
                       const float* __restrict__ bk, const float* __restrict__ bv) {
    __shared__ float Vs[RAz][DHz];
    __shared__ float tile[8][65];
    int z = blockIdx.y, j = blockIdx.z;
    int b = z / Hz, h = z % Hz;
    const float* Vm = (j == 0) ? Vq : ((j == 1) ? Vk : Vv);
    const float* bm = (j == 0) ? bq : ((j == 1) ? bk : bv);
    int tid = threadIdx.x;
#pragma unroll
    for (int i = 0; i < 8; i++) {
        int idx = tid + i * 256;
        Vs[idx >> 6][idx & 63] = Vm[(size_t)h * RAz * DHz + idx];
    }
    __syncthreads();

    int m0 = blockIdx.x * 8;
    int d = tid & 63, ml = tid >> 6;
#pragma unroll
    for (int rr = 0; rr < 2; rr++) {
        int r = ml + rr * 4;
        int m = m0 + r;
        const float* trow = g_T + ((size_t)(b * Mz + m)) * C3 + j * 512 + h * RAz;
        float acc = bm[h * DHz + d];
#pragma unroll
        for (int k = 0; k < RAz; k++) acc += trow[k] * Vs[k][d];
        tile[r][d] = acc;
    }
    __syncthreads();

    if (j == 0) {
        int m = tid >> 5, dp = tid & 31;
        size_t o = ((size_t)z * Mz + m0 + m) * 32 + dp;
        g_Qh[o] = cvt_pair(tile[m][2 * dp], tile[m][2 * dp + 1]);
    } else if (j == 1) {
        int m = tid >> 5, dp = tid & 31;
        size_t o = ((size_t)z * Mz + m0 + m) * 32 + dp;
        g_Kh[o] = cvt_pair(tile[m][2 * dp], tile[m][2 * dp + 1]);
    } else {
        int mp = tid >> 6, dd = tid & 63;
        size_t o = ((size_t)z * 256 + (m0 >> 1) + mp) * 64 + dd;
        g_Vh[o] = cvt_pair(tile[2 * mp][dd], tile[2 * mp + 1][dd]);
    }
}

// ---------------- residual + LayerNorm ----------------
template <bool SPLIT>
__launch_bounds__(256)
__global__ void ln_k(const float* __restrict__ a, const float* __restrict__ r,
                     const float* __restrict__ g, const float* __restrict__ bb,
                     float* __restrict__ out) {
    __shared__ float sh[8];
    int row = blockIdx.x;
    int tid = threadIdx.x;
    int lane = tid & 31, warp = tid >> 5;
    int c = tid * 4;
    float4 xa = *(const float4*)(a + (size_t)row * DMz + c);
    float4 ya = *(const float4*)(r + (size_t)row * DMz + c);
    float v[4] = {xa.x + ya.x, xa.y + ya.y, xa.z + ya.z, xa.w + ya.w};
    float s = v[0] + v[1] + v[2] + v[3];
#pragma unroll
    for (int o = 16; o > 0; o >>= 1) s += __shfl_xor_sync(0xffffffffu, s, o);
    if (lane == 0) sh[warp] = s;
    __syncthreads();
    if (warp == 0) {
        float t = (lane < 8) ? sh[lane] : 0.f;
#pragma unroll
        for (int o = 4; o > 0; o >>= 1) t += __shfl_xor_sync(0xffffffffu, t, o);
        if (lane == 0) sh[0] = t;
    }
    __syncthreads();
    float mu = sh[0] * (1.0f / DMz);
    __syncthreads();

    float q = 0.f;
#pragma unroll
    for (int i = 0; i < 4; i++) {
        float d = v[i] - mu;
        q += d * d;
    }
#pragma unroll
    for (int o = 16; o > 0; o >>= 1) q += __shfl_xor_sync(0xffffffffu, q, o);
    if (lane == 0) sh[warp] = q;
    __syncthreads();
    if (warp == 0) {
        float t = (lane < 8) ? sh[lane] : 0.f;
#pragma unroll
        for (int o = 4; o > 0; o >>= 1) t += __shfl_xor_sync(0xffffffffu, t, o);
        if (lane == 0) sh[0] = t;
    }
    __syncthreads();
    float var = sh[0] * (1.0f / DMz);
    float rs = rsqrtf(var + LN_EPS);
    float4 gg = *(const float4*)(g + c);
    float4 bbv = *(const float4*)(bb + c);
    float o0 = (v[0] - mu) * rs * gg.x + bbv.x;
    float o1 = (v[1] - mu) * rs * gg.y + bbv.y;
    float o2 = (v[2] - mu) * rs * gg.z + bbv.z;
    float o3 = (v[3] - mu) * rs * gg.w + bbv.w;
    *(float4*)(out + (size_t)row * DMz + c) = make_float4(o0, o1, o2, o3);
    if (SPLIT) {
        size_t o = (size_t)row * 512 + (c >> 1);
        g_x1h[o] = cvt_pair(o0, o1);
        g_x1h[o + 1] = cvt_pair(o2, o3);
    }
}

// ---------------- launch ----------------
extern "C" void kernel_launch(void* const* d_in, const int* in_sizes, int n_in,
                              void* d_out, int out_size) {
    const float* x    = (const float*)d_in[0];
    const float* mask = (const float*)d_in[1];
    const float* Pq   = (const float*)d_in[2];
    const float* Vq   = (const float*)d_in[3];
    const float* Pk   = (const float*)d_in[4];
    const float* Vk   = (const float*)d_in[5];
    const float* Pv   = (const float*)d_in[6];
    const float* Vv   = (const float*)d_in[7];
    const float* bq   = (const float*)d_in[8];
    const float* bk   = (const float*)d_in[9];
    const float* bv   = (const float*)d_in[10];
    const float* Uo   = (const float*)d_in[11];
    const float* Vo   = (const float*)d_in[12];
    const float* bo   = (const float*)d_in[13];
    const float* U1   = (const float*)d_in[14];
    const float* V1   = (const float*)d_in[15];
    const float* b1   = (const float*)d_in[16];
    const float* U2   = (const float*)d_in[17];
    const float* V2   = (const float*)d_in[18];
    const float* b2   = (const float*)d_in[19];
    const float* ln1g = (const float*)d_in[20];
    const float* ln1b = (const float*)d_in[21];
    const float* ln2g = (const float*)d_in[22];
    const float* ln2b = (const float*)d_in[23];
    float* out = (float*)d_out;

#define SYM(p, s) cudaGetSymbolAddress((void**)&p, s)
    uint32_t *xh, *wch, *Uoh, *Voh, *U1h, *V1h, *U2h, *V2h;
    uint32_t *ath, *t1h, *x1h, *mdh, *hdh, *t2h;
    float *T, *y1, *x1, *y2;
    SYM(xh, g_xh); SYM(wch, g_wch);
    SYM(Uoh, g_Uoh); SYM(Voh, g_Voh);
    SYM(U1h, g_U1h); SYM(V1h, g_V1h);
    SYM(U2h, g_U2h); SYM(V2h, g_V2h);
    SYM(ath, g_ath); SYM(t1h, g_t1h);
    SYM(x1h, g_x1h); SYM(mdh, g_mdh);
    SYM(hdh, g_hdh); SYM(t2h, g_t2h);
    SYM(T, g_T); SYM(y1, g_y1); SYM(x1, g_x1); SYM(y2, g_y2);
#undef SYM

    cudaFuncSetAttribute(hflash, cudaFuncAttributeMaxDynamicSharedMemorySize,
                         FLASH_SMEM_BYTES);

    // operand conversion
    conv_x<<<BMr * 512 / 256, 256>>>(x);
    pack_w_split<<<512 * C3 / 256, 256>>>(Pq, Pk, Pv);
    convB<<<(512 * ROz + 255) / 256, 256>>>(Uo, Uoh, 512, ROz);
    convB<<<(192 * DMz + 255) / 256, 256>>>(Vo, Voh, 192, DMz);
    convB<<<(512 * RFz + 255) / 256, 256>>>(U1, U1h, 512, RFz);
    convB<<<(192 * DFFz + 255) / 256, 256>>>(V1, V1h, 192, DFFz);
    convB<<<(2048 * RFz + 255) / 256, 256>>>(U2, U2h, 2048, RFz);
    convB<<<(192 * DMz + 255) / 256, 256>>>(V2, V2h, 192, DMz);

    // qkv low-rank
    hgemm<128, true, false, 0><<<dim3(C3 / 128, BMr / 128), 256>>>(
        xh, wch, T, nullptr, C3, DMz, nullptr);
    qkv2_k<<<dim3(Mz / 8, ZT, 3), 256>>>(Vq, Vk, Vv, bq, bk, bv);

    // fused attention
    hflash<<<dim3(Mz / 128, ZT), 256, FLASH_SMEM_BYTES>>>(mask);

    // output projection + LN1
    hgemm<64, false, true, 0><<<dim3(ROz / 128, BMr / 64), 256>>>(
        ath, Uoh, nullptr, t1h, ROz, DMz, nullptr);
    hgemm<128, true, false, 1><<<dim3(DMz / 128, BMr / 128), 256>>>(
        t1h, Voh, y1, nullptr, DMz, ROz, bo);
    ln_k<true><<<BMr, 256>>>(x, y1, ln1g, ln1b, x1);

    // FFN
    hgemm<64, false, true, 0><<<dim3(RFz / 128, BMr / 64), 256>>>(
        x1h, U1h, nullptr, mdh, RFz, DMz, nullptr);
    hgemm<128, false, true, 2><<<dim3(DFFz / 128, BMr / 128), 256>>>(
        mdh, V1h, nullptr, hdh, DFFz, RFz, b1);
    hgemm<64, false, true, 0><<<dim3(RFz / 128, BMr / 64), 256>>>(
        hdh, U2h, nullptr, t2h, RFz, DFFz, nullptr);
    hgemm<128, true, false, 1><<<dim3(DMz / 128, BMr / 128), 256>>>(
        t2h, V2h, y2, nullptr, DMz, RFz, b2);

    // LN2 -> out
    ln_k<false><<<BMr, 256>>>(x1, y2, ln2g, ln2b, out);
}

// round 15
// speedup vs baseline: 4.9654x; 1.0157x over previous
#include <cuda_runtime.h>
#include <cuda_fp16.h>
#include <math.h>
#include <stdint.h>

#define Bz 8
#define Mz 512
#define DMz 1024
#define Hz 16
#define DHz 64
#define DFFz 4096
#define RAz 32
#define RFz 384
#define ROz 384
#define BMr (Bz*Mz)          // 4096
#define C3 (3*Hz*RAz)        // 1536
#define ZT (Bz*Hz)           // 128
#define LN_EPS 1e-12f

// ---------------- scratch (device globals) ----------------
// A-side: [M][K/2] u32 pairs along K (unchanged).
// B-side: plain fp16 row-major [K][N] (u32 = 2 consecutive n).
__device__ uint32_t g_xh[BMr*512];
__device__ uint32_t g_wch[DMz*(C3/2)];           // [1024][768]
__device__ float    g_T[BMr*C3];
__device__ uint32_t g_Qh[ZT*Mz*32];              // [z][512 tok][32 dpair]  (A-side)
__device__ uint32_t g_Kh[ZT*DHz*256];            // [z][64 d][256 tokpair]  (B k-major: k=d)
__device__ uint32_t g_Vh[ZT*Mz*32];              // [z][512 tok][32 dpair]  (B k-major: k=tok)
__device__ uint32_t g_ath[BMr*512];
__device__ uint32_t g_Uoh[DMz*(ROz/2)];          // [1024][192]
__device__ uint32_t g_Voh[ROz*(DMz/2)];          // [384][512]
__device__ uint32_t g_U1h[DMz*(RFz/2)];          // [1024][192]
__device__ uint32_t g_V1h[RFz*(DFFz/2)];         // [384][2048]
__device__ uint32_t g_U2h[DFFz*(RFz/2)];         // [4096][192]
__device__ uint32_t g_V2h[RFz*(DMz/2)];          // [384][512]
__device__ uint32_t g_t1h[BMr*192];
__device__ float    g_y1[BMr*DMz];
__device__ float    g_x1[BMr*DMz];
__device__ uint32_t g_x1h[BMr*512];
__device__ uint32_t g_mdh[BMr*192];
__device__ uint32_t g_hdh[(size_t)BMr*2048];
__device__ uint32_t g_t2h[BMr*192];
__device__ float    g_y2[BMr*DMz];

// ---------------- helpers ----------------
__device__ __forceinline__ float gelu_f(float x) {
    return 0.5f * x * (1.0f + erff(x * 0.70710678118654752440f));
}
__device__ __forceinline__ uint32_t cvt_pair(float x0, float x1) {
    __half2 hh = __halves2half2(__float2half_rn(x0), __float2half_rn(x1));
    return *(uint32_t*)&hh;
}
__device__ __forceinline__ void mma16(float* c, const uint32_t* a, const uint32_t* b) {
    asm volatile(
        "mma.sync.aligned.m16n8k16.row.col.f32.f16.f16.f32 "
        "{%0,%1,%2,%3}, {%4,%5,%6,%7}, {%8,%9}, {%0,%1,%2,%3};"
        : "+f"(c[0]), "+f"(c[1]), "+f"(c[2]), "+f"(c[3])
        : "r"(a[0]), "r"(a[1]), "r"(a[2]), "r"(a[3]), "r"(b[0]), "r"(b[1]));
}
__device__ __forceinline__ uint32_t smem_u32(const void* p) {
    return (uint32_t)__cvta_generic_to_shared(p);
}
__device__ __forceinline__ void ldsm4(uint32_t& r0, uint32_t& r1, uint32_t& r2,
                                      uint32_t& r3, uint32_t addr) {
    asm volatile("ldmatrix.sync.aligned.m8n8.x4.shared.b16 {%0,%1,%2,%3}, [%4];"
                 : "=r"(r0), "=r"(r1), "=r"(r2), "=r"(r3) : "r"(addr));
}
__device__ __forceinline__ void ldsm4t(uint32_t& r0, uint32_t& r1, uint32_t& r2,
                                       uint32_t& r3, uint32_t addr) {
    asm volatile("ldmatrix.sync.aligned.m8n8.x4.trans.shared.b16 {%0,%1,%2,%3}, [%4];"
                 : "=r"(r0), "=r"(r1), "=r"(r2), "=r"(r3) : "r"(addr));
}
__device__ __forceinline__ void cp16(uint32_t dst, const void* src) {
    asm volatile("cp.async.cg.shared.global [%0], [%1], 16;" :: "r"(dst), "l"(src));
}
#define CP_COMMIT() asm volatile("cp.async.commit_group;")
#define CP_WAIT1()  asm volatile("cp.async.wait_group 1;")

// ---------------- conversion kernels ----------------
__global__ void conv_x(const float* __restrict__ x) {
    int idx = blockIdx.x * blockDim.x + threadIdx.x;
    int row = idx >> 9, p = idx & 511;
    float2 v = *(const float2*)(x + (size_t)row * DMz + 2 * p);
    g_xh[idx] = cvt_pair(v.x, v.y);
}
// Wcat as [K=1024][C3] plain fp16: wch[d][np] = pair of columns (2np, 2np+1)
__global__ void pack_w_split(const float* __restrict__ Pq, const float* __restrict__ Pk,
                             const float* __restrict__ Pv) {
    int idx = blockIdx.x * blockDim.x + threadIdx.x;   // 1024 * 768
    int d = idx / (C3 / 2), np = idx % (C3 / 2);
    float v[2];
#pragma unroll
    for (int u = 0; u < 2; u++) {
        int c = 2 * np + u;
        int j = c / 512, hr = c % 512, h = hr >> 5, r = hr & 31;
        const float* P = (j == 0) ? Pq : ((j == 1) ? Pk : Pv);
        v[u] = P[((size_t)h * DMz + d) * RAz + r];
    }
    g_wch[idx] = cvt_pair(v[0], v[1]);
}
// W[K][N] fp32 -> oh[K][N/2] u32 (2 n per u32)
__global__ void convB(const float* __restrict__ W, uint32_t* __restrict__ oh,
                      int K, int N) {
    int idx = blockIdx.x * blockDim.x + threadIdx.x;
    if (idx >= K * (N >> 1)) return;
    int k = idx / (N >> 1), np = idx % (N >> 1);
    float v0 = W[(size_t)k * N + 2 * np];
    float v1 = W[(size_t)k * N + 2 * np + 1];
    oh[idx] = cvt_pair(v0, v1);
}

// =====================================================================
// fp16 GEMM with ldmatrix. A: [M][K/2] pairs. B: [K][N/2] plain fp16.
// CTA CTAMx128, BK=16, 8 warps. 6 shared ops per 16 mmas.
// =====================================================================
template <int CTAM, bool OF32, bool OSPL, int EPI>
__launch_bounds__(256, 2)
__global__ void hgemm(const uint32_t* __restrict__ Ah, const uint32_t* __restrict__ Bh,
                      float* __restrict__ Cf, uint32_t* __restrict__ Ch,
                      int N, int K, const float* __restrict__ bias) {
    constexpr int MT = CTAM / 32;
    __shared__ uint32_t Ash[3][CTAM][8];     // [m][kpair chunks], 2x16B, swz ^(row&4)
    __shared__ uint32_t Bsh[3][16][64];      // [k][n u32], 16x16B chunks, swz ^((k&7)*2)

    int tid = threadIdx.x, lane = tid & 31, wid = tid >> 5;
    int warp_m = (wid >> 2) * (CTAM / 2);
    int warp_n = (wid & 3) * 32;
    int by = blockIdx.y, bx = blockIdx.x;
    int kp2 = K >> 1, n2 = N >> 1;
    int mq = lane >> 2, kq = lane & 3;
    int nk = K >> 4;
    int lt = lane >> 3, lr = lane & 7;

    auto load_stage = [&](int kt, int s) {
        if (tid < CTAM * 2) {
            int row = tid >> 1, hf = (tid & 1) * 4;
            int cc = hf ^ (row & 4);
            size_t so = (size_t)(by * CTAM + row) * kp2 + kt * 8 + hf;
            cp16(smem_u32(&Ash[s][row][cc]), Ah + so);
        }
        {
            int row = tid >> 4, ch = tid & 15;
            int cc = ch ^ ((row & 7) * 2);
            size_t so = (size_t)(kt * 16 + row) * n2 + bx * 64 + ch * 4;
            cp16(smem_u32(&Bsh[s][row][cc * 4]), Bh + so);
        }
    };

    float acc[MT][4][4];
#pragma unroll
    for (int i = 0; i < MT; i++)
#pragma unroll
        for (int j = 0; j < 4; j++)
#pragma unroll
            for (int t = 0; t < 4; t++) acc[i][j][t] = 0.f;

    load_stage(0, 0); CP_COMMIT();
    load_stage(1, 1); CP_COMMIT();

    for (int kt = 0; kt < nk; kt++) {
        CP_WAIT1();
        __syncthreads();
        int s = kt % 3;
        // B frags: 2 x ldmatrix.x4.trans (covers warp's 32 n)
        uint32_t fb[4][2];
#pragma unroll
        for (int p = 0; p < 2; p++) {
            int krow = (lt & 1) * 8 + lr;
            int chIdx = (warp_n >> 3) + p * 2 + (lt >> 1);
            uint32_t addr = smem_u32(&Bsh[s][krow][4 * (chIdx ^ ((krow & 7) * 2))]);
            ldsm4t(fb[2 * p][0], fb[2 * p][1], fb[2 * p + 1][0], fb[2 * p + 1][1], addr);
        }
#pragma unroll
        for (int mt = 0; mt < MT; mt++) {
            int row = warp_m + mt * 16 + (lt & 1) * 8 + lr;
            uint32_t addr = smem_u32(&Ash[s][row][((lt >> 1) * 4) ^ (row & 4)]);
            uint32_t fa[4];
            ldsm4(fa[0], fa[1], fa[2], fa[3], addr);
#pragma unroll
            for (int nt = 0; nt < 4; nt++) mma16(acc[mt][nt], fa, fb[nt]);
        }
        if (kt + 2 < nk) load_stage(kt + 2, (kt + 2) % 3);
        CP_COMMIT();
    }

#pragma unroll
    for (int mt = 0; mt < MT; mt++)
#pragma unroll
        for (int nt = 0; nt < 4; nt++) {
            int row = by * CTAM + warp_m + mt * 16 + mq;
            int col = bx * 128 + warp_n + nt * 8 + kq * 2;
            float v0 = acc[mt][nt][0], v1 = acc[mt][nt][1];
            float v2 = acc[mt][nt][2], v3 = acc[mt][nt][3];
            if (EPI >= 1) {
                float b0 = bias[col], b1 = bias[col + 1];
                v0 += b0; v1 += b1; v2 += b0; v3 += b1;
            }
            if (EPI == 2) {
                v0 = gelu_f(v0); v1 = gelu_f(v1); v2 = gelu_f(v2); v3 = gelu_f(v3);
            }
            if (OF32) {
                *(float2*)(Cf + (size_t)row * N + col) = make_float2(v0, v1);
                *(float2*)(Cf + (size_t)(row + 8) * N + col) = make_float2(v2, v3);
            }
            if (OSPL) {
                size_t o = (size_t)row * (N >> 1) + (col >> 1);
                Ch[o] = cvt_pair(v0, v1);
                o = (size_t)(row + 8) * (N >> 1) + (col >> 1);
                Ch[o] = cvt_pair(v2, v3);
            }
        }
}

// =====================================================================
// Fused flash attention with ldmatrix B-operands.
// Q: [tok][dpair] (A-side). K: [d][tokpair] (k-major, k=d).
// V: [tok][dpair]  (k-major, k=tok).
// =====================================================================
#define FLASH_SMEM_BYTES 83968
__launch_bounds__(256, 1)
__global__ void hflash(const float* __restrict__ mask) {
    extern __shared__ uint32_t dsm[];
    uint32_t* Qh = dsm;                               // [128][32]
    uint32_t* Khs[2] = {dsm + 4096,  dsm + 8192};     // [64 d][64 u32] each
    uint32_t* Vhs[2] = {dsm + 12288, dsm + 16384};    // [128 tok][32 u32] each
    float* mk = (float*)(dsm + 20480);                // [512]

    int tid = threadIdx.x, lane = tid & 31, w = tid >> 5;
    int mq = lane >> 2, kq = lane & 3;
    int lt = lane >> 3, lr = lane & 7;
    int by = blockIdx.x, z = blockIdx.y;
    int b = z >> 4, h = z & 15;

    const uint32_t* Qhb = g_Qh + (size_t)z * Mz * 32;
    const uint32_t* Khb = g_Kh + (size_t)z * DHz * 256;
    const uint32_t* Vhb = g_Vh + (size_t)z * Mz * 32;

    {
        float2 mv = *(const float2*)(mask + (size_t)b * Mz + tid * 2);
        *(float2*)(mk + tid * 2) = mv;
    }

    auto load_kv = [&](int j, int s) {
        // K tile: 64 d-rows x 64 u32 (128 tokens); 16 chunks/row
#pragma unroll
        for (int i = 0; i < 4; i++) {
            int g = tid + i * 256;            // 1024
            int row = g >> 4, ch = g & 15;
            int cc = ch ^ ((row & 7) * 2);
            cp16(smem_u32(&Khs[s][row * 64 + cc * 4]),
                 Khb + (size_t)row * 256 + j * 64 + ch * 4);
        }
        // V tile: 128 tok-rows x 32 u32 (64 d); 8 chunks/row
#pragma unroll
        for (int i = 0; i < 4; i++) {
            int g = tid + i * 256;            // 1024
            int row = g >> 3, ch = g & 7;
            int cc = ch ^ (row & 7);
            cp16(smem_u32(&Vhs[s][row * 32 + cc * 4]),
                 Vhb + (size_t)(j * 128 + row) * 32 + ch * 4);
        }
    };

#pragma unroll
    for (int i = 0; i < 4; i++) {
        int g = tid + i * 256;
        int row = g >> 3, q0 = (g & 7) * 4;
        int cc = q0 ^ ((row & 7) * 4);
        size_t so = (size_t)(by * 128 + row) * 32 + q0;
        cp16(smem_u32(&Qh[row * 32 + cc]), Qhb + so);
    }
    load_kv(0, 0); CP_COMMIT();
    load_kv(1, 1); CP_COMMIT();

    float sacc[16][4];
    float oacc[8][4];
#pragma unroll
    for (int i = 0; i < 8; i++)
#pragma unroll
        for (int t = 0; t < 4; t++) oacc[i][t] = 0.f;
    float rmax0 = -1e30f, rmax1 = -1e30f;
    float rsum0 = 0.f, rsum1 = 0.f;
    uint32_t qh[4][4];

    for (int j = 0; j < 4; j++) {
        CP_WAIT1();
        __syncthreads();
        int s = j & 1;
        if (j == 0) {
            int r0 = w * 16 + mq, r1 = r0 + 8;
#pragma unroll
            for (int c = 0; c < 4; c++) {
                int p0 = (c * 8 + kq) ^ (mq * 4);
                int p1 = (c * 8 + 4 + kq) ^ (mq * 4);
                qh[c][0] = Qh[r0 * 32 + p0];
                qh[c][1] = Qh[r1 * 32 + p0];
                qh[c][2] = Qh[r0 * 32 + p1];
                qh[c][3] = Qh[r1 * 32 + p1];
            }
        }
        // ---- S = Q K^T  (B frags via ldmatrix.x4.trans on d-major K) ----
#pragma unroll
        for (int nt = 0; nt < 16; nt++)
#pragma unroll
            for (int t = 0; t < 4; t++) sacc[nt][t] = 0.f;
#pragma unroll
        for (int c = 0; c < 4; c++) {
#pragma unroll
            for (int ntp = 0; ntp < 8; ntp++) {
                int drow = c * 16 + (lt & 1) * 8 + lr;
                int chk = ntp * 2 + (lt >> 1);
                uint32_t addr = smem_u32(&Khs[s][drow * 64 + 4 * (chk ^ ((drow & 7) * 2))]);
                uint32_t b0, b1, b2, b3;
                ldsm4t(b0, b1, b2, b3, addr);
                uint32_t fb0[2] = {b0, b1}, fb1[2] = {b2, b3};
                mma16(sacc[2 * ntp], qh[c], fb0);
                mma16(sacc[2 * ntp + 1], qh[c], fb1);
            }
        }
        // ---- scale + mask + online softmax ----
        float tm0 = -1e30f, tm1 = -1e30f;
#pragma unroll
        for (int nt = 0; nt < 16; nt++) {
            int n0 = j * 128 + nt * 8 + kq * 2;
            float m0 = mk[n0], m1 = mk[n0 + 1];
            sacc[nt][0] = sacc[nt][0] * 0.125f + m0;
            sacc[nt][1] = sacc[nt][1] * 0.125f + m1;
            sacc[nt][2] = sacc[nt][2] * 0.125f + m0;
            sacc[nt][3] = sacc[nt][3] * 0.125f + m1;
            tm0 = fmaxf(tm0, fmaxf(sacc[nt][0], sacc[nt][1]));
            tm1 = fmaxf(tm1, fmaxf(sacc[nt][2], sacc[nt][3]));
        }
        tm0 = fmaxf(tm0, __shfl_xor_sync(0xffffffffu, tm0, 1));
        tm0 = fmaxf(tm0, __shfl_xor_sync(0xffffffffu, tm0, 2));
        tm1 = fmaxf(tm1, __shfl_xor_sync(0xffffffffu, tm1, 1));
        tm1 = fmaxf(tm1, __shfl_xor_sync(0xffffffffu, tm1, 2));
        float nm0 = fmaxf(rmax0, tm0), nm1 = fmaxf(rmax1, tm1);
        float f0 = __expf(rmax0 - nm0), f1 = __expf(rmax1 - nm1);
        rmax0 = nm0; rmax1 = nm1;
        rsum0 *= f0; rsum1 *= f1;
#pragma unroll
        for (int nt = 0; nt < 8; nt++) {
            oacc[nt][0] *= f0; oacc[nt][1] *= f0;
            oacc[nt][2] *= f1; oacc[nt][3] *= f1;
        }
        float ps0 = 0.f, ps1 = 0.f;
#pragma unroll
        for (int nt = 0; nt < 16; nt++) {
            sacc[nt][0] = __expf(sacc[nt][0] - nm0);
            sacc[nt][1] = __expf(sacc[nt][1] - nm0);
            sacc[nt][2] = __expf(sacc[nt][2] - nm1);
            sacc[nt][3] = __expf(sacc[nt][3] - nm1);
            ps0 += sacc[nt][0] + sacc[nt][1];
            ps1 += sacc[nt][2] + sacc[nt][3];
        }
        rsum0 += ps0; rsum1 += ps1;
        // ---- O += P V  (V frags via ldmatrix.x4.trans on tok-major V) ----
#pragma unroll
        for (int cc = 0; cc < 8; cc++) {
            uint32_t pah[4];
            pah[0] = cvt_pair(sacc[2 * cc][0],     sacc[2 * cc][1]);
            pah[1] = cvt_pair(sacc[2 * cc][2],     sacc[2 * cc][3]);
            pah[2] = cvt_pair(sacc[2 * cc + 1][0], sacc[2 * cc + 1][1]);
            pah[3] = cvt_pair(sacc[2 * cc + 1][2], sacc[2 * cc + 1][3]);
#pragma unroll
            for (int ntp = 0; ntp < 4; ntp++) {
                int trow = cc * 16 + (lt & 1) * 8 + lr;
                int chk = ntp * 2 + (lt >> 1);
                uint32_t addr = smem_u32(&Vhs[s][trow * 32 + 4 * (chk ^ (trow & 7))]);
                uint32_t b0, b1, b2, b3;
                ldsm4t(b0, b1, b2, b3, addr);
                uint32_t fb0[2] = {b0, b1}, fb1[2] = {b2, b3};
                mma16(oacc[2 * ntp], pah, fb0);
                mma16(oacc[2 * ntp + 1], pah, fb1);
            }
        }
        __syncthreads();
        if (j + 2 < 4) load_kv(j + 2, s);
        CP_COMMIT();
    }

    // ---- epilogue ----
    rsum0 += __shfl_xor_sync(0xffffffffu, rsum0, 1);
    rsum0 += __shfl_xor_sync(0xffffffffu, rsum0, 2);
    rsum1 += __shfl_xor_sync(0xffffffffu, rsum1, 1);
    rsum1 += __shfl_xor_sync(0xffffffffu, rsum1, 2);
    float inv0 = 1.0f / rsum0, inv1 = 1.0f / rsum1;
    int m0 = by * 128 + w * 16 + mq;
#pragma unroll
    for (int nt = 0; nt < 8; nt++) {
        int d = nt * 8 + kq * 2;
        int colp = (h * DHz + d) >> 1;
        size_t o = (size_t)(b * Mz + m0) * 512 + colp;
        g_ath[o] = cvt_pair(oacc[nt][0] * inv0, oacc[nt][1] * inv0);
        o = (size_t)(b * Mz + m0 + 8) * 512 + colp;
        g_ath[o] = cvt_pair(oacc[nt][2] * inv1, oacc[nt][3] * inv1);
    }
}

// ---------------- rank-32 expansion + pack (Q A-fmt; K d-major; V tok-major) ----------------
__launch_bounds__(256)
__global__ void qkv2_k(const float* __restrict__ Vq, const float* __restrict__ Vk,
                       const float* __restrict__ Vv, const float* __restrict__ bq,
                       const float* __restrict__ bk, const float* __restrict__ bv) {
    __shared__ float Vs[RAz][DHz];
    __shared__ float tile[8][65];
    int z = blockIdx.y, j = blockIdx.z;
    int b = z / Hz, h = z % Hz;
    const float* Vm = (j == 0) ? Vq : ((j == 1) ? Vk : Vv);
    const float* bm = (j == 0) ? bq : ((j == 1) ? bk : bv);
    int tid = threadIdx.x;
#pragma unroll
    for (int i = 0; i < 8; i++) {
        int idx = tid + i * 256;
        Vs[idx >> 6][idx & 63] = Vm[(size_t)h * RAz * DHz + idx];
    }
    __syncthreads();

    int m0 = blockIdx.x * 8;
    int d = tid & 63, ml = tid >> 6;
#pragma unroll
    for (int rr = 0; rr < 2; rr++) {
        int r = ml + rr * 4;
        int m = m0 + r;
        const float* trow = g_T + ((size_t)(b * Mz + m)) * C3 + j * 512 + h * RAz;
        float acc = bm[h * DHz + d];
#pragma unroll
        for (int k = 0; k < RAz; k++) acc += trow[k] * Vs[k][d];
        tile[r][d] = acc;
    }
    __syncthreads();

    if (j == 0) {
        // Q: [tok][dpair]
        int m = tid >> 5, dp = tid & 31;
        size_t o = ((size_t)z * Mz + m0 + m) * 32 + dp;
        g_Qh[o] = cvt_pair(tile[m][2 * dp], tile[m][2 * dp + 1]);
    } else if (j == 1) {
        // K: d-major [d][tokpair]
        int mp = tid >> 6, dd = tid & 63;
        size_t o = ((size_t)z * DHz + dd) * 256 + (m0 >> 1) + mp;
        g_Kh[o] = cvt_pair(tile[2 * mp][dd], tile[2 * mp + 1][dd]);
    } else {
        // V: tok-major [tok][dpair]
        int m = tid >> 5, dp = tid & 31;
        size_t o = ((size_t)z * Mz + m0 + m) * 32 + dp;
        g_Vh[o] = cvt_pair(tile[m][2 * dp], tile[m][2 * dp + 1]);
    }
}

// ---------------- residual + LayerNorm ----------------
template <bool SPLIT>
__launch_bounds__(256)
__global__ void ln_k(const float* __restrict__ a, const float* __restrict__ r,
                     const float* __restrict__ g, const float* __restrict__ bb,
                     float* __restrict__ out) {
    __shared__ float sh[8];
    int row = blockIdx.x;
    int tid = threadIdx.x;
    int lane = tid & 31, warp = tid >> 5;
    int c = tid * 4;
    float4 xa = *(const float4*)(a + (size_t)row * DMz + c);
    float4 ya = *(const float4*)(r + (size_t)row * DMz + c);
    float v[4] = {xa.x + ya.x, xa.y + ya.y, xa.z + ya.z, xa.w + ya.w};
    float s = v[0] + v[1] + v[2] + v[3];
#pragma unroll
    for (int o = 16; o > 0; o >>= 1) s += __shfl_xor_sync(0xffffffffu, s, o);
    if (lane == 0) sh[warp] = s;
    __syncthreads();
    if (warp == 0) {
        float t = (lane < 8) ? sh[lane] : 0.f;
#pragma unroll
        for (int o = 4; o > 0; o >>= 1) t += __shfl_xor_sync(0xffffffffu, t, o);
        if (lane == 0) sh[0] = t;
    }
    __syncthreads();
    float mu = sh[0] * (1.0f / DMz);
    __syncthreads();

    float q = 0.f;
#pragma unroll
    for (int i = 0; i < 4; i++) {
        float d = v[i] - mu;
        q += d * d;
    }
#pragma unroll
    for (int o = 16; o > 0; o >>= 1) q += __shfl_xor_sync(0xffffffffu, q, o);
    if (lane == 0) sh[warp] = q;
    __syncthreads();
    if (warp == 0) {
        float t = (lane < 8) ? sh[lane] : 0.f;
#pragma unroll
        for (int o = 4; o > 0; o >>= 1) t += __shfl_xor_sync(0xffffffffu, t, o);
        if (lane == 0) sh[0] = t;
    }
    __syncthreads();
    float var = sh[0] * (1.0f / DMz);
    float rs = rsqrtf(var + LN_EPS);
    float4 gg = *(const float4*)(g + c);
    float4 bbv = *(const float4*)(bb + c);
    float o0 = (v[0] - mu) * rs * gg.x + bbv.x;
    float o1 = (v[1] - mu) * rs * gg.y + bbv.y;
    float o2 = (v[2] - mu) * rs * gg.z + bbv.z;
    float o3 = (v[3] - mu) * rs * gg.w + bbv.w;
    *(float4*)(out + (size_t)row * DMz + c) = make_float4(o0, o1, o2, o3);
    if (SPLIT) {
        size_t o = (size_t)row * 512 + (c >> 1);
        g_x1h[o] = cvt_pair(o0, o1);
        g_x1h[o + 1] = cvt_pair(o2, o3);
    }
}

// ---------------- launch ----------------
extern "C" void kernel_launch(void* const* d_in, const int* in_sizes, int n_in,
                              void* d_out, int out_size) {
    const float* x    = (const float*)d_in[0];
    const float* mask = (const float*)d_in[1];
    const float* Pq   = (const float*)d_in[2];
    const float* Vq   = (const float*)d_in[3];
    const float* Pk   = (const float*)d_in[4];
    const float* Vk   = (const float*)d_in[5];
    const float* Pv   = (const float*)d_in[6];
    const float* Vv   = (const float*)d_in[7];
    const float* bq   = (const float*)d_in[8];
    const float* bk   = (const float*)d_in[9];
    const float* bv   = (const float*)d_in[10];
    const float* Uo   = (const float*)d_in[11];
    const float* Vo   = (const float*)d_in[12];
    const float* bo   = (const float*)d_in[13];
    const float* U1   = (const float*)d_in[14];
    const float* V1   = (const float*)d_in[15];
    const float* b1   = (const float*)d_in[16];
    const float* U2   = (const float*)d_in[17];
    const float* V2   = (const float*)d_in[18];
    const float* b2   = (const float*)d_in[19];
    const float* ln1g = (const float*)d_in[20];
    const float* ln1b = (const float*)d_in[21];
    const float* ln2g = (const float*)d_in[22];
    const float* ln2b = (const float*)d_in[23];
    float* out = (float*)d_out;

#define SYM(p, s) cudaGetSymbolAddress((void**)&p, s)
    uint32_t *xh, *wch, *Uoh, *Voh, *U1h, *V1h, *U2h, *V2h;
    uint32_t *ath, *t1h, *x1h, *mdh, *hdh, *t2h;
    float *T, *y1, *x1, *y2;
    SYM(xh, g_xh); SYM(wch, g_wch);
    SYM(Uoh, g_Uoh); SYM(Voh, g_Voh);
    SYM(U1h, g_U1h); SYM(V1h, g_V1h);
    SYM(U2h, g_U2h); SYM(V2h, g_V2h);
    SYM(ath, g_ath); SYM(t1h, g_t1h);
    SYM(x1h, g_x1h); SYM(mdh, g_mdh);
    SYM(hdh, g_hdh); SYM(t2h, g_t2h);
    SYM(T, g_T); SYM(y1, g_y1); SYM(x1, g_x1); SYM(y2, g_y2);
#undef SYM

    cudaFuncSetAttribute(hflash, cudaFuncAttributeMaxDynamicSharedMemorySize,
                         FLASH_SMEM_BYTES);

    // operand conversion (B-side weights -> [K][N/2] u32 rows)
    conv_x<<<BMr * 512 / 256, 256>>>(x);
    pack_w_split<<<DMz * (C3 / 2) / 256, 256>>>(Pq, Pk, Pv);
    convB<<<(DMz * (ROz / 2) + 255) / 256, 256>>>(Uo, Uoh, DMz, ROz);
    convB<<<(ROz * (DMz / 2) + 255) / 256, 256>>>(Vo, Voh, ROz, DMz);
    convB<<<(DMz * (RFz / 2) + 255) / 256, 256>>>(U1, U1h, DMz, RFz);
    convB<<<(RFz * (DFFz / 2) + 255) / 256, 256>>>(V1, V1h, RFz, DFFz);
    convB<<<(DFFz * (RFz / 2) + 255) / 256, 256>>>(U2, U2h, DFFz, RFz);
    convB<<<(RFz * (DMz / 2) + 255) / 256, 256>>>(V2, V2h, RFz, DMz);

    // qkv low-rank
    hgemm<128, true, false, 0><<<dim3(C3 / 128, BMr / 128), 256>>>(
        xh, wch, T, nullptr, C3, DMz, nullptr);
    qkv2_k<<<dim3(Mz / 8, ZT, 3), 256>>>(Vq, Vk, Vv, bq, bk, bv);

    // fused attention
    hflash<<<dim3(Mz / 128, ZT), 256, FLASH_SMEM_BYTES>>>(mask);

    // output projection + LN1
    hgemm<64, false, true, 0><<<dim3(ROz / 128, BMr / 64), 256>>>(
        ath, Uoh, nullptr, t1h, ROz, DMz, nullptr);
    hgemm<128, true, false, 1><<<dim3(DMz / 128, BMr / 128), 256>>>(
        t1h, Voh, y1, nullptr, DMz, ROz, bo);
    ln_k<true><<<BMr, 256>>>(x, y1, ln1g, ln1b, x1);

    // FFN
    hgemm<64, false, true, 0><<<dim3(RFz / 128, BMr / 64), 256>>>(
        x1h, U1h, nullptr, mdh, RFz, DMz, nullptr);
    hgemm<128, false, true, 2><<<dim3(DFFz / 128, BMr / 128), 256>>>(
        mdh, V1h, nullptr, hdh, DFFz, RFz, b1);
    hgemm<64, false, true, 0><<<dim3(RFz / 128, BMr / 64), 256>>>(
        hdh, U2h, nullptr, t2h, RFz, DFFz, nullptr);
    hgemm<128, true, false, 1><<<dim3(DMz / 128, BMr / 128), 256>>>(
        t2h, V2h, y2, nullptr, DMz, RFz, b2);

    // LN2 -> out
    ln_k<false><<<BMr, 256>>>(x1, y2, ln2g, ln2b, out);
}